// round 4
// baseline (speedup 1.0000x reference)
#include <cuda_runtime.h>
#include <math.h>

#define BSZ     4
#define NTOK    4096
#define C_IN    384
#define C_DSSP  64
#define CH      128
#define NB      4
#define KTOT    832          /* 384 + 384 + 64 */
#define TOKENS  (BSZ*NTOK)   /* 16384 */
#define TILE_M  128
#define NTHR    256
#define RST     132          /* smem stride for 128-wide activation rows */
#define XST     36           /* smem stride for 32-wide input chunks */
#define SMEM_BYTES (2*TILE_M*RST*(int)sizeof(float))   /* 135168 */

// ---------------- device scratch (no allocations allowed) ----------------
__device__ __align__(16) float g_WTcat[KTOT*CH];   // [k][n], concat of W_in|W_init|W_dssp transposed
__device__ __align__(16) float g_WT1[NB][CH*CH];   // [k][n]
__device__ __align__(16) float g_WT2[NB][CH*CH];   // [k][n]
__device__ __align__(16) float g_WTout[CH*8];      // [k][j], j:0..4 W_out rows, 5..6 W_mult rows
__device__ float g_bias0[CH];                      // b_in + b_init + b_dssp
__device__ float g_bout[8];                        // b_out(5) | b_mult(2)
__device__ float g_scratch[TOKENS*5];              // per token: d0, c1, c2, c3, c4

// ---------------- prep: transpose/fuse weights ----------------
__global__ void prep_kernel(
    const float* __restrict__ Win,  const float* __restrict__ bin,
    const float* __restrict__ Wini, const float* __restrict__ bini,
    const float* __restrict__ Wd,   const float* __restrict__ bd,
    const float* __restrict__ W1,   const float* __restrict__ W2,
    const float* __restrict__ Wout, const float* __restrict__ bout,
    const float* __restrict__ Wmu,  const float* __restrict__ bmu)
{
    int id = blockIdx.x * blockDim.x + threadIdx.x;
    int stride = gridDim.x * blockDim.x;

    for (int x = id; x < KTOT*CH; x += stride) {
        int k = x / CH, n = x % CH;
        float v;
        if (k < 384)       v = Win [n*384 + k];
        else if (k < 768)  v = Wini[n*384 + (k-384)];
        else               v = Wd  [n*64  + (k-768)];
        g_WTcat[x] = v;
    }
    for (int x = id; x < NB*CH*CH; x += stride) {
        int b = x / (CH*CH);
        int r = x % (CH*CH);
        int k = r / CH, n = r % CH;
        g_WT1[b][k*CH + n] = W1[b*CH*CH + n*CH + k];
        g_WT2[b][k*CH + n] = W2[b*CH*CH + n*CH + k];
    }
    for (int x = id; x < CH*8; x += stride) {
        int k = x / 8, j = x % 8;
        float v = 0.f;
        if (j < 5)      v = Wout[j*CH + k];
        else if (j < 7) v = Wmu [(j-5)*CH + k];
        g_WTout[x] = v;
    }
    if (id < CH) g_bias0[id] = bin[id] + bini[id] + bd[id];
    if (id < 8)  g_bout[id] = (id < 5) ? bout[id] : ((id < 7) ? bmu[id-5] : 0.f);
}

// ---------------- GEMM microkernel: 8x8 per thread ----------------
// A: smem rows [i][k] (stride astride), W: global [k][128]; 4*nk4 k-steps.
__device__ __forceinline__ void gemm_chunk(
    const float* __restrict__ Arow, int astride,
    const float* __restrict__ W, int nk4, int nc, float (&acc)[8][8])
{
    #pragma unroll 1
    for (int kq = 0; kq < nk4; kq++) {
        float4 a4[8];
        #pragma unroll
        for (int i = 0; i < 8; i++)
            a4[i] = *(const float4*)(Arow + i*astride + kq*4);
        #pragma unroll
        for (int kk = 0; kk < 4; kk++) {
            const float4* wp = (const float4*)(W + (kq*4 + kk)*CH + nc*8);
            float4 b0 = wp[0];
            float4 b1 = wp[1];
            #pragma unroll
            for (int i = 0; i < 8; i++) {
                float av = (kk==0) ? a4[i].x : (kk==1) ? a4[i].y : (kk==2) ? a4[i].z : a4[i].w;
                acc[i][0] = fmaf(av, b0.x, acc[i][0]);
                acc[i][1] = fmaf(av, b0.y, acc[i][1]);
                acc[i][2] = fmaf(av, b0.z, acc[i][2]);
                acc[i][3] = fmaf(av, b0.w, acc[i][3]);
                acc[i][4] = fmaf(av, b1.x, acc[i][4]);
                acc[i][5] = fmaf(av, b1.y, acc[i][5]);
                acc[i][6] = fmaf(av, b1.z, acc[i][6]);
                acc[i][7] = fmaf(av, b1.w, acc[i][7]);
            }
        }
    }
}

// stage relu(X tile) chunk (32 cols) into smem, natural [m][k] layout
__device__ __forceinline__ void stage_relu(
    const float* __restrict__ X, int K, int c, float* Xs, int tid)
{
    #pragma unroll
    for (int r = 0; r < 4; r++) {
        int idx = tid + r*NTHR;            // 0..1023
        int m   = idx >> 3;
        int f4  = idx & 7;
        float4 v = *(const float4*)(X + (size_t)m*K + c*32 + f4*4);
        v.x = fmaxf(v.x, 0.f); v.y = fmaxf(v.y, 0.f);
        v.z = fmaxf(v.z, 0.f); v.w = fmaxf(v.w, 0.f);
        *(float4*)(Xs + m*XST + f4*4) = v;
    }
}

__device__ __forceinline__ float softplus_f(float x)
{
    return fmaxf(x, 0.f) + log1pf(expf(-fabsf(x)));
}

// ---------------- fused MLP kernel: 128 tokens per CTA ----------------
__global__ __launch_bounds__(NTHR, 1) void fused_mlp_kernel(
    const float* __restrict__ s, const float* __restrict__ si, const float* __restrict__ ds,
    const float* __restrict__ b1, const float* __restrict__ b2)
{
    extern __shared__ float smem[];
    float* shH = smem;                   // h   [128][RST]
    float* shR = smem + TILE_M*RST;      // relu(h)
    float* Xs  = smem;                   // aliases shH during phase 1 only

    const int tid  = threadIdx.x;
    const int mr   = tid >> 4;           // 0..15 (8 rows each)
    const int nc   = tid & 15;           // 0..15 (8 cols each)
    const int tok0 = blockIdx.x * TILE_M;

    float acc[8][8];
    #pragma unroll
    for (int i = 0; i < 8; i++)
        #pragma unroll
        for (int j = 0; j < 8; j++) acc[i][j] = 0.f;

    // ---- phase 1: h = relu(s)W_in^T + relu(si)W_init^T + relu(dssp)W_dssp^T ----
    {
        const float* srcs[3] = { s + (size_t)tok0*C_IN, si + (size_t)tok0*C_IN, ds + (size_t)tok0*C_DSSP };
        const int    Ks[3]   = { C_IN, C_IN, C_DSSP };
        const int    ofs[3]  = { 0, 384, 768 };
        for (int p = 0; p < 3; p++) {
            int nchunks = Ks[p] / 32;
            for (int c = 0; c < nchunks; c++) {
                __syncthreads();
                stage_relu(srcs[p], Ks[p], c, Xs, tid);
                __syncthreads();
                gemm_chunk(Xs + (mr*8)*XST, XST,
                           g_WTcat + (ofs[p] + c*32)*CH, 8, nc, acc);
            }
        }
    }
    // bias
    {
        const float4* pb = (const float4*)(g_bias0 + nc*8);
        float4 c0 = pb[0], c1 = pb[1];
        #pragma unroll
        for (int i = 0; i < 8; i++) {
            acc[i][0] += c0.x; acc[i][1] += c0.y; acc[i][2] += c0.z; acc[i][3] += c0.w;
            acc[i][4] += c1.x; acc[i][5] += c1.y; acc[i][6] += c1.z; acc[i][7] += c1.w;
        }
    }
    // write h and relu(h) (Xs alias dead from here)
    __syncthreads();
    #pragma unroll
    for (int i = 0; i < 8; i++) {
        int row = (mr*8 + i)*RST + nc*8;
        float4 h0 = make_float4(acc[i][0], acc[i][1], acc[i][2], acc[i][3]);
        float4 h1 = make_float4(acc[i][4], acc[i][5], acc[i][6], acc[i][7]);
        *(float4*)(shH + row)     = h0;
        *(float4*)(shH + row + 4) = h1;
        float4 r0 = make_float4(fmaxf(h0.x,0.f), fmaxf(h0.y,0.f), fmaxf(h0.z,0.f), fmaxf(h0.w,0.f));
        float4 r1 = make_float4(fmaxf(h1.x,0.f), fmaxf(h1.y,0.f), fmaxf(h1.z,0.f), fmaxf(h1.w,0.f));
        *(float4*)(shR + row)     = r0;
        *(float4*)(shR + row + 4) = r1;
    }
    __syncthreads();

    // ---- resnet blocks ----
    for (int blk = 0; blk < NB; blk++) {
        // tmp = relu( relu(h) @ W1^T + b1 )
        float tmp[8][8];
        #pragma unroll
        for (int i = 0; i < 8; i++)
            #pragma unroll
            for (int j = 0; j < 8; j++) tmp[i][j] = 0.f;
        gemm_chunk(shR + (mr*8)*RST, RST, g_WT1[blk], 32, nc, tmp);

        {
            const float4* pb = (const float4*)(b1 + blk*CH + nc*8);
            float4 c0 = pb[0], c1 = pb[1];
            #pragma unroll
            for (int i = 0; i < 8; i++) {
                tmp[i][0] = fmaxf(tmp[i][0] + c0.x, 0.f);
                tmp[i][1] = fmaxf(tmp[i][1] + c0.y, 0.f);
                tmp[i][2] = fmaxf(tmp[i][2] + c0.z, 0.f);
                tmp[i][3] = fmaxf(tmp[i][3] + c0.w, 0.f);
                tmp[i][4] = fmaxf(tmp[i][4] + c1.x, 0.f);
                tmp[i][5] = fmaxf(tmp[i][5] + c1.y, 0.f);
                tmp[i][6] = fmaxf(tmp[i][6] + c1.z, 0.f);
                tmp[i][7] = fmaxf(tmp[i][7] + c1.w, 0.f);
            }
        }
        __syncthreads();   // all reads of shR done
        #pragma unroll
        for (int i = 0; i < 8; i++) {
            int row = (mr*8 + i)*RST + nc*8;
            *(float4*)(shR + row)     = make_float4(tmp[i][0], tmp[i][1], tmp[i][2], tmp[i][3]);
            *(float4*)(shR + row + 4) = make_float4(tmp[i][4], tmp[i][5], tmp[i][6], tmp[i][7]);
        }
        __syncthreads();

        // h = h + relu(tmp) @ W2^T + b2
        float del[8][8];
        #pragma unroll
        for (int i = 0; i < 8; i++)
            #pragma unroll
            for (int j = 0; j < 8; j++) del[i][j] = 0.f;
        gemm_chunk(shR + (mr*8)*RST, RST, g_WT2[blk], 32, nc, del);

        const float4* pb2 = (const float4*)(b2 + blk*CH + nc*8);
        float4 c0 = pb2[0], c1 = pb2[1];
        __syncthreads();   // all reads of shR done before overwrite
        #pragma unroll
        for (int i = 0; i < 8; i++) {
            int row = (mr*8 + i)*RST + nc*8;
            float4 h0 = *(const float4*)(shH + row);
            float4 h1 = *(const float4*)(shH + row + 4);
            h0.x += del[i][0] + c0.x; h0.y += del[i][1] + c0.y;
            h0.z += del[i][2] + c0.z; h0.w += del[i][3] + c0.w;
            h1.x += del[i][4] + c1.x; h1.y += del[i][5] + c1.y;
            h1.z += del[i][6] + c1.z; h1.w += del[i][7] + c1.w;
            *(float4*)(shH + row)     = h0;
            *(float4*)(shH + row + 4) = h1;
            *(float4*)(shR + row)     = make_float4(fmaxf(h0.x,0.f), fmaxf(h0.y,0.f), fmaxf(h0.z,0.f), fmaxf(h0.w,0.f));
            *(float4*)(shR + row + 4) = make_float4(fmaxf(h1.x,0.f), fmaxf(h1.y,0.f), fmaxf(h1.z,0.f), fmaxf(h1.w,0.f));
        }
        __syncthreads();
    }

    // ---- head: 7 outputs per token -> scratch ----
    if (tid < TILE_M) {
        int m = tid;
        float o[7];
        #pragma unroll
        for (int j = 0; j < 7; j++) o[j] = g_bout[j];
        const float* rrow = shR + m*RST;
        #pragma unroll 4
        for (int k = 0; k < CH; k++) {
            float r = rrow[k];
            const float* w = g_WTout + k*8;
            #pragma unroll
            for (int j = 0; j < 7; j++) o[j] = fmaf(r, w[j], o[j]);
        }
        float d0 = softplus_f(o[0]) * softplus_f(o[5]) + softplus_f(o[6]);
        int g = tok0 + m;
        g_scratch[g*5 + 0] = d0;
        g_scratch[g*5 + 1] = o[1];
        g_scratch[g*5 + 2] = o[2];
        g_scratch[g*5 + 3] = o[3];
        g_scratch[g*5 + 4] = o[4];
    }
}

// ---------------- zero + band writer: one CTA per output row ----------------
__global__ void band_kernel(float* __restrict__ out, const float* __restrict__ smp)
{
    const float sm = *smp;
    int row = blockIdx.x;               // b*4096 + i
    int i   = row & (NTOK - 1);
    size_t base = (size_t)row * NTOK;
    int t = threadIdx.x;                // 128 threads

    float d0 = sm * g_scratch[row*5 + 0];
    float d1 = (i >= 1) ? sm * (g_scratch[row*5 + 1] + g_scratch[(row-1)*5 + 3]) : 0.f;
    float d2 = (i >= 2) ? sm * (g_scratch[row*5 + 2] + g_scratch[(row-2)*5 + 4]) : 0.f;

    #pragma unroll
    for (int q = 0; q < 8; q++) {
        int v  = q*128 + t;             // float4 index within row
        int c0 = v*4;
        float4 val = make_float4(0.f, 0.f, 0.f, 0.f);
        if (c0 <= i && c0 + 3 >= i - 2) {
            float* f = (float*)&val;
            #pragma unroll
            for (int e = 0; e < 4; e++) {
                int col = c0 + e;
                if (col == i)          f[e] = d0;
                else if (col == i - 1) f[e] = d1;
                else if (col == i - 2) f[e] = d2;
            }
        }
        *(float4*)(out + base + c0) = val;
    }
}

// ---------------- launch ----------------
extern "C" void kernel_launch(void* const* d_in, const int* in_sizes, int n_in,
                              void* d_out, int out_size)
{
    (void)in_sizes; (void)n_in; (void)out_size;
    const float* s    = (const float*)d_in[0];
    const float* si   = (const float*)d_in[1];
    const float* ds   = (const float*)d_in[2];
    const float* Win  = (const float*)d_in[3];
    const float* bin  = (const float*)d_in[4];
    const float* Wini = (const float*)d_in[5];
    const float* bini = (const float*)d_in[6];
    const float* Wd   = (const float*)d_in[7];
    const float* bd   = (const float*)d_in[8];
    const float* W1   = (const float*)d_in[9];
    const float* b1   = (const float*)d_in[10];
    const float* W2   = (const float*)d_in[11];
    const float* b2   = (const float*)d_in[12];
    const float* Wout = (const float*)d_in[13];
    const float* bout = (const float*)d_in[14];
    const float* Wmu  = (const float*)d_in[15];
    const float* bmu  = (const float*)d_in[16];
    const float* smod = (const float*)d_in[17];
    float* out = (float*)d_out;

    cudaFuncSetAttribute(fused_mlp_kernel,
                         cudaFuncAttributeMaxDynamicSharedMemorySize, SMEM_BYTES);

    prep_kernel<<<64, 256>>>(Win, bin, Wini, bini, Wd, bd, W1, W2, Wout, bout, Wmu, bmu);
    fused_mlp_kernel<<<TOKENS/TILE_M, NTHR, SMEM_BYTES>>>(s, si, ds, b1, b2);
    band_kernel<<<TOKENS, 128>>>(out, smod);
}

// round 5
// speedup vs baseline: 1.2414x; 1.2414x over previous
#include <cuda_runtime.h>
#include <math.h>

#define BSZ     4
#define NTOK    4096
#define C_IN    384
#define C_DSSP  64
#define CH      128
#define NB      4
#define KTOT    832          /* 384 + 384 + 64 */
#define TOKENS  (BSZ*NTOK)   /* 16384 */
#define TILE_M  128
#define NTHR    256
#define RST     132          /* smem stride for 128-wide activation rows */
#define XST     36           /* smem stride for 32-wide input chunks */
#define SMEM_BYTES (2*TILE_M*RST*(int)sizeof(float))   /* 135168 */

typedef unsigned long long u64;

// ---------------- device scratch (no allocations allowed) ----------------
__device__ __align__(16) float g_WTcat[KTOT*CH];   // [k][n], concat of W_in|W_init|W_dssp transposed
__device__ __align__(16) float g_WT1[NB][CH*CH];   // [k][n]
__device__ __align__(16) float g_WT2[NB][CH*CH];   // [k][n]
__device__ __align__(16) float g_WTout[CH*8];      // [k][j], j:0..4 W_out rows, 5..6 W_mult rows
__device__ float g_bias0[CH];                      // b_in + b_init + b_dssp
__device__ float g_bout[8];                        // b_out(5) | b_mult(2)
__device__ float g_scratch[TOKENS*5];              // per token: d0, c1, c2, c3, c4

// ---------------- f32x2 packed helpers ----------------
__device__ __forceinline__ u64 bcast2(float a) {
    u64 v;
    asm("mov.b64 %0, {%1, %1};" : "=l"(v) : "f"(a));
    return v;
}
__device__ __forceinline__ void fma2(u64& acc, u64 a, u64 b) {
    asm("fma.rn.f32x2 %0, %1, %2, %0;" : "+l"(acc) : "l"(a), "l"(b));
}
__device__ __forceinline__ float2 unpack2(u64 v) {
    float2 r;
    asm("mov.b64 {%0, %1}, %2;" : "=f"(r.x), "=f"(r.y) : "l"(v));
    return r;
}
__device__ __forceinline__ void unpack_acc(const u64 (&a2)[8][4], float (&a)[8][8]) {
    #pragma unroll
    for (int i = 0; i < 8; i++)
        #pragma unroll
        for (int j = 0; j < 4; j++) {
            float2 f = unpack2(a2[i][j]);
            a[i][2*j]   = f.x;
            a[i][2*j+1] = f.y;
        }
}

// ---------------- prep: transpose/fuse weights ----------------
__global__ void prep_kernel(
    const float* __restrict__ Win,  const float* __restrict__ bin,
    const float* __restrict__ Wini, const float* __restrict__ bini,
    const float* __restrict__ Wd,   const float* __restrict__ bd,
    const float* __restrict__ W1,   const float* __restrict__ W2,
    const float* __restrict__ Wout, const float* __restrict__ bout,
    const float* __restrict__ Wmu,  const float* __restrict__ bmu)
{
    int id = blockIdx.x * blockDim.x + threadIdx.x;
    int stride = gridDim.x * blockDim.x;

    for (int x = id; x < KTOT*CH; x += stride) {
        int k = x / CH, n = x % CH;
        float v;
        if (k < 384)       v = Win [n*384 + k];
        else if (k < 768)  v = Wini[n*384 + (k-384)];
        else               v = Wd  [n*64  + (k-768)];
        g_WTcat[x] = v;
    }
    for (int x = id; x < NB*CH*CH; x += stride) {
        int b = x / (CH*CH);
        int r = x % (CH*CH);
        int k = r / CH, n = r % CH;
        g_WT1[b][k*CH + n] = W1[b*CH*CH + n*CH + k];
        g_WT2[b][k*CH + n] = W2[b*CH*CH + n*CH + k];
    }
    for (int x = id; x < CH*8; x += stride) {
        int k = x / 8, j = x % 8;
        float v = 0.f;
        if (j < 5)      v = Wout[j*CH + k];
        else if (j < 7) v = Wmu [(j-5)*CH + k];
        g_WTout[x] = v;
    }
    if (id < CH) g_bias0[id] = bin[id] + bini[id] + bd[id];
    if (id < 8)  g_bout[id] = (id < 5) ? bout[id] : ((id < 7) ? bmu[id-5] : 0.f);
}

// ---------------- GEMM microkernel: 8x8 per thread via packed f32x2 ----------------
// A: smem rows [i][k] (stride astride), W: global [k][128]; 4*nk4 k-steps.
// acc2[i][jp] holds output columns (nc*8 + 2*jp, nc*8 + 2*jp + 1) packed as f32x2.
__device__ __forceinline__ void gemm_chunk2(
    const float* __restrict__ Arow, int astride,
    const float* __restrict__ W, int nk4, int nc, u64 (&acc2)[8][4])
{
    #pragma unroll 1
    for (int kq = 0; kq < nk4; kq++) {
        float4 a4[8];
        #pragma unroll
        for (int i = 0; i < 8; i++)
            a4[i] = *(const float4*)(Arow + i*astride + kq*4);
        #pragma unroll
        for (int kk = 0; kk < 4; kk++) {
            const ulonglong2* wp = (const ulonglong2*)(W + (kq*4 + kk)*CH + nc*8);
            ulonglong2 b01 = wp[0];
            ulonglong2 b23 = wp[1];
            #pragma unroll
            for (int i = 0; i < 8; i++) {
                float av = (kk==0) ? a4[i].x : (kk==1) ? a4[i].y : (kk==2) ? a4[i].z : a4[i].w;
                u64 avv = bcast2(av);
                fma2(acc2[i][0], avv, b01.x);
                fma2(acc2[i][1], avv, b01.y);
                fma2(acc2[i][2], avv, b23.x);
                fma2(acc2[i][3], avv, b23.y);
            }
        }
    }
}

// stage relu(X tile) chunk (32 cols) into smem, natural [m][k] layout
__device__ __forceinline__ void stage_relu(
    const float* __restrict__ X, int K, int c, float* Xs, int tid)
{
    #pragma unroll
    for (int r = 0; r < 4; r++) {
        int idx = tid + r*NTHR;            // 0..1023
        int m   = idx >> 3;
        int f4  = idx & 7;
        float4 v = *(const float4*)(X + (size_t)m*K + c*32 + f4*4);
        v.x = fmaxf(v.x, 0.f); v.y = fmaxf(v.y, 0.f);
        v.z = fmaxf(v.z, 0.f); v.w = fmaxf(v.w, 0.f);
        *(float4*)(Xs + m*XST + f4*4) = v;
    }
}

__device__ __forceinline__ float softplus_f(float x)
{
    return fmaxf(x, 0.f) + log1pf(expf(-fabsf(x)));
}

// ---------------- fused MLP kernel: 128 tokens per CTA ----------------
__global__ __launch_bounds__(NTHR, 1) void fused_mlp_kernel(
    const float* __restrict__ s, const float* __restrict__ si, const float* __restrict__ ds,
    const float* __restrict__ b1, const float* __restrict__ b2)
{
    extern __shared__ float smem[];
    float* shH = smem;                   // h   [128][RST]
    float* shR = smem + TILE_M*RST;      // relu(h)
    float* Xs  = smem;                   // aliases shH during phase 1 only

    const int tid  = threadIdx.x;
    const int mr   = tid >> 4;           // 0..15 (8 rows each)
    const int nc   = tid & 15;           // 0..15 (8 cols each)
    const int tok0 = blockIdx.x * TILE_M;

    u64 acc2[8][4];
    #pragma unroll
    for (int i = 0; i < 8; i++)
        #pragma unroll
        for (int j = 0; j < 4; j++) acc2[i][j] = 0ull;

    // ---- phase 1: h = relu(s)W_in^T + relu(si)W_init^T + relu(dssp)W_dssp^T ----
    {
        const float* srcs[3] = { s + (size_t)tok0*C_IN, si + (size_t)tok0*C_IN, ds + (size_t)tok0*C_DSSP };
        const int    Ks[3]   = { C_IN, C_IN, C_DSSP };
        const int    ofs[3]  = { 0, 384, 768 };
        for (int p = 0; p < 3; p++) {
            int nchunks = Ks[p] / 32;
            for (int c = 0; c < nchunks; c++) {
                __syncthreads();
                stage_relu(srcs[p], Ks[p], c, Xs, tid);
                __syncthreads();
                gemm_chunk2(Xs + (mr*8)*XST, XST,
                            g_WTcat + (ofs[p] + c*32)*CH, 8, nc, acc2);
            }
        }
    }
    // bias + unpack
    float acc[8][8];
    unpack_acc(acc2, acc);
    {
        const float4* pb = (const float4*)(g_bias0 + nc*8);
        float4 c0 = pb[0], c1 = pb[1];
        #pragma unroll
        for (int i = 0; i < 8; i++) {
            acc[i][0] += c0.x; acc[i][1] += c0.y; acc[i][2] += c0.z; acc[i][3] += c0.w;
            acc[i][4] += c1.x; acc[i][5] += c1.y; acc[i][6] += c1.z; acc[i][7] += c1.w;
        }
    }
    // write h and relu(h) (Xs alias dead from here)
    __syncthreads();
    #pragma unroll
    for (int i = 0; i < 8; i++) {
        int row = (mr*8 + i)*RST + nc*8;
        float4 h0 = make_float4(acc[i][0], acc[i][1], acc[i][2], acc[i][3]);
        float4 h1 = make_float4(acc[i][4], acc[i][5], acc[i][6], acc[i][7]);
        *(float4*)(shH + row)     = h0;
        *(float4*)(shH + row + 4) = h1;
        float4 r0 = make_float4(fmaxf(h0.x,0.f), fmaxf(h0.y,0.f), fmaxf(h0.z,0.f), fmaxf(h0.w,0.f));
        float4 r1 = make_float4(fmaxf(h1.x,0.f), fmaxf(h1.y,0.f), fmaxf(h1.z,0.f), fmaxf(h1.w,0.f));
        *(float4*)(shR + row)     = r0;
        *(float4*)(shR + row + 4) = r1;
    }
    __syncthreads();

    // ---- resnet blocks ----
    for (int blk = 0; blk < NB; blk++) {
        // tmp = relu( relu(h) @ W1^T + b1 )
        u64 t2[8][4];
        #pragma unroll
        for (int i = 0; i < 8; i++)
            #pragma unroll
            for (int j = 0; j < 4; j++) t2[i][j] = 0ull;
        gemm_chunk2(shR + (mr*8)*RST, RST, g_WT1[blk], 32, nc, t2);

        float tmp[8][8];
        unpack_acc(t2, tmp);
        {
            const float4* pb = (const float4*)(b1 + blk*CH + nc*8);
            float4 c0 = pb[0], c1 = pb[1];
            #pragma unroll
            for (int i = 0; i < 8; i++) {
                tmp[i][0] = fmaxf(tmp[i][0] + c0.x, 0.f);
                tmp[i][1] = fmaxf(tmp[i][1] + c0.y, 0.f);
                tmp[i][2] = fmaxf(tmp[i][2] + c0.z, 0.f);
                tmp[i][3] = fmaxf(tmp[i][3] + c0.w, 0.f);
                tmp[i][4] = fmaxf(tmp[i][4] + c1.x, 0.f);
                tmp[i][5] = fmaxf(tmp[i][5] + c1.y, 0.f);
                tmp[i][6] = fmaxf(tmp[i][6] + c1.z, 0.f);
                tmp[i][7] = fmaxf(tmp[i][7] + c1.w, 0.f);
            }
        }
        __syncthreads();   // all reads of shR done
        #pragma unroll
        for (int i = 0; i < 8; i++) {
            int row = (mr*8 + i)*RST + nc*8;
            *(float4*)(shR + row)     = make_float4(tmp[i][0], tmp[i][1], tmp[i][2], tmp[i][3]);
            *(float4*)(shR + row + 4) = make_float4(tmp[i][4], tmp[i][5], tmp[i][6], tmp[i][7]);
        }
        __syncthreads();

        // h = h + relu(tmp) @ W2^T + b2
        u64 d2[8][4];
        #pragma unroll
        for (int i = 0; i < 8; i++)
            #pragma unroll
            for (int j = 0; j < 4; j++) d2[i][j] = 0ull;
        gemm_chunk2(shR + (mr*8)*RST, RST, g_WT2[blk], 32, nc, d2);

        float del[8][8];
        unpack_acc(d2, del);
        const float4* pb2 = (const float4*)(b2 + blk*CH + nc*8);
        float4 c0 = pb2[0], c1 = pb2[1];
        __syncthreads();   // all reads of shR done before overwrite
        #pragma unroll
        for (int i = 0; i < 8; i++) {
            int row = (mr*8 + i)*RST + nc*8;
            float4 h0 = *(const float4*)(shH + row);
            float4 h1 = *(const float4*)(shH + row + 4);
            h0.x += del[i][0] + c0.x; h0.y += del[i][1] + c0.y;
            h0.z += del[i][2] + c0.z; h0.w += del[i][3] + c0.w;
            h1.x += del[i][4] + c1.x; h1.y += del[i][5] + c1.y;
            h1.z += del[i][6] + c1.z; h1.w += del[i][7] + c1.w;
            *(float4*)(shH + row)     = h0;
            *(float4*)(shH + row + 4) = h1;
            *(float4*)(shR + row)     = make_float4(fmaxf(h0.x,0.f), fmaxf(h0.y,0.f), fmaxf(h0.z,0.f), fmaxf(h0.w,0.f));
            *(float4*)(shR + row + 4) = make_float4(fmaxf(h1.x,0.f), fmaxf(h1.y,0.f), fmaxf(h1.z,0.f), fmaxf(h1.w,0.f));
        }
        __syncthreads();
    }

    // ---- head: 7 outputs per token -> scratch ----
    if (tid < TILE_M) {
        int m = tid;
        float o[7];
        #pragma unroll
        for (int j = 0; j < 7; j++) o[j] = g_bout[j];
        const float* rrow = shR + m*RST;
        #pragma unroll 4
        for (int k = 0; k < CH; k++) {
            float r = rrow[k];
            const float* w = g_WTout + k*8;
            #pragma unroll
            for (int j = 0; j < 7; j++) o[j] = fmaf(r, w[j], o[j]);
        }
        float d0 = softplus_f(o[0]) * softplus_f(o[5]) + softplus_f(o[6]);
        int g = tok0 + m;
        g_scratch[g*5 + 0] = d0;
        g_scratch[g*5 + 1] = o[1];
        g_scratch[g*5 + 2] = o[2];
        g_scratch[g*5 + 3] = o[3];
        g_scratch[g*5 + 4] = o[4];
    }
}

// ---------------- zero + band writer: one CTA per output row ----------------
__global__ void band_kernel(float* __restrict__ out, const float* __restrict__ smp)
{
    const float sm = *smp;
    int row = blockIdx.x;               // b*4096 + i
    int i   = row & (NTOK - 1);
    size_t base = (size_t)row * NTOK;
    int t = threadIdx.x;                // 128 threads

    float d0 = sm * g_scratch[row*5 + 0];
    float d1 = (i >= 1) ? sm * (g_scratch[row*5 + 1] + g_scratch[(row-1)*5 + 3]) : 0.f;
    float d2 = (i >= 2) ? sm * (g_scratch[row*5 + 2] + g_scratch[(row-2)*5 + 4]) : 0.f;

    #pragma unroll
    for (int q = 0; q < 8; q++) {
        int v  = q*128 + t;             // float4 index within row
        int c0 = v*4;
        float4 val = make_float4(0.f, 0.f, 0.f, 0.f);
        if (c0 <= i && c0 + 3 >= i - 2) {
            float* f = (float*)&val;
            #pragma unroll
            for (int e = 0; e < 4; e++) {
                int col = c0 + e;
                if (col == i)          f[e] = d0;
                else if (col == i - 1) f[e] = d1;
                else if (col == i - 2) f[e] = d2;
            }
        }
        *(float4*)(out + base + c0) = val;
    }
}

// ---------------- launch ----------------
extern "C" void kernel_launch(void* const* d_in, const int* in_sizes, int n_in,
                              void* d_out, int out_size)
{
    (void)in_sizes; (void)n_in; (void)out_size;
    const float* s    = (const float*)d_in[0];
    const float* si   = (const float*)d_in[1];
    const float* ds   = (const float*)d_in[2];
    const float* Win  = (const float*)d_in[3];
    const float* bin  = (const float*)d_in[4];
    const float* Wini = (const float*)d_in[5];
    const float* bini = (const float*)d_in[6];
    const float* Wd   = (const float*)d_in[7];
    const float* bd   = (const float*)d_in[8];
    const float* W1   = (const float*)d_in[9];
    const float* b1   = (const float*)d_in[10];
    const float* W2   = (const float*)d_in[11];
    const float* b2   = (const float*)d_in[12];
    const float* Wout = (const float*)d_in[13];
    const float* bout = (const float*)d_in[14];
    const float* Wmu  = (const float*)d_in[15];
    const float* bmu  = (const float*)d_in[16];
    const float* smod = (const float*)d_in[17];
    float* out = (float*)d_out;

    cudaFuncSetAttribute(fused_mlp_kernel,
                         cudaFuncAttributeMaxDynamicSharedMemorySize, SMEM_BYTES);

    prep_kernel<<<148, 256>>>(Win, bin, Wini, bini, Wd, bd, W1, W2, Wout, bout, Wmu, bmu);
    fused_mlp_kernel<<<TOKENS/TILE_M, NTHR, SMEM_BYTES>>>(s, si, ds, b1, b2);
    band_kernel<<<TOKENS, 128>>>(out, smod);
}

// round 7
// speedup vs baseline: 1.3990x; 1.1270x over previous
#include <cuda_runtime.h>
#include <cuda_bf16.h>
#include <math.h>

typedef unsigned int u32;
typedef unsigned long long u64;

#define BSZ     4
#define NTOK    4096
#define C_IN    384
#define C_DSSP  64
#define CH      128
#define NB      4
#define TOKENS  (BSZ*NTOK)   /* 16384 */
#define TILE_M  128
#define NTHR    256
#define HSTW    132          /* H fp32 row stride (floats) */
#define AST     272          /* A/B smem row stride in BYTES (136 bf16) */

/* smem layout (bytes) */
#define AHI   0
#define ALO   34816
#define BHI   69632
#define BLO   104448
#define HOF   139264
#define SMEM_TOTAL (HOF + TILE_M*HSTW*4)   /* 206848 */

#define IMG_BYTES 34816      /* one B image: 128 rows x 136 bf16 */

/* ---------------- device scratch (no allocations allowed) ---------------- */
__device__ __align__(16) char g_Bcat_hi[7][IMG_BYTES];
__device__ __align__(16) char g_Bcat_lo[7][IMG_BYTES];
__device__ __align__(16) char g_B1_hi[NB][IMG_BYTES];
__device__ __align__(16) char g_B1_lo[NB][IMG_BYTES];
__device__ __align__(16) char g_B2_hi[NB][IMG_BYTES];
__device__ __align__(16) char g_B2_lo[NB][IMG_BYTES];
__device__ __align__(16) float g_WTout[CH*8];
__device__ float g_bias0[CH];
__device__ float g_bout[8];
__device__ float g_scratch[TOKENS*5];

/* ---------------- helpers ---------------- */
__device__ __forceinline__ u32 smem_u32(const void* p) {
    u32 a;
    asm("{ .reg .u64 t; cvta.to.shared.u64 t, %1; cvt.u32.u64 %0, t; }" : "=r"(a) : "l"(p));
    return a;
}
__device__ __forceinline__ void ldsm4(u32& r0, u32& r1, u32& r2, u32& r3, u32 addr)
{
    asm volatile("ldmatrix.sync.aligned.m8n8.x4.shared.b16 {%0,%1,%2,%3}, [%4];"
        : "=r"(r0), "=r"(r1), "=r"(r2), "=r"(r3) : "r"(addr));
}
__device__ __forceinline__ void mma16816(float (&c)[4], u32 a0, u32 a1, u32 a2, u32 a3,
                                         u32 b0, u32 b1)
{
    asm volatile("mma.sync.aligned.m16n8k16.row.col.f32.bf16.bf16.f32 "
        "{%0,%1,%2,%3},{%4,%5,%6,%7},{%8,%9},{%0,%1,%2,%3};"
        : "+f"(c[0]), "+f"(c[1]), "+f"(c[2]), "+f"(c[3])
        : "r"(a0), "r"(a1), "r"(a2), "r"(a3), "r"(b0), "r"(b1));
}
__device__ __forceinline__ void split_pack(float a, float b, u32& phi, u32& plo)
{
    __nv_bfloat16 ha = __float2bfloat16(a);
    __nv_bfloat16 hb = __float2bfloat16(b);
    __nv_bfloat16 la = __float2bfloat16(a - __bfloat162float(ha));
    __nv_bfloat16 lb = __float2bfloat16(b - __bfloat162float(hb));
    phi = (u32)__bfloat16_as_ushort(ha) | ((u32)__bfloat16_as_ushort(hb) << 16);
    plo = (u32)__bfloat16_as_ushort(la) | ((u32)__bfloat16_as_ushort(lb) << 16);
}
__device__ __forceinline__ float softplus_f(float x)
{
    return fmaxf(x, 0.f) + log1pf(expf(-fabsf(x)));
}

/* ---------------- prep: bf16-split weights into [n][k] images ---------------- */
__global__ void prep_kernel(
    const float* __restrict__ Win,  const float* __restrict__ bin,
    const float* __restrict__ Wini, const float* __restrict__ bini,
    const float* __restrict__ Wd,   const float* __restrict__ bd,
    const float* __restrict__ W1,   const float* __restrict__ W2,
    const float* __restrict__ Wout, const float* __restrict__ bout,
    const float* __restrict__ Wmu,  const float* __restrict__ bmu)
{
    int id = blockIdx.x * blockDim.x + threadIdx.x;
    int stride = gridDim.x * blockDim.x;

    for (int x = id; x < 128*832; x += stride) {
        int n = x / 832, k = x % 832;
        float v;
        if (k < 384)       v = Win [n*384 + k];
        else if (k < 768)  v = Wini[n*384 + (k-384)];
        else               v = Wd  [n*64  + (k-768)];
        int c = k >> 7, kc = k & 127;
        __nv_bfloat16 h = __float2bfloat16(v);
        __nv_bfloat16 l = __float2bfloat16(v - __bfloat162float(h));
        int off = (n*136 + kc)*2;
        *(__nv_bfloat16*)(g_Bcat_hi[c] + off) = h;
        *(__nv_bfloat16*)(g_Bcat_lo[c] + off) = l;
    }
    for (int x = id; x < NB*128*128; x += stride) {
        int blk = x >> 14; int r = x & 16383; int n = r >> 7; int k = r & 127;
        int off = (n*136 + k)*2;
        float v1 = W1[x];
        __nv_bfloat16 h1 = __float2bfloat16(v1);
        __nv_bfloat16 l1 = __float2bfloat16(v1 - __bfloat162float(h1));
        *(__nv_bfloat16*)(g_B1_hi[blk] + off) = h1;
        *(__nv_bfloat16*)(g_B1_lo[blk] + off) = l1;
        float v2 = W2[x];
        __nv_bfloat16 h2 = __float2bfloat16(v2);
        __nv_bfloat16 l2 = __float2bfloat16(v2 - __bfloat162float(h2));
        *(__nv_bfloat16*)(g_B2_hi[blk] + off) = h2;
        *(__nv_bfloat16*)(g_B2_lo[blk] + off) = l2;
    }
    for (int x = id; x < CH*8; x += stride) {
        int k = x / 8, j = x % 8;
        float v = 0.f;
        if (j < 5)      v = Wout[j*CH + k];
        else if (j < 7) v = Wmu [(j-5)*CH + k];
        g_WTout[x] = v;
    }
    if (id < CH) g_bias0[id] = bin[id] + bini[id] + bd[id];
    if (id < 8)  g_bout[id] = (id < 5) ? bout[id] : ((id < 7) ? bmu[id-5] : 0.f);
}

/* ---------------- 3-pass split GEMM core ---------------- */
__device__ __forceinline__ void gemm3(u32 ahi, u32 alo, u32 bhi, u32 blo,
                                      int nks, u32 a_t, u32 b_t, float (&acc)[16][4])
{
    #pragma unroll 1
    for (int p = 0; p < 3; p++) {
        u32 Ab = (p == 2) ? alo : ahi;
        u32 Bb = (p == 1) ? blo : bhi;
        #pragma unroll 1
        for (int ks = 0; ks < nks; ks++) {
            u32 a0, a1, a2, a3;
            ldsm4(a0, a1, a2, a3, Ab + a_t + ks*32);
            #pragma unroll
            for (int np = 0; np < 8; np++) {
                u32 b0, b1, b2, b3;
                ldsm4(b0, b1, b2, b3, Bb + b_t + np*4352 + ks*32);
                mma16816(acc[2*np],   a0, a1, a2, a3, b0, b1);
                mma16816(acc[2*np+1], a0, a1, a2, a3, b2, b3);
            }
        }
    }
}

__device__ __forceinline__ void copy_img(char* smem, const char* hi, const char* lo, int tid)
{
    const uint4* sh = (const uint4*)hi;
    const uint4* sl = (const uint4*)lo;
    uint4* dh = (uint4*)(smem + BHI);
    uint4* dl = (uint4*)(smem + BLO);
    #pragma unroll 1
    for (int i = tid; i < IMG_BYTES/16; i += NTHR) { dh[i] = sh[i]; dl[i] = sl[i]; }
}

/* ---------------- fused MLP kernel: 128 tokens/CTA, mma.sync GEMMs ---------------- */
__global__ __launch_bounds__(NTHR, 1) void fused_mlp_kernel(
    const float* __restrict__ s, const float* __restrict__ si, const float* __restrict__ ds,
    const float* __restrict__ b1g, const float* __restrict__ b2g)
{
    extern __shared__ char smem[];
    float* H = (float*)(smem + HOF);
    const int tid  = threadIdx.x;
    const int w    = tid >> 5;
    const int lane = tid & 31;
    const int seg  = lane >> 3;
    const int rr   = lane & 7;
    const int tok0 = blockIdx.x * TILE_M;

    const u32 a_t = (u32)((w*16 + (seg & 1)*8 + rr)*AST + (seg >> 1)*16);
    const u32 b_t = (u32)(((seg >> 1)*8 + rr)*AST + (seg & 1)*16);
    const int r0   = w*16 + (lane >> 2);
    const int r1   = r0 + 8;
    const int colb = (lane & 3)*2;

    u32 sb  = smem_u32(smem);
    u32 ahi = sb + AHI, alo = sb + ALO, bhi = sb + BHI, blo = sb + BLO;

    float acc[16][4];
    #pragma unroll
    for (int i = 0; i < 16; i++)
        #pragma unroll
        for (int j = 0; j < 4; j++) acc[i][j] = 0.f;

    /* ---- phase 1: accumulate 7 K-chunks of the concat input GEMM ---- */
    #pragma unroll 1
    for (int c = 0; c < 7; c++) {
        const float* src; int Krow, Kc;
        if (c < 3)      { src = s  + (size_t)tok0*C_IN   + c*128;     Krow = C_IN;   Kc = 128; }
        else if (c < 6) { src = si + (size_t)tok0*C_IN   + (c-3)*128; Krow = C_IN;   Kc = 128; }
        else            { src = ds + (size_t)tok0*C_DSSP;             Krow = C_DSSP; Kc = 64;  }
        int hp = Kc >> 1;                       /* pairs per row */
        int total = 128*hp;
        int pl = (Kc == 128) ? 6 : 5, pm = hp - 1;
        #pragma unroll 1
        for (int idx = tid; idx < total; idx += NTHR) {
            int m = idx >> pl, kp = idx & pm;
            float2 v = *(const float2*)(src + (size_t)m*Krow + kp*2);
            u32 phi, plo;
            split_pack(fmaxf(v.x, 0.f), fmaxf(v.y, 0.f), phi, plo);
            int o = m*AST + kp*4;
            *(u32*)(smem + AHI + o) = phi;
            *(u32*)(smem + ALO + o) = plo;
        }
        copy_img(smem, g_Bcat_hi[c], g_Bcat_lo[c], tid);
        __syncthreads();
        gemm3(ahi, alo, bhi, blo, (Kc == 128) ? 8 : 4, a_t, b_t, acc);
        __syncthreads();
    }

    /* phase-1 epilogue: H = D + bias0; A = split(relu(H)) */
    #pragma unroll
    for (int nt = 0; nt < 16; nt++) {
        int col = nt*8 + colb;
        float bc0 = g_bias0[col], bc1 = g_bias0[col+1];
        float v00 = acc[nt][0] + bc0, v01 = acc[nt][1] + bc1;
        float v10 = acc[nt][2] + bc0, v11 = acc[nt][3] + bc1;
        H[r0*HSTW + col] = v00; H[r0*HSTW + col+1] = v01;
        H[r1*HSTW + col] = v10; H[r1*HSTW + col+1] = v11;
        u32 phi, plo;
        split_pack(fmaxf(v00, 0.f), fmaxf(v01, 0.f), phi, plo);
        *(u32*)(smem + AHI + r0*AST + col*2) = phi;
        *(u32*)(smem + ALO + r0*AST + col*2) = plo;
        split_pack(fmaxf(v10, 0.f), fmaxf(v11, 0.f), phi, plo);
        *(u32*)(smem + AHI + r1*AST + col*2) = phi;
        *(u32*)(smem + ALO + r1*AST + col*2) = plo;
    }

    /* ---- resnet blocks ---- */
    #pragma unroll 1
    for (int blk = 0; blk < NB; blk++) {
        /* GEMM1: t = relu(relu(h) @ W1^T + b1) */
        copy_img(smem, g_B1_hi[blk], g_B1_lo[blk], tid);
        __syncthreads();
        #pragma unroll
        for (int i = 0; i < 16; i++)
            #pragma unroll
            for (int j = 0; j < 4; j++) acc[i][j] = 0.f;
        gemm3(ahi, alo, bhi, blo, 8, a_t, b_t, acc);
        __syncthreads();

        const float* bb1 = b1g + blk*CH;
        #pragma unroll
        for (int nt = 0; nt < 16; nt++) {
            int col = nt*8 + colb;
            float bc0 = bb1[col], bc1 = bb1[col+1];
            float v00 = fmaxf(acc[nt][0] + bc0, 0.f), v01 = fmaxf(acc[nt][1] + bc1, 0.f);
            float v10 = fmaxf(acc[nt][2] + bc0, 0.f), v11 = fmaxf(acc[nt][3] + bc1, 0.f);
            u32 phi, plo;
            split_pack(v00, v01, phi, plo);
            *(u32*)(smem + AHI + r0*AST + col*2) = phi;
            *(u32*)(smem + ALO + r0*AST + col*2) = plo;
            split_pack(v10, v11, phi, plo);
            *(u32*)(smem + AHI + r1*AST + col*2) = phi;
            *(u32*)(smem + ALO + r1*AST + col*2) = plo;
        }
        /* GEMM2: h += t @ W2^T + b2 */
        copy_img(smem, g_B2_hi[blk], g_B2_lo[blk], tid);
        __syncthreads();
        #pragma unroll
        for (int i = 0; i < 16; i++)
            #pragma unroll
            for (int j = 0; j < 4; j++) acc[i][j] = 0.f;
        gemm3(ahi, alo, bhi, blo, 8, a_t, b_t, acc);
        __syncthreads();

        const float* bb2 = b2g + blk*CH;
        bool last = (blk == NB-1);
        #pragma unroll
        for (int nt = 0; nt < 16; nt++) {
            int col = nt*8 + colb;
            float bc0 = bb2[col], bc1 = bb2[col+1];
            float v00 = H[r0*HSTW + col]   + acc[nt][0] + bc0;
            float v01 = H[r0*HSTW + col+1] + acc[nt][1] + bc1;
            float v10 = H[r1*HSTW + col]   + acc[nt][2] + bc0;
            float v11 = H[r1*HSTW + col+1] + acc[nt][3] + bc1;
            float w00 = fmaxf(v00, 0.f), w01 = fmaxf(v01, 0.f);
            float w10 = fmaxf(v10, 0.f), w11 = fmaxf(v11, 0.f);
            if (last) {
                H[r0*HSTW + col] = w00; H[r0*HSTW + col+1] = w01;
                H[r1*HSTW + col] = w10; H[r1*HSTW + col+1] = w11;
            } else {
                H[r0*HSTW + col] = v00; H[r0*HSTW + col+1] = v01;
                H[r1*HSTW + col] = v10; H[r1*HSTW + col+1] = v11;
                u32 phi, plo;
                split_pack(w00, w01, phi, plo);
                *(u32*)(smem + AHI + r0*AST + col*2) = phi;
                *(u32*)(smem + ALO + r0*AST + col*2) = plo;
                split_pack(w10, w11, phi, plo);
                *(u32*)(smem + AHI + r1*AST + col*2) = phi;
                *(u32*)(smem + ALO + r1*AST + col*2) = plo;
            }
        }
    }
    __syncthreads();

    /* ---- head: 7 outputs per token (H holds relu(h)) ---- */
    if (tid < TILE_M) {
        int m = tid;
        float o[7];
        #pragma unroll
        for (int j = 0; j < 7; j++) o[j] = g_bout[j];
        const float* rrow = H + m*HSTW;
        #pragma unroll 4
        for (int k = 0; k < CH; k++) {
            float r = rrow[k];
            const float* wp = g_WTout + k*8;
            #pragma unroll
            for (int j = 0; j < 7; j++) o[j] = fmaf(r, wp[j], o[j]);
        }
        float d0 = softplus_f(o[0]) * softplus_f(o[5]) + softplus_f(o[6]);
        int g = tok0 + m;
        g_scratch[g*5 + 0] = d0;
        g_scratch[g*5 + 1] = o[1];
        g_scratch[g*5 + 2] = o[2];
        g_scratch[g*5 + 3] = o[3];
        g_scratch[g*5 + 4] = o[4];
    }
}

/* ---------------- zero + band writer: one CTA per output row ---------------- */
__global__ void band_kernel(float* __restrict__ out, const float* __restrict__ smp)
{
    const float sm = *smp;
    int row = blockIdx.x;
    int i   = row & (NTOK - 1);
    size_t base = (size_t)row * NTOK;
    int t = threadIdx.x;

    float d0 = sm * g_scratch[row*5 + 0];
    float d1 = (i >= 1) ? sm * (g_scratch[row*5 + 1] + g_scratch[(row-1)*5 + 3]) : 0.f;
    float d2 = (i >= 2) ? sm * (g_scratch[row*5 + 2] + g_scratch[(row-2)*5 + 4]) : 0.f;

    #pragma unroll
    for (int q = 0; q < 8; q++) {
        int v  = q*128 + t;
        int c0 = v*4;
        float4 val = make_float4(0.f, 0.f, 0.f, 0.f);
        if (c0 <= i && c0 + 3 >= i - 2) {
            float* f = (float*)&val;
            #pragma unroll
            for (int e = 0; e < 4; e++) {
                int col = c0 + e;
                if (col == i)          f[e] = d0;
                else if (col == i - 1) f[e] = d1;
                else if (col == i - 2) f[e] = d2;
            }
        }
        *(float4*)(out + base + c0) = val;
    }
}

/* ---------------- launch ---------------- */
extern "C" void kernel_launch(void* const* d_in, const int* in_sizes, int n_in,
                              void* d_out, int out_size)
{
    (void)in_sizes; (void)n_in; (void)out_size;
    const float* s    = (const float*)d_in[0];
    const float* si   = (const float*)d_in[1];
    const float* ds   = (const float*)d_in[2];
    const float* Win  = (const float*)d_in[3];
    const float* bin  = (const float*)d_in[4];
    const float* Wini = (const float*)d_in[5];
    const float* bini = (const float*)d_in[6];
    const float* Wd   = (const float*)d_in[7];
    const float* bd   = (const float*)d_in[8];
    const float* W1   = (const float*)d_in[9];
    const float* b1   = (const float*)d_in[10];
    const float* W2   = (const float*)d_in[11];
    const float* b2   = (const float*)d_in[12];
    const float* Wout = (const float*)d_in[13];
    const float* bout = (const float*)d_in[14];
    const float* Wmu  = (const float*)d_in[15];
    const float* bmu  = (const float*)d_in[16];
    const float* smod = (const float*)d_in[17];
    float* out = (float*)d_out;

    cudaFuncSetAttribute(fused_mlp_kernel,
                         cudaFuncAttributeMaxDynamicSharedMemorySize, SMEM_TOTAL);

    prep_kernel<<<148, 256>>>(Win, bin, Wini, bini, Wd, bd, W1, W2, Wout, bout, Wmu, bmu);
    fused_mlp_kernel<<<TOKENS/TILE_M, NTHR, SMEM_TOTAL>>>(s, si, ds, b1, b2);
    band_kernel<<<TOKENS, 128>>>(out, smod);
}

// round 8
// speedup vs baseline: 1.4320x; 1.0236x over previous
#include <cuda_runtime.h>
#include <cuda_bf16.h>
#include <math.h>

typedef unsigned int u32;
typedef unsigned long long u64;

#define BSZ     4
#define NTOK    4096
#define C_IN    384
#define C_DSSP  64
#define CH      128
#define NB      4
#define TOKENS  (BSZ*NTOK)   /* 16384 */
#define TILE_M  128
#define NTHR    256
#define HSTW    132          /* H fp32 row stride (floats) */
#define AST     272          /* A/B smem row stride in BYTES (136 bf16) */

/* smem layout (bytes) */
#define AHI   0
#define ALO   34816
#define BHI   69632
#define BLO   104448
#define HOF   139264
#define SMEM_TOTAL (HOF + TILE_M*HSTW*4)   /* 206848 */

#define IMG_BYTES 34816      /* one B image: 128 rows x 136 bf16 */

/* ---------------- device scratch (no allocations allowed) ---------------- */
__device__ __align__(16) char g_Bcat_hi[7][IMG_BYTES];
__device__ __align__(16) char g_Bcat_lo[7][IMG_BYTES];
__device__ __align__(16) char g_B1_hi[NB][IMG_BYTES];
__device__ __align__(16) char g_B1_lo[NB][IMG_BYTES];
__device__ __align__(16) char g_B2_hi[NB][IMG_BYTES];
__device__ __align__(16) char g_B2_lo[NB][IMG_BYTES];
__device__ __align__(16) float g_WTout[CH*8];
__device__ float g_bias0[CH];
__device__ float g_bout[8];
__device__ float g_scratch[TOKENS*5];

/* ---------------- helpers ---------------- */
__device__ __forceinline__ u32 smem_u32(const void* p) {
    u32 a;
    asm("{ .reg .u64 t; cvta.to.shared.u64 t, %1; cvt.u32.u64 %0, t; }" : "=r"(a) : "l"(p));
    return a;
}
__device__ __forceinline__ void ldsm4(u32& r0, u32& r1, u32& r2, u32& r3, u32 addr)
{
    asm volatile("ldmatrix.sync.aligned.m8n8.x4.shared.b16 {%0,%1,%2,%3}, [%4];"
        : "=r"(r0), "=r"(r1), "=r"(r2), "=r"(r3) : "r"(addr));
}
__device__ __forceinline__ void mma16816(float (&c)[4], const u32 (&a)[4], u32 b0, u32 b1)
{
    asm volatile("mma.sync.aligned.m16n8k16.row.col.f32.bf16.bf16.f32 "
        "{%0,%1,%2,%3},{%4,%5,%6,%7},{%8,%9},{%0,%1,%2,%3};"
        : "+f"(c[0]), "+f"(c[1]), "+f"(c[2]), "+f"(c[3])
        : "r"(a[0]), "r"(a[1]), "r"(a[2]), "r"(a[3]), "r"(b0), "r"(b1));
}
__device__ __forceinline__ void split_pack(float a, float b, u32& phi, u32& plo)
{
    __nv_bfloat16 ha = __float2bfloat16(a);
    __nv_bfloat16 hb = __float2bfloat16(b);
    __nv_bfloat16 la = __float2bfloat16(a - __bfloat162float(ha));
    __nv_bfloat16 lb = __float2bfloat16(b - __bfloat162float(hb));
    phi = (u32)__bfloat16_as_ushort(ha) | ((u32)__bfloat16_as_ushort(hb) << 16);
    plo = (u32)__bfloat16_as_ushort(la) | ((u32)__bfloat16_as_ushort(lb) << 16);
}
__device__ __forceinline__ float softplus_f(float x)
{
    return fmaxf(x, 0.f) + log1pf(expf(-fabsf(x)));
}

/* ---------------- prep: bf16-split weights into [n][k] images ---------------- */
__global__ void prep_kernel(
    const float* __restrict__ Win,  const float* __restrict__ bin,
    const float* __restrict__ Wini, const float* __restrict__ bini,
    const float* __restrict__ Wd,   const float* __restrict__ bd,
    const float* __restrict__ W1,   const float* __restrict__ W2,
    const float* __restrict__ Wout, const float* __restrict__ bout,
    const float* __restrict__ Wmu,  const float* __restrict__ bmu)
{
    int id = blockIdx.x * blockDim.x + threadIdx.x;
    int stride = gridDim.x * blockDim.x;

    for (int x = id; x < 128*832; x += stride) {
        int n = x / 832, k = x % 832;
        float v;
        if (k < 384)       v = Win [n*384 + k];
        else if (k < 768)  v = Wini[n*384 + (k-384)];
        else               v = Wd  [n*64  + (k-768)];
        int c = k >> 7, kc = k & 127;
        __nv_bfloat16 h = __float2bfloat16(v);
        __nv_bfloat16 l = __float2bfloat16(v - __bfloat162float(h));
        int off = (n*136 + kc)*2;
        *(__nv_bfloat16*)(g_Bcat_hi[c] + off) = h;
        *(__nv_bfloat16*)(g_Bcat_lo[c] + off) = l;
    }
    for (int x = id; x < NB*128*128; x += stride) {
        int blk = x >> 14; int r = x & 16383; int n = r >> 7; int k = r & 127;
        int off = (n*136 + k)*2;
        float v1 = W1[x];
        __nv_bfloat16 h1 = __float2bfloat16(v1);
        __nv_bfloat16 l1 = __float2bfloat16(v1 - __bfloat162float(h1));
        *(__nv_bfloat16*)(g_B1_hi[blk] + off) = h1;
        *(__nv_bfloat16*)(g_B1_lo[blk] + off) = l1;
        float v2 = W2[x];
        __nv_bfloat16 h2 = __float2bfloat16(v2);
        __nv_bfloat16 l2 = __float2bfloat16(v2 - __bfloat162float(h2));
        *(__nv_bfloat16*)(g_B2_hi[blk] + off) = h2;
        *(__nv_bfloat16*)(g_B2_lo[blk] + off) = l2;
    }
    for (int x = id; x < CH*8; x += stride) {
        int k = x / 8, j = x % 8;
        float v = 0.f;
        if (j < 5)      v = Wout[j*CH + k];
        else if (j < 7) v = Wmu [(j-5)*CH + k];
        g_WTout[x] = v;
    }
    if (id < CH) g_bias0[id] = bin[id] + bini[id] + bd[id];
    if (id < 8)  g_bout[id] = (id < 5) ? bout[id] : ((id < 7) ? bmu[id-5] : 0.f);
}

/* ---------------- fused-pass GEMM core with B-fragment pipelining ----------------
   Per k-step: load Ahi/Alo once (2 LDSM), stream B tiles with 1-tile lookahead
   (2 LDSM per tile), issue 6 MMAs per tile (hi*hi + lo*hi + hi*lo). */
__device__ __forceinline__ void gemm3(u32 ahi, u32 alo, u32 bhi, u32 blo,
                                      int nks, u32 a_t, u32 b_t, float (&acc)[16][4])
{
    #pragma unroll 1
    for (int ks = 0; ks < nks; ks++) {
        u32 ah[4], al[4];
        ldsm4(ah[0], ah[1], ah[2], ah[3], ahi + a_t + ks*32);
        ldsm4(al[0], al[1], al[2], al[3], alo + a_t + ks*32);
        u32 bh[4], bl[4], nh[4], nl[4];
        ldsm4(bh[0], bh[1], bh[2], bh[3], bhi + b_t + ks*32);
        ldsm4(bl[0], bl[1], bl[2], bl[3], blo + b_t + ks*32);
        #pragma unroll
        for (int np = 0; np < 8; np++) {
            if (np < 7) {
                u32 off = b_t + (np+1)*4352 + ks*32;
                ldsm4(nh[0], nh[1], nh[2], nh[3], bhi + off);
                ldsm4(nl[0], nl[1], nl[2], nl[3], blo + off);
            }
            mma16816(acc[2*np],   ah, bh[0], bh[1]);
            mma16816(acc[2*np+1], ah, bh[2], bh[3]);
            mma16816(acc[2*np],   al, bh[0], bh[1]);
            mma16816(acc[2*np+1], al, bh[2], bh[3]);
            mma16816(acc[2*np],   ah, bl[0], bl[1]);
            mma16816(acc[2*np+1], ah, bl[2], bl[3]);
            #pragma unroll
            for (int q = 0; q < 4; q++) { bh[q] = nh[q]; bl[q] = nl[q]; }
        }
    }
}

__device__ __forceinline__ void copy_img(char* smem, const char* hi, const char* lo, int tid)
{
    const uint4* sh = (const uint4*)hi;
    const uint4* sl = (const uint4*)lo;
    uint4* dh = (uint4*)(smem + BHI);
    uint4* dl = (uint4*)(smem + BLO);
    #pragma unroll 1
    for (int i = tid; i < IMG_BYTES/16; i += NTHR) { dh[i] = sh[i]; dl[i] = sl[i]; }
}

/* ---------------- fused MLP kernel: 128 tokens/CTA, mma.sync GEMMs ---------------- */
__global__ __launch_bounds__(NTHR, 1) void fused_mlp_kernel(
    const float* __restrict__ s, const float* __restrict__ si, const float* __restrict__ ds,
    const float* __restrict__ b1g, const float* __restrict__ b2g)
{
    extern __shared__ char smem[];
    float* H = (float*)(smem + HOF);
    const int tid  = threadIdx.x;
    const int w    = tid >> 5;
    const int lane = tid & 31;
    const int seg  = lane >> 3;
    const int rr   = lane & 7;
    const int tok0 = blockIdx.x * TILE_M;

    const u32 a_t = (u32)((w*16 + (seg & 1)*8 + rr)*AST + (seg >> 1)*16);
    const u32 b_t = (u32)(((seg >> 1)*8 + rr)*AST + (seg & 1)*16);
    const int r0   = w*16 + (lane >> 2);
    const int r1   = r0 + 8;
    const int colb = (lane & 3)*2;

    u32 sb  = smem_u32(smem);
    u32 ahi = sb + AHI, alo = sb + ALO, bhi = sb + BHI, blo = sb + BLO;

    float acc[16][4];
    #pragma unroll
    for (int i = 0; i < 16; i++)
        #pragma unroll
        for (int j = 0; j < 4; j++) acc[i][j] = 0.f;

    /* ---- phase 1: accumulate 7 K-chunks of the concat input GEMM ---- */
    #pragma unroll 1
    for (int c = 0; c < 7; c++) {
        const float* src; int Krow, Kc;
        if (c < 3)      { src = s  + (size_t)tok0*C_IN   + c*128;     Krow = C_IN;   Kc = 128; }
        else if (c < 6) { src = si + (size_t)tok0*C_IN   + (c-3)*128; Krow = C_IN;   Kc = 128; }
        else            { src = ds + (size_t)tok0*C_DSSP;             Krow = C_DSSP; Kc = 64;  }
        int hp = Kc >> 1;                       /* pairs per row */
        int total = 128*hp;
        int pl = (Kc == 128) ? 6 : 5, pm = hp - 1;
        #pragma unroll 1
        for (int idx = tid; idx < total; idx += NTHR) {
            int m = idx >> pl, kp = idx & pm;
            float2 v = *(const float2*)(src + (size_t)m*Krow + kp*2);
            u32 phi, plo;
            split_pack(fmaxf(v.x, 0.f), fmaxf(v.y, 0.f), phi, plo);
            int o = m*AST + kp*4;
            *(u32*)(smem + AHI + o) = phi;
            *(u32*)(smem + ALO + o) = plo;
        }
        copy_img(smem, g_Bcat_hi[c], g_Bcat_lo[c], tid);
        __syncthreads();
        gemm3(ahi, alo, bhi, blo, (Kc == 128) ? 8 : 4, a_t, b_t, acc);
        __syncthreads();
    }

    /* phase-1 epilogue: H = D + bias0; A = split(relu(H)) */
    #pragma unroll
    for (int nt = 0; nt < 16; nt++) {
        int col = nt*8 + colb;
        float bc0 = g_bias0[col], bc1 = g_bias0[col+1];
        float v00 = acc[nt][0] + bc0, v01 = acc[nt][1] + bc1;
        float v10 = acc[nt][2] + bc0, v11 = acc[nt][3] + bc1;
        H[r0*HSTW + col] = v00; H[r0*HSTW + col+1] = v01;
        H[r1*HSTW + col] = v10; H[r1*HSTW + col+1] = v11;
        u32 phi, plo;
        split_pack(fmaxf(v00, 0.f), fmaxf(v01, 0.f), phi, plo);
        *(u32*)(smem + AHI + r0*AST + col*2) = phi;
        *(u32*)(smem + ALO + r0*AST + col*2) = plo;
        split_pack(fmaxf(v10, 0.f), fmaxf(v11, 0.f), phi, plo);
        *(u32*)(smem + AHI + r1*AST + col*2) = phi;
        *(u32*)(smem + ALO + r1*AST + col*2) = plo;
    }

    /* ---- resnet blocks ---- */
    #pragma unroll 1
    for (int blk = 0; blk < NB; blk++) {
        /* GEMM1: t = relu(relu(h) @ W1^T + b1) */
        copy_img(smem, g_B1_hi[blk], g_B1_lo[blk], tid);
        __syncthreads();
        #pragma unroll
        for (int i = 0; i < 16; i++)
            #pragma unroll
            for (int j = 0; j < 4; j++) acc[i][j] = 0.f;
        gemm3(ahi, alo, bhi, blo, 8, a_t, b_t, acc);
        __syncthreads();

        const float* bb1 = b1g + blk*CH;
        #pragma unroll
        for (int nt = 0; nt < 16; nt++) {
            int col = nt*8 + colb;
            float bc0 = bb1[col], bc1 = bb1[col+1];
            float v00 = fmaxf(acc[nt][0] + bc0, 0.f), v01 = fmaxf(acc[nt][1] + bc1, 0.f);
            float v10 = fmaxf(acc[nt][2] + bc0, 0.f), v11 = fmaxf(acc[nt][3] + bc1, 0.f);
            u32 phi, plo;
            split_pack(v00, v01, phi, plo);
            *(u32*)(smem + AHI + r0*AST + col*2) = phi;
            *(u32*)(smem + ALO + r0*AST + col*2) = plo;
            split_pack(v10, v11, phi, plo);
            *(u32*)(smem + AHI + r1*AST + col*2) = phi;
            *(u32*)(smem + ALO + r1*AST + col*2) = plo;
        }
        /* GEMM2: h += t @ W2^T + b2 */
        copy_img(smem, g_B2_hi[blk], g_B2_lo[blk], tid);
        __syncthreads();
        #pragma unroll
        for (int i = 0; i < 16; i++)
            #pragma unroll
            for (int j = 0; j < 4; j++) acc[i][j] = 0.f;
        gemm3(ahi, alo, bhi, blo, 8, a_t, b_t, acc);
        __syncthreads();

        const float* bb2 = b2g + blk*CH;
        bool last = (blk == NB-1);
        #pragma unroll
        for (int nt = 0; nt < 16; nt++) {
            int col = nt*8 + colb;
            float bc0 = bb2[col], bc1 = bb2[col+1];
            float v00 = H[r0*HSTW + col]   + acc[nt][0] + bc0;
            float v01 = H[r0*HSTW + col+1] + acc[nt][1] + bc1;
            float v10 = H[r1*HSTW + col]   + acc[nt][2] + bc0;
            float v11 = H[r1*HSTW + col+1] + acc[nt][3] + bc1;
            float w00 = fmaxf(v00, 0.f), w01 = fmaxf(v01, 0.f);
            float w10 = fmaxf(v10, 0.f), w11 = fmaxf(v11, 0.f);
            if (last) {
                H[r0*HSTW + col] = w00; H[r0*HSTW + col+1] = w01;
                H[r1*HSTW + col] = w10; H[r1*HSTW + col+1] = w11;
            } else {
                H[r0*HSTW + col] = v00; H[r0*HSTW + col+1] = v01;
                H[r1*HSTW + col] = v10; H[r1*HSTW + col+1] = v11;
                u32 phi, plo;
                split_pack(w00, w01, phi, plo);
                *(u32*)(smem + AHI + r0*AST + col*2) = phi;
                *(u32*)(smem + ALO + r0*AST + col*2) = plo;
                split_pack(w10, w11, phi, plo);
                *(u32*)(smem + AHI + r1*AST + col*2) = phi;
                *(u32*)(smem + ALO + r1*AST + col*2) = plo;
            }
        }
    }
    __syncthreads();

    /* ---- head: 7 outputs per token (H holds relu(h)) ---- */
    if (tid < TILE_M) {
        int m = tid;
        float o[7];
        #pragma unroll
        for (int j = 0; j < 7; j++) o[j] = g_bout[j];
        const float* rrow = H + m*HSTW;
        #pragma unroll 4
        for (int k = 0; k < CH; k++) {
            float r = rrow[k];
            const float* wp = g_WTout + k*8;
            #pragma unroll
            for (int j = 0; j < 7; j++) o[j] = fmaf(r, wp[j], o[j]);
        }
        float d0 = softplus_f(o[0]) * softplus_f(o[5]) + softplus_f(o[6]);
        int g = tok0 + m;
        g_scratch[g*5 + 0] = d0;
        g_scratch[g*5 + 1] = o[1];
        g_scratch[g*5 + 2] = o[2];
        g_scratch[g*5 + 3] = o[3];
        g_scratch[g*5 + 4] = o[4];
    }
}

/* ---------------- zero + band writer: one CTA per output row ---------------- */
__global__ void band_kernel(float* __restrict__ out, const float* __restrict__ smp)
{
    const float sm = *smp;
    int row = blockIdx.x;
    int i   = row & (NTOK - 1);
    size_t base = (size_t)row * NTOK;
    int t = threadIdx.x;

    float d0 = sm * g_scratch[row*5 + 0];
    float d1 = (i >= 1) ? sm * (g_scratch[row*5 + 1] + g_scratch[(row-1)*5 + 3]) : 0.f;
    float d2 = (i >= 2) ? sm * (g_scratch[row*5 + 2] + g_scratch[(row-2)*5 + 4]) : 0.f;

    #pragma unroll
    for (int q = 0; q < 8; q++) {
        int v  = q*128 + t;
        int c0 = v*4;
        float4 val = make_float4(0.f, 0.f, 0.f, 0.f);
        if (c0 <= i && c0 + 3 >= i - 2) {
            float* f = (float*)&val;
            #pragma unroll
            for (int e = 0; e < 4; e++) {
                int col = c0 + e;
                if (col == i)          f[e] = d0;
                else if (col == i - 1) f[e] = d1;
                else if (col == i - 2) f[e] = d2;
            }
        }
        *(float4*)(out + base + c0) = val;
    }
}

/* ---------------- launch ---------------- */
extern "C" void kernel_launch(void* const* d_in, const int* in_sizes, int n_in,
                              void* d_out, int out_size)
{
    (void)in_sizes; (void)n_in; (void)out_size;
    const float* s    = (const float*)d_in[0];
    const float* si   = (const float*)d_in[1];
    const float* ds   = (const float*)d_in[2];
    const float* Win  = (const float*)d_in[3];
    const float* bin  = (const float*)d_in[4];
    const float* Wini = (const float*)d_in[5];
    const float* bini = (const float*)d_in[6];
    const float* Wd   = (const float*)d_in[7];
    const float* bd   = (const float*)d_in[8];
    const float* W1   = (const float*)d_in[9];
    const float* b1   = (const float*)d_in[10];
    const float* W2   = (const float*)d_in[11];
    const float* b2   = (const float*)d_in[12];
    const float* Wout = (const float*)d_in[13];
    const float* bout = (const float*)d_in[14];
    const float* Wmu  = (const float*)d_in[15];
    const float* bmu  = (const float*)d_in[16];
    const float* smod = (const float*)d_in[17];
    float* out = (float*)d_out;

    cudaFuncSetAttribute(fused_mlp_kernel,
                         cudaFuncAttributeMaxDynamicSharedMemorySize, SMEM_TOTAL);

    prep_kernel<<<148, 256>>>(Win, bin, Wini, bini, Wd, bd, W1, W2, Wout, bout, Wmu, bmu);
    fused_mlp_kernel<<<TOKENS/TILE_M, NTHR, SMEM_TOTAL>>>(s, si, ds, b1, b2);
    band_kernel<<<TOKENS, 128>>>(out, smod);
}

// round 9
// speedup vs baseline: 1.8107x; 1.2644x over previous
#include <cuda_runtime.h>
#include <cuda_fp16.h>
#include <math.h>

typedef unsigned int u32;
typedef unsigned long long u64;

#define BSZ     4
#define NTOK    4096
#define C_IN    384
#define C_DSSP  64
#define CH      128
#define NB      4
#define TOKENS  (BSZ*NTOK)   /* 16384 */
#define TILE_M  128
#define NTHR    256
#define HSTW    132          /* H fp32 row stride (floats) */
#define AST     272          /* A/B smem row stride in BYTES (136 fp16) */
#define NSTAGES 15           /* 7 phase-1 + 8 resnet GEMM stages */

/* smem layout (bytes) */
#define AHI   0
#define ALO   34816
#define BB0   69632
#define BB1   104448
#define HOF   139264
#define SMEM_TOTAL (HOF + TILE_M*HSTW*4)   /* 206848 */

#define IMG_BYTES 34816      /* one B image: 128 rows x 136 fp16 */
#define IMG_V16   (IMG_BYTES/16)   /* 2176 */

/* ---------------- device scratch (no allocations allowed) ---------------- */
__device__ __align__(16) char g_Bcat[7][IMG_BYTES];
__device__ __align__(16) char g_B1[NB][IMG_BYTES];
__device__ __align__(16) char g_B2[NB][IMG_BYTES];
__device__ __align__(16) float g_WTout[CH*8];
__device__ float g_bias0[CH];
__device__ float g_bout[8];
__device__ float g_scratch[TOKENS*5];

/* ---------------- helpers ---------------- */
__device__ __forceinline__ u32 smem_u32(const void* p) {
    u32 a;
    asm("{ .reg .u64 t; cvta.to.shared.u64 t, %1; cvt.u32.u64 %0, t; }" : "=r"(a) : "l"(p));
    return a;
}
__device__ __forceinline__ void ldsm4(u32& r0, u32& r1, u32& r2, u32& r3, u32 addr)
{
    asm volatile("ldmatrix.sync.aligned.m8n8.x4.shared.b16 {%0,%1,%2,%3}, [%4];"
        : "=r"(r0), "=r"(r1), "=r"(r2), "=r"(r3) : "r"(addr));
}
__device__ __forceinline__ void mma16816(float (&c)[4], const u32 (&a)[4], u32 b0, u32 b1)
{
    asm volatile("mma.sync.aligned.m16n8k16.row.col.f32.f16.f16.f32 "
        "{%0,%1,%2,%3},{%4,%5,%6,%7},{%8,%9},{%0,%1,%2,%3};"
        : "+f"(c[0]), "+f"(c[1]), "+f"(c[2]), "+f"(c[3])
        : "r"(a[0]), "r"(a[1]), "r"(a[2]), "r"(a[3]), "r"(b0), "r"(b1));
}
__device__ __forceinline__ void split_pack_h(float a, float b, u32& phi, u32& plo)
{
    __half ha = __float2half_rn(a), hb = __float2half_rn(b);
    __half la = __float2half_rn(a - __half2float(ha));
    __half lb = __float2half_rn(b - __half2float(hb));
    phi = (u32)__half_as_ushort(ha) | ((u32)__half_as_ushort(hb) << 16);
    plo = (u32)__half_as_ushort(la) | ((u32)__half_as_ushort(lb) << 16);
}
__device__ __forceinline__ float softplus_f(float x)
{
    return fmaxf(x, 0.f) + log1pf(expf(-fabsf(x)));
}
__device__ __forceinline__ const char* stage_img(int s)
{
    if (s < 7) return g_Bcat[s];
    int r = s - 7;
    return (r & 1) ? g_B2[r >> 1] : g_B1[r >> 1];
}
__device__ __forceinline__ void prefetch_img(const char* src, u32 dst, int tid)
{
    u64 g = __cvta_generic_to_global(src);
    #pragma unroll
    for (int i = 0; i < 9; i++) {
        int idx = i*NTHR + tid;
        if (idx < IMG_V16)
            asm volatile("cp.async.cg.shared.global [%0], [%1], 16;"
                :: "r"(dst + idx*16), "l"(g + (u64)idx*16));
    }
}
#define CP_COMMIT()  asm volatile("cp.async.commit_group;" ::: "memory")
#define CP_WAIT1()   asm volatile("cp.async.wait_group 1;" ::: "memory")

/* zero ~35 float4 slices of this CTA's output region per stage (streamed) */
__device__ __forceinline__ void zero_chunk(float* zbase, int s, int tid)
{
    int j0 = s*35, j1 = j0+35; if (j1 > 512) j1 = 512;
    #pragma unroll 1
    for (int j = j0; j < j1; j++) {
        float* p = zbase + (size_t)(j*256 + tid)*4;
        asm volatile("st.global.cs.v4.f32 [%0], {%1,%1,%1,%1};"
            :: "l"(p), "f"(0.f) : "memory");
    }
}

/* ---------------- prep: fp16 weights into [n][k] images ---------------- */
__global__ void prep_kernel(
    const float* __restrict__ Win,  const float* __restrict__ bin,
    const float* __restrict__ Wini, const float* __restrict__ bini,
    const float* __restrict__ Wd,   const float* __restrict__ bd,
    const float* __restrict__ W1,   const float* __restrict__ W2,
    const float* __restrict__ Wout, const float* __restrict__ bout,
    const float* __restrict__ Wmu,  const float* __restrict__ bmu)
{
    int id = blockIdx.x * blockDim.x + threadIdx.x;
    int stride = gridDim.x * blockDim.x;

    for (int x = id; x < 128*832; x += stride) {
        int n = x / 832, k = x % 832;
        float v;
        if (k < 384)       v = Win [n*384 + k];
        else if (k < 768)  v = Wini[n*384 + (k-384)];
        else               v = Wd  [n*64  + (k-768)];
        int c = k >> 7, kc = k & 127;
        *(__half*)(g_Bcat[c] + (n*136 + kc)*2) = __float2half_rn(v);
    }
    for (int x = id; x < NB*128*128; x += stride) {
        int blk = x >> 14; int r = x & 16383; int n = r >> 7; int k = r & 127;
        int off = (n*136 + k)*2;
        *(__half*)(g_B1[blk] + off) = __float2half_rn(W1[x]);
        *(__half*)(g_B2[blk] + off) = __float2half_rn(W2[x]);
    }
    for (int x = id; x < CH*8; x += stride) {
        int k = x / 8, j = x % 8;
        float v = 0.f;
        if (j < 5)      v = Wout[j*CH + k];
        else if (j < 7) v = Wmu [(j-5)*CH + k];
        g_WTout[x] = v;
    }
    if (id < CH) g_bias0[id] = bin[id] + bini[id] + bd[id];
    if (id < 8)  g_bout[id] = (id < 5) ? bout[id] : ((id < 7) ? bmu[id-5] : 0.f);
}

/* ---------------- 2-pass split GEMM core (A = hi+lo, B = fp16 hi) ---------------- */
__device__ __forceinline__ void gemm2(u32 ahi, u32 alo, u32 bimg,
                                      int nks, u32 a_t, u32 b_t, float (&acc)[16][4])
{
    #pragma unroll 1
    for (int ks = 0; ks < nks; ks++) {
        u32 ah[4], al[4];
        ldsm4(ah[0], ah[1], ah[2], ah[3], ahi + a_t + ks*32);
        ldsm4(al[0], al[1], al[2], al[3], alo + a_t + ks*32);
        u32 bc[4], bn[4];
        ldsm4(bc[0], bc[1], bc[2], bc[3], bimg + b_t + ks*32);
        #pragma unroll
        for (int np = 0; np < 8; np++) {
            if (np < 7)
                ldsm4(bn[0], bn[1], bn[2], bn[3], bimg + b_t + (np+1)*4352 + ks*32);
            mma16816(acc[2*np],   ah, bc[0], bc[1]);
            mma16816(acc[2*np+1], ah, bc[2], bc[3]);
            mma16816(acc[2*np],   al, bc[0], bc[1]);
            mma16816(acc[2*np+1], al, bc[2], bc[3]);
            bc[0] = bn[0]; bc[1] = bn[1]; bc[2] = bn[2]; bc[3] = bn[3];
        }
    }
}

/* ---------------- fused MLP kernel ---------------- */
__global__ __launch_bounds__(NTHR, 1) void fused_mlp_kernel(
    const float* __restrict__ s, const float* __restrict__ si, const float* __restrict__ ds,
    const float* __restrict__ b1g, const float* __restrict__ b2g,
    float* __restrict__ out)
{
    extern __shared__ char smem[];
    float* H = (float*)(smem + HOF);
    const int tid  = threadIdx.x;
    const int w    = tid >> 5;
    const int lane = tid & 31;
    const int seg  = lane >> 3;
    const int rr   = lane & 7;
    const int tok0 = blockIdx.x * TILE_M;
    float* zbase = out + (size_t)tok0 * NTOK;   /* this CTA's 128 output rows */

    const u32 a_t = (u32)((w*16 + (seg & 1)*8 + rr)*AST + (seg >> 1)*16);
    const u32 b_t = (u32)(((seg >> 1)*8 + rr)*AST + (seg & 1)*16);
    const int r0   = w*16 + (lane >> 2);
    const int r1   = r0 + 8;
    const int colb = (lane & 3)*2;

    u32 sb  = smem_u32(smem);
    u32 ahi = sb + AHI, alo = sb + ALO;
    u32 bb[2] = { sb + BB0, sb + BB1 };

    float acc[16][4];
    #pragma unroll
    for (int i = 0; i < 16; i++)
        #pragma unroll
        for (int j = 0; j < 4; j++) acc[i][j] = 0.f;

    /* initial B prefetch */
    prefetch_img(stage_img(0), bb[0], tid);
    CP_COMMIT();
    int st = 0;

    /* ---- phase 1: accumulate 7 K-chunks of the concat input GEMM ---- */
    #pragma unroll 1
    for (int c = 0; c < 7; c++) {
        if (st+1 < NSTAGES) prefetch_img(stage_img(st+1), bb[(st+1)&1], tid);
        CP_COMMIT();

        const float* src; int Krow, Kc;
        if (c < 3)      { src = s  + (size_t)tok0*C_IN   + c*128;     Krow = C_IN;   Kc = 128; }
        else if (c < 6) { src = si + (size_t)tok0*C_IN   + (c-3)*128; Krow = C_IN;   Kc = 128; }
        else            { src = ds + (size_t)tok0*C_DSSP;             Krow = C_DSSP; Kc = 64;  }
        int hp = Kc >> 1;
        int total = 128*hp;
        int pl = (Kc == 128) ? 6 : 5, pm = hp - 1;
        #pragma unroll 1
        for (int idx = tid; idx < total; idx += NTHR) {
            int m = idx >> pl, kp = idx & pm;
            float2 v = *(const float2*)(src + (size_t)m*Krow + kp*2);
            u32 phi, plo;
            split_pack_h(fmaxf(v.x, 0.f), fmaxf(v.y, 0.f), phi, plo);
            int o = m*AST + kp*4;
            *(u32*)(smem + AHI + o) = phi;
            *(u32*)(smem + ALO + o) = plo;
        }
        CP_WAIT1();
        __syncthreads();
        gemm2(ahi, alo, bb[st&1], (Kc == 128) ? 8 : 4, a_t, b_t, acc);
        zero_chunk(zbase, st, tid);
        __syncthreads();
        st++;
    }

    /* phase-1 epilogue: H = D + bias0; A = split(relu(H)) */
    #pragma unroll
    for (int nt = 0; nt < 16; nt++) {
        int col = nt*8 + colb;
        float bc0 = g_bias0[col], bc1 = g_bias0[col+1];
        float v00 = acc[nt][0] + bc0, v01 = acc[nt][1] + bc1;
        float v10 = acc[nt][2] + bc0, v11 = acc[nt][3] + bc1;
        H[r0*HSTW + col] = v00; H[r0*HSTW + col+1] = v01;
        H[r1*HSTW + col] = v10; H[r1*HSTW + col+1] = v11;
        u32 phi, plo;
        split_pack_h(fmaxf(v00, 0.f), fmaxf(v01, 0.f), phi, plo);
        *(u32*)(smem + AHI + r0*AST + col*2) = phi;
        *(u32*)(smem + ALO + r0*AST + col*2) = plo;
        split_pack_h(fmaxf(v10, 0.f), fmaxf(v11, 0.f), phi, plo);
        *(u32*)(smem + AHI + r1*AST + col*2) = phi;
        *(u32*)(smem + ALO + r1*AST + col*2) = plo;
    }

    /* ---- resnet blocks ---- */
    #pragma unroll 1
    for (int blk = 0; blk < NB; blk++) {
        /* GEMM1: t = relu(relu(h) @ W1^T + b1) */
        if (st+1 < NSTAGES) prefetch_img(stage_img(st+1), bb[(st+1)&1], tid);
        CP_COMMIT();
        CP_WAIT1();
        __syncthreads();       /* epilogue A-writes + B image visible */
        #pragma unroll
        for (int i = 0; i < 16; i++)
            #pragma unroll
            for (int j = 0; j < 4; j++) acc[i][j] = 0.f;
        gemm2(ahi, alo, bb[st&1], 8, a_t, b_t, acc);
        zero_chunk(zbase, st, tid);
        __syncthreads();
        st++;

        const float* bb1 = b1g + blk*CH;
        #pragma unroll
        for (int nt = 0; nt < 16; nt++) {
            int col = nt*8 + colb;
            float bc0 = bb1[col], bc1 = bb1[col+1];
            float v00 = fmaxf(acc[nt][0] + bc0, 0.f), v01 = fmaxf(acc[nt][1] + bc1, 0.f);
            float v10 = fmaxf(acc[nt][2] + bc0, 0.f), v11 = fmaxf(acc[nt][3] + bc1, 0.f);
            u32 phi, plo;
            split_pack_h(v00, v01, phi, plo);
            *(u32*)(smem + AHI + r0*AST + col*2) = phi;
            *(u32*)(smem + ALO + r0*AST + col*2) = plo;
            split_pack_h(v10, v11, phi, plo);
            *(u32*)(smem + AHI + r1*AST + col*2) = phi;
            *(u32*)(smem + ALO + r1*AST + col*2) = plo;
        }

        /* GEMM2: h += t @ W2^T + b2 */
        if (st+1 < NSTAGES) prefetch_img(stage_img(st+1), bb[(st+1)&1], tid);
        CP_COMMIT();
        CP_WAIT1();
        __syncthreads();
        #pragma unroll
        for (int i = 0; i < 16; i++)
            #pragma unroll
            for (int j = 0; j < 4; j++) acc[i][j] = 0.f;
        gemm2(ahi, alo, bb[st&1], 8, a_t, b_t, acc);
        zero_chunk(zbase, st, tid);
        __syncthreads();
        st++;

        const float* bb2 = b2g + blk*CH;
        bool last = (blk == NB-1);
        #pragma unroll
        for (int nt = 0; nt < 16; nt++) {
            int col = nt*8 + colb;
            float bc0 = bb2[col], bc1 = bb2[col+1];
            float v00 = H[r0*HSTW + col]   + acc[nt][0] + bc0;
            float v01 = H[r0*HSTW + col+1] + acc[nt][1] + bc1;
            float v10 = H[r1*HSTW + col]   + acc[nt][2] + bc0;
            float v11 = H[r1*HSTW + col+1] + acc[nt][3] + bc1;
            float w00 = fmaxf(v00, 0.f), w01 = fmaxf(v01, 0.f);
            float w10 = fmaxf(v10, 0.f), w11 = fmaxf(v11, 0.f);
            if (last) {
                H[r0*HSTW + col] = w00; H[r0*HSTW + col+1] = w01;
                H[r1*HSTW + col] = w10; H[r1*HSTW + col+1] = w11;
            } else {
                H[r0*HSTW + col] = v00; H[r0*HSTW + col+1] = v01;
                H[r1*HSTW + col] = v10; H[r1*HSTW + col+1] = v11;
                u32 phi, plo;
                split_pack_h(w00, w01, phi, plo);
                *(u32*)(smem + AHI + r0*AST + col*2) = phi;
                *(u32*)(smem + ALO + r0*AST + col*2) = plo;
                split_pack_h(w10, w11, phi, plo);
                *(u32*)(smem + AHI + r1*AST + col*2) = phi;
                *(u32*)(smem + ALO + r1*AST + col*2) = plo;
            }
        }
    }
    __syncthreads();

    /* ---- head: 7 outputs per token (H holds relu(h)) ---- */
    if (tid < TILE_M) {
        int m = tid;
        float o[7];
        #pragma unroll
        for (int j = 0; j < 7; j++) o[j] = g_bout[j];
        const float* rrow = H + m*HSTW;
        #pragma unroll 4
        for (int k = 0; k < CH; k++) {
            float r = rrow[k];
            const float* wp = g_WTout + k*8;
            #pragma unroll
            for (int j = 0; j < 7; j++) o[j] = fmaf(r, wp[j], o[j]);
        }
        float d0 = softplus_f(o[0]) * softplus_f(o[5]) + softplus_f(o[6]);
        int g = tok0 + m;
        g_scratch[g*5 + 0] = d0;
        g_scratch[g*5 + 1] = o[1];
        g_scratch[g*5 + 2] = o[2];
        g_scratch[g*5 + 3] = o[3];
        g_scratch[g*5 + 4] = o[4];
    }
}

/* ---------------- diagonal writer (zeros already laid down by fused kernel) ---------------- */
__global__ void diag_kernel(float* __restrict__ out, const float* __restrict__ smp)
{
    const float sm = *smp;
    int row = blockIdx.x * blockDim.x + threadIdx.x;   /* 0..16383 */
    int i   = row & (NTOK - 1);
    size_t base = (size_t)row * NTOK;

    float d0 = sm * g_scratch[row*5 + 0];
    out[base + i] = d0;
    if (i >= 1) out[base + i - 1] = sm * (g_scratch[row*5 + 1] + g_scratch[(row-1)*5 + 3]);
    if (i >= 2) out[base + i - 2] = sm * (g_scratch[row*5 + 2] + g_scratch[(row-2)*5 + 4]);
}

/* ---------------- launch ---------------- */
extern "C" void kernel_launch(void* const* d_in, const int* in_sizes, int n_in,
                              void* d_out, int out_size)
{
    (void)in_sizes; (void)n_in; (void)out_size;
    const float* s    = (const float*)d_in[0];
    const float* si   = (const float*)d_in[1];
    const float* ds   = (const float*)d_in[2];
    const float* Win  = (const float*)d_in[3];
    const float* bin  = (const float*)d_in[4];
    const float* Wini = (const float*)d_in[5];
    const float* bini = (const float*)d_in[6];
    const float* Wd   = (const float*)d_in[7];
    const float* bd   = (const float*)d_in[8];
    const float* W1   = (const float*)d_in[9];
    const float* b1   = (const float*)d_in[10];
    const float* W2   = (const float*)d_in[11];
    const float* b2   = (const float*)d_in[12];
    const float* Wout = (const float*)d_in[13];
    const float* bout = (const float*)d_in[14];
    const float* Wmu  = (const float*)d_in[15];
    const float* bmu  = (const float*)d_in[16];
    const float* smod = (const float*)d_in[17];
    float* out = (float*)d_out;

    cudaFuncSetAttribute(fused_mlp_kernel,
                         cudaFuncAttributeMaxDynamicSharedMemorySize, SMEM_TOTAL);

    prep_kernel<<<148, 256>>>(Win, bin, Wini, bini, Wd, bd, W1, W2, Wout, bout, Wmu, bmu);
    fused_mlp_kernel<<<TOKENS/TILE_M, NTHR, SMEM_TOTAL>>>(s, si, ds, b1, b2, out);
    diag_kernel<<<TOKENS/128, 128>>>(out, smod);
}

// round 10
// speedup vs baseline: 2.0415x; 1.1274x over previous
#include <cuda_runtime.h>
#include <cuda_fp16.h>
#include <math.h>

typedef unsigned int u32;
typedef unsigned long long u64;

#define BSZ     4
#define NTOK    4096
#define C_IN    384
#define C_DSSP  64
#define CH      128
#define NB      4
#define TOKENS  (BSZ*NTOK)   /* 16384 */
#define TILE_M  128
#define NTHR    256
#define HSTW    132          /* H fp32 row stride (floats) */
#define AST     272          /* A/B smem row stride in BYTES (136 fp16) */
#define NSTAGES 15           /* 7 phase-1 + 8 resnet GEMM stages */

/* smem layout (bytes) */
#define AIMG  0
#define BB0   34816
#define BB1   69632
#define HOF   104448
#define SMEM_TOTAL (HOF + TILE_M*HSTW*4)   /* 172032 */

#define IMG_BYTES 34816      /* one image: 128 rows x 136 fp16 */
#define IMG_V16   (IMG_BYTES/16)   /* 2176 */

/* ---------------- device scratch (no allocations allowed) ---------------- */
__device__ __align__(16) char g_Bcat[7][IMG_BYTES];
__device__ __align__(16) char g_B1[NB][IMG_BYTES];
__device__ __align__(16) char g_B2[NB][IMG_BYTES];
__device__ __align__(16) float g_WTout[CH*8];
__device__ float g_bias0[CH];
__device__ float g_bout[8];
__device__ float g_scratch[TOKENS*5];

/* ---------------- helpers ---------------- */
__device__ __forceinline__ u32 smem_u32(const void* p) {
    u32 a;
    asm("{ .reg .u64 t; cvta.to.shared.u64 t, %1; cvt.u32.u64 %0, t; }" : "=r"(a) : "l"(p));
    return a;
}
__device__ __forceinline__ void ldsm4(u32& r0, u32& r1, u32& r2, u32& r3, u32 addr)
{
    asm volatile("ldmatrix.sync.aligned.m8n8.x4.shared.b16 {%0,%1,%2,%3}, [%4];"
        : "=r"(r0), "=r"(r1), "=r"(r2), "=r"(r3) : "r"(addr));
}
__device__ __forceinline__ void mma16816(float (&c)[4], const u32 (&a)[4], u32 b0, u32 b1)
{
    asm volatile("mma.sync.aligned.m16n8k16.row.col.f32.f16.f16.f32 "
        "{%0,%1,%2,%3},{%4,%5,%6,%7},{%8,%9},{%0,%1,%2,%3};"
        : "+f"(c[0]), "+f"(c[1]), "+f"(c[2]), "+f"(c[3])
        : "r"(a[0]), "r"(a[1]), "r"(a[2]), "r"(a[3]), "r"(b0), "r"(b1));
}
__device__ __forceinline__ u32 pack_h(float a, float b)
{
    __half ha = __float2half_rn(a), hb = __float2half_rn(b);
    return (u32)__half_as_ushort(ha) | ((u32)__half_as_ushort(hb) << 16);
}
__device__ __forceinline__ float softplus_f(float x)
{
    return fmaxf(x, 0.f) + log1pf(expf(-fabsf(x)));
}
__device__ __forceinline__ const char* stage_img(int s)
{
    if (s < 7) return g_Bcat[s];
    int r = s - 7;
    return (r & 1) ? g_B2[r >> 1] : g_B1[r >> 1];
}
__device__ __forceinline__ void prefetch_img(const char* src, u32 dst, int tid)
{
    u64 g = __cvta_generic_to_global(src);
    #pragma unroll
    for (int i = 0; i < 9; i++) {
        int idx = i*NTHR + tid;
        if (idx < IMG_V16)
            asm volatile("cp.async.cg.shared.global [%0], [%1], 16;"
                :: "r"(dst + idx*16), "l"(g + (u64)idx*16));
    }
}
#define CP_COMMIT()  asm volatile("cp.async.commit_group;" ::: "memory")
#define CP_WAIT1()   asm volatile("cp.async.wait_group 1;" ::: "memory")

/* zero ~35 float4 slices of this CTA's output region per stage (streamed) */
__device__ __forceinline__ void zero_chunk(float* zbase, int s, int tid)
{
    int j0 = s*35, j1 = j0+35; if (j1 > 512) j1 = 512;
    #pragma unroll 1
    for (int j = j0; j < j1; j++) {
        float* p = zbase + (size_t)(j*256 + tid)*4;
        asm volatile("st.global.cs.v4.f32 [%0], {%1,%1,%1,%1};"
            :: "l"(p), "f"(0.f) : "memory");
    }
}

/* ---------------- prep: fp16 weights into [n][k] images ---------------- */
__global__ void prep_kernel(
    const float* __restrict__ Win,  const float* __restrict__ bin,
    const float* __restrict__ Wini, const float* __restrict__ bini,
    const float* __restrict__ Wd,   const float* __restrict__ bd,
    const float* __restrict__ W1,   const float* __restrict__ W2,
    const float* __restrict__ Wout, const float* __restrict__ bout,
    const float* __restrict__ Wmu,  const float* __restrict__ bmu)
{
    int id = blockIdx.x * blockDim.x + threadIdx.x;
    int stride = gridDim.x * blockDim.x;

    for (int x = id; x < 128*832; x += stride) {
        int n = x / 832, k = x % 832;
        float v;
        if (k < 384)       v = Win [n*384 + k];
        else if (k < 768)  v = Wini[n*384 + (k-384)];
        else               v = Wd  [n*64  + (k-768)];
        int c = k >> 7, kc = k & 127;
        *(__half*)(g_Bcat[c] + (n*136 + kc)*2) = __float2half_rn(v);
    }
    for (int x = id; x < NB*128*128; x += stride) {
        int blk = x >> 14; int r = x & 16383; int n = r >> 7; int k = r & 127;
        int off = (n*136 + k)*2;
        *(__half*)(g_B1[blk] + off) = __float2half_rn(W1[x]);
        *(__half*)(g_B2[blk] + off) = __float2half_rn(W2[x]);
    }
    for (int x = id; x < CH*8; x += stride) {
        int k = x / 8, j = x % 8;
        float v = 0.f;
        if (j < 5)      v = Wout[j*CH + k];
        else if (j < 7) v = Wmu [(j-5)*CH + k];
        g_WTout[x] = v;
    }
    if (id < CH) g_bias0[id] = bin[id] + bini[id] + bd[id];
    if (id < 8)  g_bout[id] = (id < 5) ? bout[id] : ((id < 7) ? bmu[id-5] : 0.f);
}

/* ---------------- single-pass fp16 GEMM core ---------------- */
__device__ __forceinline__ void gemm1(u32 aimg, u32 bimg,
                                      int nks, u32 a_t, u32 b_t, float (&acc)[16][4])
{
    #pragma unroll 1
    for (int ks = 0; ks < nks; ks++) {
        u32 ah[4];
        ldsm4(ah[0], ah[1], ah[2], ah[3], aimg + a_t + ks*32);
        u32 bc[4], bn[4];
        ldsm4(bc[0], bc[1], bc[2], bc[3], bimg + b_t + ks*32);
        #pragma unroll
        for (int np = 0; np < 8; np++) {
            if (np < 7)
                ldsm4(bn[0], bn[1], bn[2], bn[3], bimg + b_t + (np+1)*4352 + ks*32);
            mma16816(acc[2*np],   ah, bc[0], bc[1]);
            mma16816(acc[2*np+1], ah, bc[2], bc[3]);
            bc[0] = bn[0]; bc[1] = bn[1]; bc[2] = bn[2]; bc[3] = bn[3];
        }
    }
}

/* ---------------- fused MLP kernel ---------------- */
__global__ __launch_bounds__(NTHR, 1) void fused_mlp_kernel(
    const float* __restrict__ s, const float* __restrict__ si, const float* __restrict__ ds,
    const float* __restrict__ b1g, const float* __restrict__ b2g,
    float* __restrict__ out)
{
    extern __shared__ char smem[];
    float* H = (float*)(smem + HOF);
    const int tid  = threadIdx.x;
    const int w    = tid >> 5;
    const int lane = tid & 31;
    const int seg  = lane >> 3;
    const int rr   = lane & 7;
    const int tok0 = blockIdx.x * TILE_M;
    float* zbase = out + (size_t)tok0 * NTOK;   /* this CTA's 128 output rows */

    const u32 a_t = (u32)((w*16 + (seg & 1)*8 + rr)*AST + (seg >> 1)*16);
    const u32 b_t = (u32)(((seg >> 1)*8 + rr)*AST + (seg & 1)*16);
    const int r0   = w*16 + (lane >> 2);
    const int r1   = r0 + 8;
    const int colb = (lane & 3)*2;

    u32 sb   = smem_u32(smem);
    u32 aimg = sb + AIMG;
    u32 bb[2] = { sb + BB0, sb + BB1 };

    float acc[16][4];
    #pragma unroll
    for (int i = 0; i < 16; i++)
        #pragma unroll
        for (int j = 0; j < 4; j++) acc[i][j] = 0.f;

    /* initial B prefetch */
    prefetch_img(stage_img(0), bb[0], tid);
    CP_COMMIT();
    int st = 0;

    /* ---- phase 1: accumulate 7 K-chunks of the concat input GEMM ---- */
    #pragma unroll 1
    for (int c = 0; c < 7; c++) {
        if (st+1 < NSTAGES) prefetch_img(stage_img(st+1), bb[(st+1)&1], tid);
        CP_COMMIT();

        const float* src; int Krow, Kc;
        if (c < 3)      { src = s  + (size_t)tok0*C_IN   + c*128;     Krow = C_IN;   Kc = 128; }
        else if (c < 6) { src = si + (size_t)tok0*C_IN   + (c-3)*128; Krow = C_IN;   Kc = 128; }
        else            { src = ds + (size_t)tok0*C_DSSP;             Krow = C_DSSP; Kc = 64;  }
        int hp = Kc >> 1;
        int total = 128*hp;
        int pl = (Kc == 128) ? 6 : 5, pm = hp - 1;
        #pragma unroll 1
        for (int idx = tid; idx < total; idx += NTHR) {
            int m = idx >> pl, kp = idx & pm;
            float2 v = *(const float2*)(src + (size_t)m*Krow + kp*2);
            *(u32*)(smem + AIMG + m*AST + kp*4) =
                pack_h(fmaxf(v.x, 0.f), fmaxf(v.y, 0.f));
        }
        CP_WAIT1();
        __syncthreads();
        gemm1(aimg, bb[st&1], (Kc == 128) ? 8 : 4, a_t, b_t, acc);
        zero_chunk(zbase, st, tid);
        __syncthreads();
        st++;
    }

    /* phase-1 epilogue: H = D + bias0; A = fp16(relu(H)) */
    #pragma unroll
    for (int nt = 0; nt < 16; nt++) {
        int col = nt*8 + colb;
        float bc0 = g_bias0[col], bc1 = g_bias0[col+1];
        float v00 = acc[nt][0] + bc0, v01 = acc[nt][1] + bc1;
        float v10 = acc[nt][2] + bc0, v11 = acc[nt][3] + bc1;
        H[r0*HSTW + col] = v00; H[r0*HSTW + col+1] = v01;
        H[r1*HSTW + col] = v10; H[r1*HSTW + col+1] = v11;
        *(u32*)(smem + AIMG + r0*AST + col*2) = pack_h(fmaxf(v00, 0.f), fmaxf(v01, 0.f));
        *(u32*)(smem + AIMG + r1*AST + col*2) = pack_h(fmaxf(v10, 0.f), fmaxf(v11, 0.f));
    }

    /* ---- resnet blocks ---- */
    #pragma unroll 1
    for (int blk = 0; blk < NB; blk++) {
        /* GEMM1: t = relu(relu(h) @ W1^T + b1) */
        if (st+1 < NSTAGES) prefetch_img(stage_img(st+1), bb[(st+1)&1], tid);
        CP_COMMIT();
        CP_WAIT1();
        __syncthreads();       /* epilogue A-writes + B image visible */
        #pragma unroll
        for (int i = 0; i < 16; i++)
            #pragma unroll
            for (int j = 0; j < 4; j++) acc[i][j] = 0.f;
        gemm1(aimg, bb[st&1], 8, a_t, b_t, acc);
        zero_chunk(zbase, st, tid);
        __syncthreads();
        st++;

        const float* bb1 = b1g + blk*CH;
        #pragma unroll
        for (int nt = 0; nt < 16; nt++) {
            int col = nt*8 + colb;
            float bc0 = bb1[col], bc1 = bb1[col+1];
            float v00 = fmaxf(acc[nt][0] + bc0, 0.f), v01 = fmaxf(acc[nt][1] + bc1, 0.f);
            float v10 = fmaxf(acc[nt][2] + bc0, 0.f), v11 = fmaxf(acc[nt][3] + bc1, 0.f);
            *(u32*)(smem + AIMG + r0*AST + col*2) = pack_h(v00, v01);
            *(u32*)(smem + AIMG + r1*AST + col*2) = pack_h(v10, v11);
        }

        /* GEMM2: h += t @ W2^T + b2 */
        if (st+1 < NSTAGES) prefetch_img(stage_img(st+1), bb[(st+1)&1], tid);
        CP_COMMIT();
        CP_WAIT1();
        __syncthreads();
        #pragma unroll
        for (int i = 0; i < 16; i++)
            #pragma unroll
            for (int j = 0; j < 4; j++) acc[i][j] = 0.f;
        gemm1(aimg, bb[st&1], 8, a_t, b_t, acc);
        zero_chunk(zbase, st, tid);
        __syncthreads();
        st++;

        const float* bb2 = b2g + blk*CH;
        bool last = (blk == NB-1);
        #pragma unroll
        for (int nt = 0; nt < 16; nt++) {
            int col = nt*8 + colb;
            float bc0 = bb2[col], bc1 = bb2[col+1];
            float v00 = H[r0*HSTW + col]   + acc[nt][0] + bc0;
            float v01 = H[r0*HSTW + col+1] + acc[nt][1] + bc1;
            float v10 = H[r1*HSTW + col]   + acc[nt][2] + bc0;
            float v11 = H[r1*HSTW + col+1] + acc[nt][3] + bc1;
            float w00 = fmaxf(v00, 0.f), w01 = fmaxf(v01, 0.f);
            float w10 = fmaxf(v10, 0.f), w11 = fmaxf(v11, 0.f);
            if (last) {
                H[r0*HSTW + col] = w00; H[r0*HSTW + col+1] = w01;
                H[r1*HSTW + col] = w10; H[r1*HSTW + col+1] = w11;
            } else {
                H[r0*HSTW + col] = v00; H[r0*HSTW + col+1] = v01;
                H[r1*HSTW + col] = v10; H[r1*HSTW + col+1] = v11;
                *(u32*)(smem + AIMG + r0*AST + col*2) = pack_h(w00, w01);
                *(u32*)(smem + AIMG + r1*AST + col*2) = pack_h(w10, w11);
            }
        }
    }
    __syncthreads();

    /* ---- head: 7 outputs per token (H holds relu(h)) ---- */
    if (tid < TILE_M) {
        int m = tid;
        float o[7];
        #pragma unroll
        for (int j = 0; j < 7; j++) o[j] = g_bout[j];
        const float* rrow = H + m*HSTW;
        #pragma unroll 4
        for (int k = 0; k < CH; k++) {
            float r = rrow[k];
            const float* wp = g_WTout + k*8;
            #pragma unroll
            for (int j = 0; j < 7; j++) o[j] = fmaf(r, wp[j], o[j]);
        }
        float d0 = softplus_f(o[0]) * softplus_f(o[5]) + softplus_f(o[6]);
        int g = tok0 + m;
        g_scratch[g*5 + 0] = d0;
        g_scratch[g*5 + 1] = o[1];
        g_scratch[g*5 + 2] = o[2];
        g_scratch[g*5 + 3] = o[3];
        g_scratch[g*5 + 4] = o[4];
    }
}

/* ---------------- diagonal writer (zeros already laid down by fused kernel) ---------------- */
__global__ void diag_kernel(float* __restrict__ out, const float* __restrict__ smp)
{
    const float sm = *smp;
    int row = blockIdx.x * blockDim.x + threadIdx.x;   /* 0..16383 */
    int i   = row & (NTOK - 1);
    size_t base = (size_t)row * NTOK;

    float d0 = sm * g_scratch[row*5 + 0];
    out[base + i] = d0;
    if (i >= 1) out[base + i - 1] = sm * (g_scratch[row*5 + 1] + g_scratch[(row-1)*5 + 3]);
    if (i >= 2) out[base + i - 2] = sm * (g_scratch[row*5 + 2] + g_scratch[(row-2)*5 + 4]);
}

/* ---------------- launch ---------------- */
extern "C" void kernel_launch(void* const* d_in, const int* in_sizes, int n_in,
                              void* d_out, int out_size)
{
    (void)in_sizes; (void)n_in; (void)out_size;
    const float* s    = (const float*)d_in[0];
    const float* si   = (const float*)d_in[1];
    const float* ds   = (const float*)d_in[2];
    const float* Win  = (const float*)d_in[3];
    const float* bin  = (const float*)d_in[4];
    const float* Wini = (const float*)d_in[5];
    const float* bini = (const float*)d_in[6];
    const float* Wd   = (const float*)d_in[7];
    const float* bd   = (const float*)d_in[8];
    const float* W1   = (const float*)d_in[9];
    const float* b1   = (const float*)d_in[10];
    const float* W2   = (const float*)d_in[11];
    const float* b2   = (const float*)d_in[12];
    const float* Wout = (const float*)d_in[13];
    const float* bout = (const float*)d_in[14];
    const float* Wmu  = (const float*)d_in[15];
    const float* bmu  = (const float*)d_in[16];
    const float* smod = (const float*)d_in[17];
    float* out = (float*)d_out;

    cudaFuncSetAttribute(fused_mlp_kernel,
                         cudaFuncAttributeMaxDynamicSharedMemorySize, SMEM_TOTAL);

    prep_kernel<<<148, 256>>>(Win, bin, Wini, bini, Wd, bd, W1, W2, Wout, bout, Wmu, bmu);
    fused_mlp_kernel<<<TOKENS/TILE_M, NTHR, SMEM_TOTAL>>>(s, si, ds, b1, b2, out);
    diag_kernel<<<TOKENS/128, 128>>>(out, smod);
}

// round 11
// speedup vs baseline: 2.9592x; 1.4496x over previous
#include <cuda_runtime.h>
#include <cuda_fp16.h>
#include <math.h>

typedef unsigned int u32;
typedef unsigned long long u64;

#define BSZ     4
#define NTOK    4096
#define C_IN    384
#define C_DSSP  64
#define CH      128
#define NB      4
#define TOKENS  (BSZ*NTOK)   /* 16384 */
#define TILE_M  64
#define NTHR    256
#define AST     272          /* A/B smem row stride in BYTES (136 fp16) */
#define NSTAGES 15           /* 7 phase-1 + 8 resnet GEMM stages */

/* smem layout (bytes) */
#define AIMG  0
#define BB0   17408
#define BB1   52224
#define SMEM_TOTAL 87040
#define HFSTR 133            /* fp32 head-buffer row stride (floats), coprime w/ 32 */

#define IMG_BYTES 34816      /* one B image: 128 rows x 136 fp16 */
#define IMG_V16   (IMG_BYTES/16)   /* 2176 */

/* ---------------- device scratch (no allocations allowed) ---------------- */
__device__ __align__(16) char g_Bcat[7][IMG_BYTES];
__device__ __align__(16) char g_B1[NB][IMG_BYTES];
__device__ __align__(16) char g_B2[NB][IMG_BYTES];
__device__ __align__(16) float g_WTout[CH*8];
__device__ float g_bias0[CH];
__device__ float g_bout[8];
__device__ float g_scratch[TOKENS*5];

/* ---------------- helpers ---------------- */
__device__ __forceinline__ u32 smem_u32(const void* p) {
    u32 a;
    asm("{ .reg .u64 t; cvta.to.shared.u64 t, %1; cvt.u32.u64 %0, t; }" : "=r"(a) : "l"(p));
    return a;
}
__device__ __forceinline__ void ldsm4(u32& r0, u32& r1, u32& r2, u32& r3, u32 addr)
{
    asm volatile("ldmatrix.sync.aligned.m8n8.x4.shared.b16 {%0,%1,%2,%3}, [%4];"
        : "=r"(r0), "=r"(r1), "=r"(r2), "=r"(r3) : "r"(addr));
}
__device__ __forceinline__ void mma16816(float (&c)[4], const u32 (&a)[4], u32 b0, u32 b1)
{
    asm volatile("mma.sync.aligned.m16n8k16.row.col.f32.f16.f16.f32 "
        "{%0,%1,%2,%3},{%4,%5,%6,%7},{%8,%9},{%0,%1,%2,%3};"
        : "+f"(c[0]), "+f"(c[1]), "+f"(c[2]), "+f"(c[3])
        : "r"(a[0]), "r"(a[1]), "r"(a[2]), "r"(a[3]), "r"(b0), "r"(b1));
}
__device__ __forceinline__ u32 pack_h(float a, float b)
{
    __half ha = __float2half_rn(a), hb = __float2half_rn(b);
    return (u32)__half_as_ushort(ha) | ((u32)__half_as_ushort(hb) << 16);
}
__device__ __forceinline__ float softplus_f(float x)
{
    return fmaxf(x, 0.f) + log1pf(expf(-fabsf(x)));
}
__device__ __forceinline__ const char* stage_img(int s)
{
    if (s < 7) return g_Bcat[s];
    int r = s - 7;
    return (r & 1) ? g_B2[r >> 1] : g_B1[r >> 1];
}
__device__ __forceinline__ void prefetch_img(const char* src, u32 dst, int tid)
{
    u64 g = __cvta_generic_to_global(src);
    #pragma unroll
    for (int i = 0; i < 9; i++) {
        int idx = i*NTHR + tid;
        if (idx < IMG_V16)
            asm volatile("cp.async.cg.shared.global [%0], [%1], 16;"
                :: "r"(dst + idx*16), "l"(g + (u64)idx*16));
    }
}
#define CP_COMMIT()  asm volatile("cp.async.commit_group;" ::: "memory")
#define CP_WAIT1()   asm volatile("cp.async.wait_group 1;" ::: "memory")

/* zero ~18 float4 slices of this CTA's 64-row output region per stage */
__device__ __forceinline__ void zero_chunk(float* zbase, int s, int tid)
{
    int j0 = s*18, j1 = j0+18; if (j1 > 256) j1 = 256;
    #pragma unroll 1
    for (int j = j0; j < j1; j++) {
        float* p = zbase + (size_t)(j*256 + tid)*4;
        asm volatile("st.global.cs.v4.f32 [%0], {%1,%1,%1,%1};"
            :: "l"(p), "f"(0.f) : "memory");
    }
}

/* ---------------- prep: fp16 weights into [n][k] images ---------------- */
__global__ void prep_kernel(
    const float* __restrict__ Win,  const float* __restrict__ bin,
    const float* __restrict__ Wini, const float* __restrict__ bini,
    const float* __restrict__ Wd,   const float* __restrict__ bd,
    const float* __restrict__ W1,   const float* __restrict__ W2,
    const float* __restrict__ Wout, const float* __restrict__ bout,
    const float* __restrict__ Wmu,  const float* __restrict__ bmu)
{
    int id = blockIdx.x * blockDim.x + threadIdx.x;
    int stride = gridDim.x * blockDim.x;

    for (int x = id; x < 128*832; x += stride) {
        int n = x / 832, k = x % 832;
        float v;
        if (k < 384)       v = Win [n*384 + k];
        else if (k < 768)  v = Wini[n*384 + (k-384)];
        else               v = Wd  [n*64  + (k-768)];
        int c = k >> 7, kc = k & 127;
        *(__half*)(g_Bcat[c] + (n*136 + kc)*2) = __float2half_rn(v);
    }
    for (int x = id; x < NB*128*128; x += stride) {
        int blk = x >> 14; int r = x & 16383; int n = r >> 7; int k = r & 127;
        int off = (n*136 + k)*2;
        *(__half*)(g_B1[blk] + off) = __float2half_rn(W1[x]);
        *(__half*)(g_B2[blk] + off) = __float2half_rn(W2[x]);
    }
    for (int x = id; x < CH*8; x += stride) {
        int k = x / 8, j = x % 8;
        float v = 0.f;
        if (j < 5)      v = Wout[j*CH + k];
        else if (j < 7) v = Wmu [(j-5)*CH + k];
        g_WTout[x] = v;
    }
    if (id < CH) g_bias0[id] = bin[id] + bini[id] + bd[id];
    if (id < 8)  g_bout[id] = (id < 5) ? bout[id] : ((id < 7) ? bmu[id-5] : 0.f);
}

/* ---------------- single-pass fp16 GEMM core: warp covers 16 rows x 64 cols ---- */
__device__ __forceinline__ void gemm1(u32 aimg, u32 bimg,
                                      int nks, u32 a_t, u32 b_t, float (&acc)[8][4])
{
    #pragma unroll 1
    for (int ks = 0; ks < nks; ks++) {
        u32 ah[4];
        ldsm4(ah[0], ah[1], ah[2], ah[3], aimg + a_t + ks*32);
        u32 bc[4], bn[4];
        ldsm4(bc[0], bc[1], bc[2], bc[3], bimg + b_t + ks*32);
        #pragma unroll
        for (int np = 0; np < 4; np++) {
            if (np < 3)
                ldsm4(bn[0], bn[1], bn[2], bn[3], bimg + b_t + (np+1)*4352 + ks*32);
            mma16816(acc[2*np],   ah, bc[0], bc[1]);
            mma16816(acc[2*np+1], ah, bc[2], bc[3]);
            bc[0] = bn[0]; bc[1] = bn[1]; bc[2] = bn[2]; bc[3] = bn[3];
        }
    }
}

/* ---------------- fused MLP kernel: 64 tokens/CTA, 2 CTAs/SM ---------------- */
__global__ __launch_bounds__(NTHR, 2) void fused_mlp_kernel(
    const float* __restrict__ s, const float* __restrict__ si, const float* __restrict__ ds,
    const float* __restrict__ b1g, const float* __restrict__ b2g,
    float* __restrict__ out)
{
    extern __shared__ char smem[];
    const int tid  = threadIdx.x;
    const int w    = tid >> 5;
    const int wr   = w >> 1;            /* row group 0..3  (16 rows) */
    const int wc   = w & 1;             /* col group 0..1  (64 cols) */
    const int lane = tid & 31;
    const int seg  = lane >> 3;
    const int rr   = lane & 7;
    const int tok0 = blockIdx.x * TILE_M;
    float* zbase = out + (size_t)tok0 * NTOK;   /* this CTA's 64 output rows */

    const u32 a_t = (u32)((wr*16 + (seg & 1)*8 + rr)*AST + (seg >> 1)*16);
    const u32 b_t = (u32)((wc*64 + (seg >> 1)*8 + rr)*AST + (seg & 1)*16);
    const int r0   = wr*16 + (lane >> 2);
    const int r1   = r0 + 8;
    const int colb = wc*64 + (lane & 3)*2;

    u32 sb   = smem_u32(smem);
    u32 aimg = sb + AIMG;
    u32 bb[2] = { sb + BB0, sb + BB1 };

    float acc[8][4], hreg[8][4];
    #pragma unroll
    for (int i = 0; i < 8; i++)
        #pragma unroll
        for (int j = 0; j < 4; j++) acc[i][j] = 0.f;

    prefetch_img(stage_img(0), bb[0], tid);
    CP_COMMIT();
    int st = 0;

    /* ---- phase 1: accumulate 7 K-chunks of the concat input GEMM ---- */
    #pragma unroll 1
    for (int c = 0; c < 7; c++) {
        if (st+1 < NSTAGES) prefetch_img(stage_img(st+1), bb[(st+1)&1], tid);
        CP_COMMIT();

        const float* src; int Krow, Kc;
        if (c < 3)      { src = s  + (size_t)tok0*C_IN   + c*128;     Krow = C_IN;   Kc = 128; }
        else if (c < 6) { src = si + (size_t)tok0*C_IN   + (c-3)*128; Krow = C_IN;   Kc = 128; }
        else            { src = ds + (size_t)tok0*C_DSSP;             Krow = C_DSSP; Kc = 64;  }
        int hp = Kc >> 1;
        int total = TILE_M*hp;
        int pl = (Kc == 128) ? 6 : 5, pm = hp - 1;
        #pragma unroll 1
        for (int idx = tid; idx < total; idx += NTHR) {
            int m = idx >> pl, kp = idx & pm;
            float2 v = *(const float2*)(src + (size_t)m*Krow + kp*2);
            *(u32*)(smem + AIMG + m*AST + kp*4) =
                pack_h(fmaxf(v.x, 0.f), fmaxf(v.y, 0.f));
        }
        CP_WAIT1();
        __syncthreads();
        gemm1(aimg, bb[st&1], (Kc == 128) ? 8 : 4, a_t, b_t, acc);
        zero_chunk(zbase, st, tid);
        __syncthreads();
        st++;
    }

    /* phase-1 epilogue: hreg = D + bias0; A = fp16(relu(hreg)) */
    #pragma unroll
    for (int nt = 0; nt < 8; nt++) {
        int col = colb + nt*8;
        float bc0 = g_bias0[col], bc1 = g_bias0[col+1];
        hreg[nt][0] = acc[nt][0] + bc0; hreg[nt][1] = acc[nt][1] + bc1;
        hreg[nt][2] = acc[nt][2] + bc0; hreg[nt][3] = acc[nt][3] + bc1;
        *(u32*)(smem + AIMG + r0*AST + col*2) =
            pack_h(fmaxf(hreg[nt][0], 0.f), fmaxf(hreg[nt][1], 0.f));
        *(u32*)(smem + AIMG + r1*AST + col*2) =
            pack_h(fmaxf(hreg[nt][2], 0.f), fmaxf(hreg[nt][3], 0.f));
    }

    /* ---- resnet blocks ---- */
    #pragma unroll 1
    for (int blk = 0; blk < NB; blk++) {
        /* GEMM1: t = relu(relu(h) @ W1^T + b1) */
        if (st+1 < NSTAGES) prefetch_img(stage_img(st+1), bb[(st+1)&1], tid);
        CP_COMMIT();
        CP_WAIT1();
        __syncthreads();
        #pragma unroll
        for (int i = 0; i < 8; i++)
            #pragma unroll
            for (int j = 0; j < 4; j++) acc[i][j] = 0.f;
        gemm1(aimg, bb[st&1], 8, a_t, b_t, acc);
        zero_chunk(zbase, st, tid);
        __syncthreads();
        st++;

        const float* bb1 = b1g + blk*CH;
        #pragma unroll
        for (int nt = 0; nt < 8; nt++) {
            int col = colb + nt*8;
            float bc0 = bb1[col], bc1 = bb1[col+1];
            *(u32*)(smem + AIMG + r0*AST + col*2) =
                pack_h(fmaxf(acc[nt][0] + bc0, 0.f), fmaxf(acc[nt][1] + bc1, 0.f));
            *(u32*)(smem + AIMG + r1*AST + col*2) =
                pack_h(fmaxf(acc[nt][2] + bc0, 0.f), fmaxf(acc[nt][3] + bc1, 0.f));
        }

        /* GEMM2: h += t @ W2^T + b2 */
        if (st+1 < NSTAGES) prefetch_img(stage_img(st+1), bb[(st+1)&1], tid);
        CP_COMMIT();
        CP_WAIT1();
        __syncthreads();
        #pragma unroll
        for (int i = 0; i < 8; i++)
            #pragma unroll
            for (int j = 0; j < 4; j++) acc[i][j] = 0.f;
        gemm1(aimg, bb[st&1], 8, a_t, b_t, acc);
        zero_chunk(zbase, st, tid);
        __syncthreads();
        st++;

        const float* bb2 = b2g + blk*CH;
        bool last = (blk == NB-1);
        float* HF = (float*)(smem + BB0);   /* dead after last GEMM (post-sync) */
        #pragma unroll
        for (int nt = 0; nt < 8; nt++) {
            int col = colb + nt*8;
            float bc0 = bb2[col], bc1 = bb2[col+1];
            hreg[nt][0] += acc[nt][0] + bc0; hreg[nt][1] += acc[nt][1] + bc1;
            hreg[nt][2] += acc[nt][2] + bc0; hreg[nt][3] += acc[nt][3] + bc1;
            float w00 = fmaxf(hreg[nt][0], 0.f), w01 = fmaxf(hreg[nt][1], 0.f);
            float w10 = fmaxf(hreg[nt][2], 0.f), w11 = fmaxf(hreg[nt][3], 0.f);
            if (last) {
                HF[r0*HFSTR + col] = w00; HF[r0*HFSTR + col+1] = w01;
                HF[r1*HFSTR + col] = w10; HF[r1*HFSTR + col+1] = w11;
            } else {
                *(u32*)(smem + AIMG + r0*AST + col*2) = pack_h(w00, w01);
                *(u32*)(smem + AIMG + r1*AST + col*2) = pack_h(w10, w11);
            }
        }
    }
    __syncthreads();

    /* ---- head: 7 outputs per token (HF holds fp32 relu(h)) ---- */
    if (tid < TILE_M) {
        int m = tid;
        float o[7];
        #pragma unroll
        for (int j = 0; j < 7; j++) o[j] = g_bout[j];
        const float* rrow = (const float*)(smem + BB0) + m*HFSTR;
        #pragma unroll 4
        for (int k = 0; k < CH; k++) {
            float r = rrow[k];
            const float* wp = g_WTout + k*8;
            #pragma unroll
            for (int j = 0; j < 7; j++) o[j] = fmaf(r, wp[j], o[j]);
        }
        float d0 = softplus_f(o[0]) * softplus_f(o[5]) + softplus_f(o[6]);
        int g = tok0 + m;
        g_scratch[g*5 + 0] = d0;
        g_scratch[g*5 + 1] = o[1];
        g_scratch[g*5 + 2] = o[2];
        g_scratch[g*5 + 3] = o[3];
        g_scratch[g*5 + 4] = o[4];
    }
}

/* ---------------- diagonal writer (zeros already laid down by fused kernel) ---------------- */
__global__ void diag_kernel(float* __restrict__ out, const float* __restrict__ smp)
{
    const float sm = *smp;
    int row = blockIdx.x * blockDim.x + threadIdx.x;   /* 0..16383 */
    int i   = row & (NTOK - 1);
    size_t base = (size_t)row * NTOK;

    float d0 = sm * g_scratch[row*5 + 0];
    out[base + i] = d0;
    if (i >= 1) out[base + i - 1] = sm * (g_scratch[row*5 + 1] + g_scratch[(row-1)*5 + 3]);
    if (i >= 2) out[base + i - 2] = sm * (g_scratch[row*5 + 2] + g_scratch[(row-2)*5 + 4]);
}

/* ---------------- launch ---------------- */
extern "C" void kernel_launch(void* const* d_in, const int* in_sizes, int n_in,
                              void* d_out, int out_size)
{
    (void)in_sizes; (void)n_in; (void)out_size;
    const float* s    = (const float*)d_in[0];
    const float* si   = (const float*)d_in[1];
    const float* ds   = (const float*)d_in[2];
    const float* Win  = (const float*)d_in[3];
    const float* bin  = (const float*)d_in[4];
    const float* Wini = (const float*)d_in[5];
    const float* bini = (const float*)d_in[6];
    const float* Wd   = (const float*)d_in[7];
    const float* bd   = (const float*)d_in[8];
    const float* W1   = (const float*)d_in[9];
    const float* b1   = (const float*)d_in[10];
    const float* W2   = (const float*)d_in[11];
    const float* b2   = (const float*)d_in[12];
    const float* Wout = (const float*)d_in[13];
    const float* bout = (const float*)d_in[14];
    const float* Wmu  = (const float*)d_in[15];
    const float* bmu  = (const float*)d_in[16];
    const float* smod = (const float*)d_in[17];
    float* out = (float*)d_out;

    cudaFuncSetAttribute(fused_mlp_kernel,
                         cudaFuncAttributeMaxDynamicSharedMemorySize, SMEM_TOTAL);

    prep_kernel<<<148, 256>>>(Win, bin, Wini, bini, Wd, bd, W1, W2, Wout, bout, Wmu, bmu);
    fused_mlp_kernel<<<TOKENS/TILE_M, NTHR, SMEM_TOTAL>>>(s, si, ds, b1, b2, out);
    diag_kernel<<<TOKENS/128, 128>>>(out, smod);
}

// round 12
// speedup vs baseline: 3.5437x; 1.1975x over previous
#include <cuda_runtime.h>
#include <cuda_fp16.h>
#include <math.h>

typedef unsigned int u32;
typedef unsigned long long u64;

#define BSZ     4
#define NTOK    4096
#define C_IN    384
#define C_DSSP  64
#define CH      128
#define NB      4
#define TOKENS  (BSZ*NTOK)   /* 16384 */
#define TILE_M  64
#define NTHR    512
#define AST     272          /* A/B smem row stride in BYTES (136 fp16) */
#define NSTAGES 15           /* 7 phase-1 + 8 resnet GEMM stages */

/* smem layout (bytes) */
#define AIMG  0
#define BB0   17408
#define BB1   52224
#define SMEM_TOTAL 87040
#define HFSTR 133            /* fp32 head-buffer row stride (floats) */

#define IMG_BYTES 34816      /* one B image: 128 rows x 136 fp16 */
#define IMG_V16   (IMG_BYTES/16)   /* 2176 */

/* ---------------- device scratch (no allocations allowed) ---------------- */
__device__ __align__(16) char g_Bcat[7][IMG_BYTES];
__device__ __align__(16) char g_B1[NB][IMG_BYTES];
__device__ __align__(16) char g_B2[NB][IMG_BYTES];
__device__ __align__(16) float g_WTout[CH*8];
__device__ float g_bias0[CH];
__device__ float g_bout[8];
__device__ float g_scratch[TOKENS*5];

/* ---------------- helpers ---------------- */
__device__ __forceinline__ u32 smem_u32(const void* p) {
    u32 a;
    asm("{ .reg .u64 t; cvta.to.shared.u64 t, %1; cvt.u32.u64 %0, t; }" : "=r"(a) : "l"(p));
    return a;
}
__device__ __forceinline__ void ldsm4(u32& r0, u32& r1, u32& r2, u32& r3, u32 addr)
{
    asm volatile("ldmatrix.sync.aligned.m8n8.x4.shared.b16 {%0,%1,%2,%3}, [%4];"
        : "=r"(r0), "=r"(r1), "=r"(r2), "=r"(r3) : "r"(addr));
}
__device__ __forceinline__ void mma16816(float (&c)[4], const u32 (&a)[4], u32 b0, u32 b1)
{
    asm volatile("mma.sync.aligned.m16n8k16.row.col.f32.f16.f16.f32 "
        "{%0,%1,%2,%3},{%4,%5,%6,%7},{%8,%9},{%0,%1,%2,%3};"
        : "+f"(c[0]), "+f"(c[1]), "+f"(c[2]), "+f"(c[3])
        : "r"(a[0]), "r"(a[1]), "r"(a[2]), "r"(a[3]), "r"(b0), "r"(b1));
}
__device__ __forceinline__ u32 pack_h(float a, float b)
{
    __half ha = __float2half_rn(a), hb = __float2half_rn(b);
    return (u32)__half_as_ushort(ha) | ((u32)__half_as_ushort(hb) << 16);
}
__device__ __forceinline__ float softplus_f(float x)
{
    return fmaxf(x, 0.f) + log1pf(expf(-fabsf(x)));
}
__device__ __forceinline__ const char* stage_img(int s)
{
    if (s < 7) return g_Bcat[s];
    int r = s - 7;
    return (r & 1) ? g_B2[r >> 1] : g_B1[r >> 1];
}
__device__ __forceinline__ void prefetch_img(const char* src, u32 dst, int tid)
{
    u64 g = __cvta_generic_to_global(src);
    #pragma unroll
    for (int i = 0; i < 5; i++) {
        int idx = i*NTHR + tid;
        if (idx < IMG_V16)
            asm volatile("cp.async.cg.shared.global [%0], [%1], 16;"
                :: "r"(dst + idx*16), "l"(g + (u64)idx*16));
    }
}
#define CP_COMMIT()  asm volatile("cp.async.commit_group;" ::: "memory")
#define CP_WAIT1()   asm volatile("cp.async.wait_group 1;" ::: "memory")

/* zero 9 float4 slices (per 512 threads) of this CTA's 64-row region per stage */
__device__ __forceinline__ void zero_chunk(float* zbase, int s, int tid)
{
    int j0 = s*9, j1 = j0+9; if (j1 > 128) j1 = 128;
    #pragma unroll 1
    for (int j = j0; j < j1; j++) {
        float* p = zbase + (size_t)(j*NTHR + tid)*4;
        asm volatile("st.global.cs.v4.f32 [%0], {%1,%1,%1,%1};"
            :: "l"(p), "f"(0.f) : "memory");
    }
}

/* ---------------- prep: fp16 weights into [n][k] images ---------------- */
__global__ void prep_kernel(
    const float* __restrict__ Win,  const float* __restrict__ bin,
    const float* __restrict__ Wini, const float* __restrict__ bini,
    const float* __restrict__ Wd,   const float* __restrict__ bd,
    const float* __restrict__ W1,   const float* __restrict__ W2,
    const float* __restrict__ Wout, const float* __restrict__ bout,
    const float* __restrict__ Wmu,  const float* __restrict__ bmu)
{
    int id = blockIdx.x * blockDim.x + threadIdx.x;
    int stride = gridDim.x * blockDim.x;

    for (int x = id; x < 128*832; x += stride) {
        int n = x / 832, k = x % 832;
        float v;
        if (k < 384)       v = Win [n*384 + k];
        else if (k < 768)  v = Wini[n*384 + (k-384)];
        else               v = Wd  [n*64  + (k-768)];
        int c = k >> 7, kc = k & 127;
        *(__half*)(g_Bcat[c] + (n*136 + kc)*2) = __float2half_rn(v);
    }
    for (int x = id; x < NB*128*128; x += stride) {
        int blk = x >> 14; int r = x & 16383; int n = r >> 7; int k = r & 127;
        int off = (n*136 + k)*2;
        *(__half*)(g_B1[blk] + off) = __float2half_rn(W1[x]);
        *(__half*)(g_B2[blk] + off) = __float2half_rn(W2[x]);
    }
    for (int x = id; x < CH*8; x += stride) {
        int k = x / 8, j = x % 8;
        float v = 0.f;
        if (j < 5)      v = Wout[j*CH + k];
        else if (j < 7) v = Wmu [(j-5)*CH + k];
        g_WTout[x] = v;
    }
    if (id < CH) g_bias0[id] = bin[id] + bini[id] + bd[id];
    if (id < 8)  g_bout[id] = (id < 5) ? bout[id] : ((id < 7) ? bmu[id-5] : 0.f);
}

/* ------- single-pass fp16 GEMM core: warp covers 16 rows x 32 cols ------- */
__device__ __forceinline__ void gemm1(u32 aimg, u32 bimg,
                                      int nks, u32 a_t, u32 b_t, float (&acc)[4][4])
{
    #pragma unroll 1
    for (int ks = 0; ks < nks; ks++) {
        u32 ah[4];
        ldsm4(ah[0], ah[1], ah[2], ah[3], aimg + a_t + ks*32);
        u32 bc[4], bn[4];
        ldsm4(bc[0], bc[1], bc[2], bc[3], bimg + b_t + ks*32);
        ldsm4(bn[0], bn[1], bn[2], bn[3], bimg + b_t + 4352 + ks*32);
        mma16816(acc[0], ah, bc[0], bc[1]);
        mma16816(acc[1], ah, bc[2], bc[3]);
        mma16816(acc[2], ah, bn[0], bn[1]);
        mma16816(acc[3], ah, bn[2], bn[3]);
    }
}

/* ---------------- fused MLP kernel: 64 tokens/CTA, 512 thr, 2 CTAs/SM ------ */
__global__ __launch_bounds__(NTHR, 2) void fused_mlp_kernel(
    const float* __restrict__ s, const float* __restrict__ si, const float* __restrict__ ds,
    const float* __restrict__ b1g, const float* __restrict__ b2g,
    float* __restrict__ out)
{
    extern __shared__ char smem[];
    const int tid  = threadIdx.x;
    const int w    = tid >> 5;
    const int wr   = w >> 2;            /* row group 0..3  (16 rows)  */
    const int wcc  = w & 3;             /* col group 0..3  (32 cols)  */
    const int lane = tid & 31;
    const int seg  = lane >> 3;
    const int rr   = lane & 7;
    const int tok0 = blockIdx.x * TILE_M;
    float* zbase = out + (size_t)tok0 * NTOK;   /* this CTA's 64 output rows */

    const u32 a_t = (u32)((wr*16 + (seg & 1)*8 + rr)*AST + (seg >> 1)*16);
    const u32 b_t = (u32)((wcc*32 + (seg >> 1)*8 + rr)*AST + (seg & 1)*16);
    const int r0   = wr*16 + (lane >> 2);
    const int r1   = r0 + 8;
    const int colb = wcc*32 + (lane & 3)*2;

    u32 sb   = smem_u32(smem);
    u32 aimg = sb + AIMG;
    u32 bb[2] = { sb + BB0, sb + BB1 };

    float acc[4][4], hreg[4][4];
    #pragma unroll
    for (int i = 0; i < 4; i++)
        #pragma unroll
        for (int j = 0; j < 4; j++) acc[i][j] = 0.f;

    prefetch_img(stage_img(0), bb[0], tid);
    CP_COMMIT();
    int st = 0;

    /* ---- phase 1: accumulate 7 K-chunks of the concat input GEMM ---- */
    #pragma unroll 1
    for (int c = 0; c < 7; c++) {
        if (st+1 < NSTAGES) prefetch_img(stage_img(st+1), bb[(st+1)&1], tid);
        CP_COMMIT();

        const float* src; int Krow, Kc;
        if (c < 3)      { src = s  + (size_t)tok0*C_IN   + c*128;     Krow = C_IN;   Kc = 128; }
        else if (c < 6) { src = si + (size_t)tok0*C_IN   + (c-3)*128; Krow = C_IN;   Kc = 128; }
        else            { src = ds + (size_t)tok0*C_DSSP;             Krow = C_DSSP; Kc = 64;  }
        int hp = Kc >> 1;
        int total = TILE_M*hp;
        int pl = (Kc == 128) ? 6 : 5, pm = hp - 1;
        #pragma unroll 1
        for (int idx = tid; idx < total; idx += NTHR) {
            int m = idx >> pl, kp = idx & pm;
            float2 v = *(const float2*)(src + (size_t)m*Krow + kp*2);
            *(u32*)(smem + AIMG + m*AST + kp*4) =
                pack_h(fmaxf(v.x, 0.f), fmaxf(v.y, 0.f));
        }
        CP_WAIT1();
        __syncthreads();
        gemm1(aimg, bb[st&1], (Kc == 128) ? 8 : 4, a_t, b_t, acc);
        zero_chunk(zbase, st, tid);
        __syncthreads();
        st++;
    }

    /* phase-1 epilogue: hreg = D + bias0; A = fp16(relu(hreg)) */
    #pragma unroll
    for (int nt = 0; nt < 4; nt++) {
        int col = colb + nt*8;
        float bc0 = g_bias0[col], bc1 = g_bias0[col+1];
        hreg[nt][0] = acc[nt][0] + bc0; hreg[nt][1] = acc[nt][1] + bc1;
        hreg[nt][2] = acc[nt][2] + bc0; hreg[nt][3] = acc[nt][3] + bc1;
        *(u32*)(smem + AIMG + r0*AST + col*2) =
            pack_h(fmaxf(hreg[nt][0], 0.f), fmaxf(hreg[nt][1], 0.f));
        *(u32*)(smem + AIMG + r1*AST + col*2) =
            pack_h(fmaxf(hreg[nt][2], 0.f), fmaxf(hreg[nt][3], 0.f));
    }

    /* ---- resnet blocks ---- */
    #pragma unroll 1
    for (int blk = 0; blk < NB; blk++) {
        /* GEMM1: t = relu(relu(h) @ W1^T + b1) */
        if (st+1 < NSTAGES) prefetch_img(stage_img(st+1), bb[(st+1)&1], tid);
        CP_COMMIT();
        CP_WAIT1();
        __syncthreads();
        #pragma unroll
        for (int i = 0; i < 4; i++)
            #pragma unroll
            for (int j = 0; j < 4; j++) acc[i][j] = 0.f;
        gemm1(aimg, bb[st&1], 8, a_t, b_t, acc);
        zero_chunk(zbase, st, tid);
        __syncthreads();
        st++;

        const float* bb1 = b1g + blk*CH;
        #pragma unroll
        for (int nt = 0; nt < 4; nt++) {
            int col = colb + nt*8;
            float bc0 = bb1[col], bc1 = bb1[col+1];
            *(u32*)(smem + AIMG + r0*AST + col*2) =
                pack_h(fmaxf(acc[nt][0] + bc0, 0.f), fmaxf(acc[nt][1] + bc1, 0.f));
            *(u32*)(smem + AIMG + r1*AST + col*2) =
                pack_h(fmaxf(acc[nt][2] + bc0, 0.f), fmaxf(acc[nt][3] + bc1, 0.f));
        }

        /* GEMM2: h += t @ W2^T + b2 */
        if (st+1 < NSTAGES) prefetch_img(stage_img(st+1), bb[(st+1)&1], tid);
        CP_COMMIT();
        CP_WAIT1();
        __syncthreads();
        #pragma unroll
        for (int i = 0; i < 4; i++)
            #pragma unroll
            for (int j = 0; j < 4; j++) acc[i][j] = 0.f;
        gemm1(aimg, bb[st&1], 8, a_t, b_t, acc);
        zero_chunk(zbase, st, tid);
        __syncthreads();
        st++;

        const float* bb2 = b2g + blk*CH;
        bool last = (blk == NB-1);
        float* HF = (float*)(smem + BB0);   /* dead after last GEMM (post-sync) */
        #pragma unroll
        for (int nt = 0; nt < 4; nt++) {
            int col = colb + nt*8;
            float bc0 = bb2[col], bc1 = bb2[col+1];
            hreg[nt][0] += acc[nt][0] + bc0; hreg[nt][1] += acc[nt][1] + bc1;
            hreg[nt][2] += acc[nt][2] + bc0; hreg[nt][3] += acc[nt][3] + bc1;
            float w00 = fmaxf(hreg[nt][0], 0.f), w01 = fmaxf(hreg[nt][1], 0.f);
            float w10 = fmaxf(hreg[nt][2], 0.f), w11 = fmaxf(hreg[nt][3], 0.f);
            if (last) {
                HF[r0*HFSTR + col] = w00; HF[r0*HFSTR + col+1] = w01;
                HF[r1*HFSTR + col] = w10; HF[r1*HFSTR + col+1] = w11;
            } else {
                *(u32*)(smem + AIMG + r0*AST + col*2) = pack_h(w00, w01);
                *(u32*)(smem + AIMG + r1*AST + col*2) = pack_h(w10, w11);
            }
        }
    }
    __syncthreads();

    /* ---- head: 7 outputs per token (HF holds fp32 relu(h)) ---- */
    if (tid < TILE_M) {
        int m = tid;
        float o[7];
        #pragma unroll
        for (int j = 0; j < 7; j++) o[j] = g_bout[j];
        const float* rrow = (const float*)(smem + BB0) + m*HFSTR;
        #pragma unroll 4
        for (int k = 0; k < CH; k++) {
            float r = rrow[k];
            const float* wp = g_WTout + k*8;
            #pragma unroll
            for (int j = 0; j < 7; j++) o[j] = fmaf(r, wp[j], o[j]);
        }
        float d0 = softplus_f(o[0]) * softplus_f(o[5]) + softplus_f(o[6]);
        int g = tok0 + m;
        g_scratch[g*5 + 0] = d0;
        g_scratch[g*5 + 1] = o[1];
        g_scratch[g*5 + 2] = o[2];
        g_scratch[g*5 + 3] = o[3];
        g_scratch[g*5 + 4] = o[4];
    }
}

/* ------- diagonal writer (zeros already laid down by fused kernel) ------- */
__global__ void diag_kernel(float* __restrict__ out, const float* __restrict__ smp)
{
    const float sm = *smp;
    int row = blockIdx.x * blockDim.x + threadIdx.x;   /* 0..16383 */
    int i   = row & (NTOK - 1);
    size_t base = (size_t)row * NTOK;

    float d0 = sm * g_scratch[row*5 + 0];
    out[base + i] = d0;
    if (i >= 1) out[base + i - 1] = sm * (g_scratch[row*5 + 1] + g_scratch[(row-1)*5 + 3]);
    if (i >= 2) out[base + i - 2] = sm * (g_scratch[row*5 + 2] + g_scratch[(row-2)*5 + 4]);
}

/* ---------------- launch ---------------- */
extern "C" void kernel_launch(void* const* d_in, const int* in_sizes, int n_in,
                              void* d_out, int out_size)
{
    (void)in_sizes; (void)n_in; (void)out_size;
    const float* s    = (const float*)d_in[0];
    const float* si   = (const float*)d_in[1];
    const float* ds   = (const float*)d_in[2];
    const float* Win  = (const float*)d_in[3];
    const float* bin  = (const float*)d_in[4];
    const float* Wini = (const float*)d_in[5];
    const float* bini = (const float*)d_in[6];
    const float* Wd   = (const float*)d_in[7];
    const float* bd   = (const float*)d_in[8];
    const float* W1   = (const float*)d_in[9];
    const float* b1   = (const float*)d_in[10];
    const float* W2   = (const float*)d_in[11];
    const float* b2   = (const float*)d_in[12];
    const float* Wout = (const float*)d_in[13];
    const float* bout = (const float*)d_in[14];
    const float* Wmu  = (const float*)d_in[15];
    const float* bmu  = (const float*)d_in[16];
    const float* smod = (const float*)d_in[17];
    float* out = (float*)d_out;

    cudaFuncSetAttribute(fused_mlp_kernel,
                         cudaFuncAttributeMaxDynamicSharedMemorySize, SMEM_TOTAL);

    prep_kernel<<<148, 256>>>(Win, bin, Wini, bini, Wd, bd, W1, W2, Wout, bout, Wmu, bmu);
    fused_mlp_kernel<<<TOKENS/TILE_M, NTHR, SMEM_TOTAL>>>(s, si, ds, b1, b2, out);
    diag_kernel<<<TOKENS/128, 128>>>(out, smod);
}

// round 13
// speedup vs baseline: 4.0670x; 1.1477x over previous
#include <cuda_runtime.h>
#include <cuda_fp16.h>
#include <math.h>

typedef unsigned int u32;
typedef unsigned long long u64;

#define BSZ     4
#define NTOK    4096
#define C_IN    384
#define C_DSSP  64
#define CH      128
#define NB      4
#define TOKENS  (BSZ*NTOK)   /* 16384 */
#define TILE_M  64
#define NTHR    512
#define AST     272          /* A/B smem row stride in BYTES (136 fp16) */
#define NSTAGES 15           /* 7 phase-1 + 8 resnet GEMM stages */

/* smem layout (bytes): A ping-pong + B ping-pong */
#define A0    0
#define A1    17408
#define BB0   34816
#define BB1   69632
#define SMEM_TOTAL 104448
#define HFSTR 133            /* fp32 head-buffer row stride (floats); HF lives at BB1 */

#define IMG_BYTES 34816      /* one B image: 128 rows x 136 fp16 */
#define IMG_V16   (IMG_BYTES/16)   /* 2176 */

/* ---------------- device scratch (no allocations allowed) ---------------- */
__device__ __align__(16) char g_Bcat[7][IMG_BYTES];
__device__ __align__(16) char g_B1[NB][IMG_BYTES];
__device__ __align__(16) char g_B2[NB][IMG_BYTES];
__device__ __align__(16) float g_WTout[CH*8];
__device__ float g_bias0[CH];
__device__ float g_bout[8];
__device__ float g_scratch[TOKENS*5];

/* ---------------- helpers ---------------- */
__device__ __forceinline__ u32 smem_u32(const void* p) {
    u32 a;
    asm("{ .reg .u64 t; cvta.to.shared.u64 t, %1; cvt.u32.u64 %0, t; }" : "=r"(a) : "l"(p));
    return a;
}
__device__ __forceinline__ void ldsm4(u32& r0, u32& r1, u32& r2, u32& r3, u32 addr)
{
    asm volatile("ldmatrix.sync.aligned.m8n8.x4.shared.b16 {%0,%1,%2,%3}, [%4];"
        : "=r"(r0), "=r"(r1), "=r"(r2), "=r"(r3) : "r"(addr));
}
__device__ __forceinline__ void mma16816(float (&c)[4], const u32 (&a)[4], u32 b0, u32 b1)
{
    asm volatile("mma.sync.aligned.m16n8k16.row.col.f32.f16.f16.f32 "
        "{%0,%1,%2,%3},{%4,%5,%6,%7},{%8,%9},{%0,%1,%2,%3};"
        : "+f"(c[0]), "+f"(c[1]), "+f"(c[2]), "+f"(c[3])
        : "r"(a[0]), "r"(a[1]), "r"(a[2]), "r"(a[3]), "r"(b0), "r"(b1));
}
__device__ __forceinline__ u32 pack_h(float a, float b)
{
    __half ha = __float2half_rn(a), hb = __float2half_rn(b);
    return (u32)__half_as_ushort(ha) | ((u32)__half_as_ushort(hb) << 16);
}
__device__ __forceinline__ float softplus_f(float x)
{
    return fmaxf(x, 0.f) + log1pf(expf(-fabsf(x)));
}
__device__ __forceinline__ const char* stage_img(int s)
{
    if (s < 7) return g_Bcat[s];
    int r = s - 7;
    return (r & 1) ? g_B2[r >> 1] : g_B1[r >> 1];
}
__device__ __forceinline__ void prefetch_img(const char* src, u32 dst, int tid)
{
    u64 g = __cvta_generic_to_global(src);
    #pragma unroll
    for (int i = 0; i < 5; i++) {
        int idx = i*NTHR + tid;
        if (idx < IMG_V16)
            asm volatile("cp.async.cg.shared.global [%0], [%1], 16;"
                :: "r"(dst + idx*16), "l"(g + (u64)idx*16));
    }
}
#define CP_COMMIT()  asm volatile("cp.async.commit_group;" ::: "memory")
#define CP_WAIT1()   asm volatile("cp.async.wait_group 1;" ::: "memory")

/* zero 9 float4 slices of this CTA's 64-row output region per stage */
__device__ __forceinline__ void zero_chunk(float* zbase, int s, int tid)
{
    int j0 = s*9, j1 = j0+9; if (j1 > 128) j1 = 128;
    #pragma unroll 1
    for (int j = j0; j < j1; j++) {
        float* p = zbase + (size_t)(j*NTHR + tid)*4;
        asm volatile("st.global.cs.v4.f32 [%0], {%1,%1,%1,%1};"
            :: "l"(p), "f"(0.f) : "memory");
    }
}

/* phase-1 A staging: split into LDG-issue and pack-store halves */
__device__ __forceinline__ void load_a(const float* src, int Krow, int Kc,
                                       int tid, float2 (&va)[8])
{
    int n  = (Kc == 128) ? 8 : 4;
    int pl = (Kc == 128) ? 6 : 5, pm = (Kc >> 1) - 1;
    #pragma unroll
    for (int i = 0; i < 8; i++) if (i < n) {
        int idx = i*NTHR + tid;
        int m = idx >> pl, kp = idx & pm;
        va[i] = *(const float2*)(src + (size_t)m*Krow + kp*2);
    }
}
__device__ __forceinline__ void pack_a(char* smem, u32 aoff, int Kc,
                                       int tid, const float2 (&va)[8])
{
    int n  = (Kc == 128) ? 8 : 4;
    int pl = (Kc == 128) ? 6 : 5, pm = (Kc >> 1) - 1;
    #pragma unroll
    for (int i = 0; i < 8; i++) if (i < n) {
        int idx = i*NTHR + tid;
        int m = idx >> pl, kp = idx & pm;
        *(u32*)(smem + aoff + m*AST + kp*4) =
            pack_h(fmaxf(va[i].x, 0.f), fmaxf(va[i].y, 0.f));
    }
}

/* ---------------- prep: fp16 weights into [n][k] images ---------------- */
__global__ void prep_kernel(
    const float* __restrict__ Win,  const float* __restrict__ bin,
    const float* __restrict__ Wini, const float* __restrict__ bini,
    const float* __restrict__ Wd,   const float* __restrict__ bd,
    const float* __restrict__ W1,   const float* __restrict__ W2,
    const float* __restrict__ Wout, const float* __restrict__ bout,
    const float* __restrict__ Wmu,  const float* __restrict__ bmu)
{
    int id = blockIdx.x * blockDim.x + threadIdx.x;
    int stride = gridDim.x * blockDim.x;

    for (int x = id; x < 128*832; x += stride) {
        int n = x / 832, k = x % 832;
        float v;
        if (k < 384)       v = Win [n*384 + k];
        else if (k < 768)  v = Wini[n*384 + (k-384)];
        else               v = Wd  [n*64  + (k-768)];
        int c = k >> 7, kc = k & 127;
        *(__half*)(g_Bcat[c] + (n*136 + kc)*2) = __float2half_rn(v);
    }
    for (int x = id; x < NB*128*128; x += stride) {
        int blk = x >> 14; int r = x & 16383; int n = r >> 7; int k = r & 127;
        int off = (n*136 + k)*2;
        *(__half*)(g_B1[blk] + off) = __float2half_rn(W1[x]);
        *(__half*)(g_B2[blk] + off) = __float2half_rn(W2[x]);
    }
    for (int x = id; x < CH*8; x += stride) {
        int k = x / 8, j = x % 8;
        float v = 0.f;
        if (j < 5)      v = Wout[j*CH + k];
        else if (j < 7) v = Wmu [(j-5)*CH + k];
        g_WTout[x] = v;
    }
    if (id < CH) g_bias0[id] = bin[id] + bini[id] + bd[id];
    if (id < 8)  g_bout[id] = (id < 5) ? bout[id] : ((id < 7) ? bmu[id-5] : 0.f);
}

/* ------- single-pass fp16 GEMM core: warp covers 16 rows x 32 cols ------- */
__device__ __forceinline__ void gemm1(u32 aimg, u32 bimg,
                                      int nks, u32 a_t, u32 b_t, float (&acc)[4][4])
{
    #pragma unroll 1
    for (int ks = 0; ks < nks; ks++) {
        u32 ah[4];
        ldsm4(ah[0], ah[1], ah[2], ah[3], aimg + a_t + ks*32);
        u32 bc[4], bn[4];
        ldsm4(bc[0], bc[1], bc[2], bc[3], bimg + b_t + ks*32);
        ldsm4(bn[0], bn[1], bn[2], bn[3], bimg + b_t + 4352 + ks*32);
        mma16816(acc[0], ah, bc[0], bc[1]);
        mma16816(acc[1], ah, bc[2], bc[3]);
        mma16816(acc[2], ah, bn[0], bn[1]);
        mma16816(acc[3], ah, bn[2], bn[3]);
    }
}

/* -------- fused MLP kernel: 64 tokens/CTA, 512 thr, 2 CTAs/SM, 1 bar/stage -- */
__global__ __launch_bounds__(NTHR, 2) void fused_mlp_kernel(
    const float* __restrict__ s, const float* __restrict__ si, const float* __restrict__ ds,
    const float* __restrict__ b1g, const float* __restrict__ b2g,
    float* __restrict__ out)
{
    extern __shared__ char smem[];
    const int tid  = threadIdx.x;
    const int w    = tid >> 5;
    const int wr   = w >> 2;            /* row group 0..3  (16 rows)  */
    const int wcc  = w & 3;             /* col group 0..3  (32 cols)  */
    const int lane = tid & 31;
    const int seg  = lane >> 3;
    const int rr   = lane & 7;
    const int tok0 = blockIdx.x * TILE_M;
    float* zbase = out + (size_t)tok0 * NTOK;

    const u32 a_t = (u32)((wr*16 + (seg & 1)*8 + rr)*AST + (seg >> 1)*16);
    const u32 b_t = (u32)((wcc*32 + (seg >> 1)*8 + rr)*AST + (seg & 1)*16);
    const int r0   = wr*16 + (lane >> 2);
    const int r1   = r0 + 8;
    const int colb = wcc*32 + (lane & 3)*2;

    u32 sb = smem_u32(smem);
    u32 aoff[2] = { A0, A1 };
    u32 bb[2]   = { sb + BB0, sb + BB1 };

    float acc[4][4], hreg[4][4];
    float2 va[8];
    #pragma unroll
    for (int i = 0; i < 4; i++)
        #pragma unroll
        for (int j = 0; j < 4; j++) acc[i][j] = 0.f;

    /* phase-1 chunk descriptors */
    const float* csrc[7]; int ckrow[7], ckc[7];
    #pragma unroll
    for (int c = 0; c < 3; c++) { csrc[c] = s  + (size_t)tok0*C_IN + c*128;     ckrow[c] = C_IN; ckc[c] = 128; }
    #pragma unroll
    for (int c = 3; c < 6; c++) { csrc[c] = si + (size_t)tok0*C_IN + (c-3)*128; ckrow[c] = C_IN; ckc[c] = 128; }
    csrc[6] = ds + (size_t)tok0*C_DSSP; ckrow[6] = C_DSSP; ckc[6] = 64;

    /* prologue: B(0) prefetch; A(0) load+pack into A[0] */
    prefetch_img(stage_img(0), bb[0], tid);
    CP_COMMIT();
    load_a(csrc[0], ckrow[0], ckc[0], tid, va);
    pack_a(smem, aoff[0], ckc[0], tid, va);

    /* ---- phase 1: 7 chunk-GEMM stages, one barrier each ---- */
    #pragma unroll 1
    for (int c = 0; c < 7; c++) {
        __syncthreads();                 /* A(c), B(c) visible; all done with stage c-1 */
        prefetch_img(stage_img(c+1), bb[(c+1)&1], tid);
        CP_COMMIT();
        if (c+1 < 7) load_a(csrc[c+1], ckrow[c+1], ckc[c+1], tid, va);
        CP_WAIT1();
        gemm1(sb + aoff[c&1], bb[c&1], (ckc[c] == 128) ? 8 : 4, a_t, b_t, acc);
        zero_chunk(zbase, c, tid);
        if (c+1 < 7) pack_a(smem, aoff[(c+1)&1], ckc[c+1], tid, va);
    }

    /* phase-1 epilogue: hreg = D + bias0; A[1] = fp16(relu(hreg)) (gemm6 read A[0]) */
    #pragma unroll
    for (int nt = 0; nt < 4; nt++) {
        int col = colb + nt*8;
        float bc0 = g_bias0[col], bc1 = g_bias0[col+1];
        hreg[nt][0] = acc[nt][0] + bc0; hreg[nt][1] = acc[nt][1] + bc1;
        hreg[nt][2] = acc[nt][2] + bc0; hreg[nt][3] = acc[nt][3] + bc1;
        *(u32*)(smem + A1 + r0*AST + col*2) =
            pack_h(fmaxf(hreg[nt][0], 0.f), fmaxf(hreg[nt][1], 0.f));
        *(u32*)(smem + A1 + r1*AST + col*2) =
            pack_h(fmaxf(hreg[nt][2], 0.f), fmaxf(hreg[nt][3], 0.f));
    }

    /* ---- resnet: 8 stages, one barrier each; A ping-pongs via epilogues ---- */
    int ap = 1;                          /* first resnet gemm reads A[1] */
    #pragma unroll 1
    for (int st = 7; st < NSTAGES; st++) {
        __syncthreads();
        if (st+1 < NSTAGES) prefetch_img(stage_img(st+1), bb[(st+1)&1], tid);
        CP_COMMIT();
        CP_WAIT1();
        #pragma unroll
        for (int i = 0; i < 4; i++)
            #pragma unroll
            for (int j = 0; j < 4; j++) acc[i][j] = 0.f;
        gemm1(sb + aoff[ap], bb[st&1], 8, a_t, b_t, acc);
        zero_chunk(zbase, st, tid);

        int r = st - 7;
        int blk = r >> 1;
        if (!(r & 1)) {
            /* after GEMM1: A[ap^1] = fp16(relu(acc + b1)) */
            const float* bb1 = b1g + blk*CH;
            #pragma unroll
            for (int nt = 0; nt < 4; nt++) {
                int col = colb + nt*8;
                float bc0 = bb1[col], bc1 = bb1[col+1];
                *(u32*)(smem + aoff[ap^1] + r0*AST + col*2) =
                    pack_h(fmaxf(acc[nt][0] + bc0, 0.f), fmaxf(acc[nt][1] + bc1, 0.f));
                *(u32*)(smem + aoff[ap^1] + r1*AST + col*2) =
                    pack_h(fmaxf(acc[nt][2] + bc0, 0.f), fmaxf(acc[nt][3] + bc1, 0.f));
            }
        } else {
            /* after GEMM2: h += acc + b2; A[ap^1] or HF(last) */
            const float* bb2 = b2g + blk*CH;
            bool last = (st == NSTAGES-1);
            float* HF = (float*)(smem + BB1);   /* BB1 last read at stage 13 */
            #pragma unroll
            for (int nt = 0; nt < 4; nt++) {
                int col = colb + nt*8;
                float bc0 = bb2[col], bc1 = bb2[col+1];
                hreg[nt][0] += acc[nt][0] + bc0; hreg[nt][1] += acc[nt][1] + bc1;
                hreg[nt][2] += acc[nt][2] + bc0; hreg[nt][3] += acc[nt][3] + bc1;
                float w00 = fmaxf(hreg[nt][0], 0.f), w01 = fmaxf(hreg[nt][1], 0.f);
                float w10 = fmaxf(hreg[nt][2], 0.f), w11 = fmaxf(hreg[nt][3], 0.f);
                if (last) {
                    HF[r0*HFSTR + col] = w00; HF[r0*HFSTR + col+1] = w01;
                    HF[r1*HFSTR + col] = w10; HF[r1*HFSTR + col+1] = w11;
                } else {
                    *(u32*)(smem + aoff[ap^1] + r0*AST + col*2) = pack_h(w00, w01);
                    *(u32*)(smem + aoff[ap^1] + r1*AST + col*2) = pack_h(w10, w11);
                }
            }
        }
        ap ^= 1;
    }
    __syncthreads();

    /* ---- head: 7 outputs per token (HF at BB1 holds fp32 relu(h)) ---- */
    if (tid < TILE_M) {
        int m = tid;
        float o[7];
        #pragma unroll
        for (int j = 0; j < 7; j++) o[j] = g_bout[j];
        const float* rrow = (const float*)(smem + BB1) + m*HFSTR;
        #pragma unroll 4
        for (int k = 0; k < CH; k++) {
            float r = rrow[k];
            const float* wp = g_WTout + k*8;
            #pragma unroll
            for (int j = 0; j < 7; j++) o[j] = fmaf(r, wp[j], o[j]);
        }
        float d0 = softplus_f(o[0]) * softplus_f(o[5]) + softplus_f(o[6]);
        int g = tok0 + m;
        g_scratch[g*5 + 0] = d0;
        g_scratch[g*5 + 1] = o[1];
        g_scratch[g*5 + 2] = o[2];
        g_scratch[g*5 + 3] = o[3];
        g_scratch[g*5 + 4] = o[4];
    }
}

/* ------- diagonal writer (zeros already laid down by fused kernel) ------- */
__global__ void diag_kernel(float* __restrict__ out, const float* __restrict__ smp)
{
    const float sm = *smp;
    int row = blockIdx.x * blockDim.x + threadIdx.x;   /* 0..16383 */
    int i   = row & (NTOK - 1);
    size_t base = (size_t)row * NTOK;

    float d0 = sm * g_scratch[row*5 + 0];
    out[base + i] = d0;
    if (i >= 1) out[base + i - 1] = sm * (g_scratch[row*5 + 1] + g_scratch[(row-1)*5 + 3]);
    if (i >= 2) out[base + i - 2] = sm * (g_scratch[row*5 + 2] + g_scratch[(row-2)*5 + 4]);
}

/* ---------------- launch ---------------- */
extern "C" void kernel_launch(void* const* d_in, const int* in_sizes, int n_in,
                              void* d_out, int out_size)
{
    (void)in_sizes; (void)n_in; (void)out_size;
    const float* s    = (const float*)d_in[0];
    const float* si   = (const float*)d_in[1];
    const float* ds   = (const float*)d_in[2];
    const float* Win  = (const float*)d_in[3];
    const float* bin  = (const float*)d_in[4];
    const float* Wini = (const float*)d_in[5];
    const float* bini = (const float*)d_in[6];
    const float* Wd   = (const float*)d_in[7];
    const float* bd   = (const float*)d_in[8];
    const float* W1   = (const float*)d_in[9];
    const float* b1   = (const float*)d_in[10];
    const float* W2   = (const float*)d_in[11];
    const float* b2   = (const float*)d_in[12];
    const float* Wout = (const float*)d_in[13];
    const float* bout = (const float*)d_in[14];
    const float* Wmu  = (const float*)d_in[15];
    const float* bmu  = (const float*)d_in[16];
    const float* smod = (const float*)d_in[17];
    float* out = (float*)d_out;

    cudaFuncSetAttribute(fused_mlp_kernel,
                         cudaFuncAttributeMaxDynamicSharedMemorySize, SMEM_TOTAL);

    prep_kernel<<<148, 256>>>(Win, bin, Wini, bini, Wd, bd, W1, W2, Wout, bout, Wmu, bmu);
    fused_mlp_kernel<<<TOKENS/TILE_M, NTHR, SMEM_TOTAL>>>(s, si, ds, b1, b2, out);
    diag_kernel<<<TOKENS/128, 128>>>(out, smod);
}

// round 14
// speedup vs baseline: 4.1381x; 1.0175x over previous
#include <cuda_runtime.h>
#include <cuda_fp16.h>
#include <math.h>

typedef unsigned int u32;
typedef unsigned long long u64;

#define BSZ     4
#define NTOK    4096
#define C_IN    384
#define C_DSSP  64
#define CH      128
#define NB      4
#define TOKENS  (BSZ*NTOK)   /* 16384 */
#define TILE_M  64
#define NTHR    512
#define AST     272          /* A/B smem row stride in BYTES (136 fp16) */
#define NSTAGES 15           /* 7 phase-1 + 8 resnet GEMM stages */

/* smem layout (bytes): A ping-pong + B ping-pong */
#define A0    0
#define A1    17408
#define BB0   34816
#define BB1   69632
#define SMEM_TOTAL 104448
#define HFSTR 133            /* fp32 head-buffer row stride (floats); HF lives at BB1 */

#define IMG_BYTES 34816      /* one B image: 128 rows x 136 fp16 */
#define IMG_V16   (IMG_BYTES/16)   /* 2176 */

/* ---------------- device scratch (no allocations allowed) ---------------- */
__device__ __align__(16) char g_Bcat[7][IMG_BYTES];
__device__ __align__(16) char g_B1[NB][IMG_BYTES];
__device__ __align__(16) char g_B2[NB][IMG_BYTES];
__device__ __align__(16) float g_WTout[CH*8];
__device__ float g_bias0[CH];
__device__ float g_bout[8];
__device__ float g_scratch[TOKENS*5];

/* ---------------- helpers ---------------- */
__device__ __forceinline__ u32 smem_u32(const void* p) {
    u32 a;
    asm("{ .reg .u64 t; cvta.to.shared.u64 t, %1; cvt.u32.u64 %0, t; }" : "=r"(a) : "l"(p));
    return a;
}
__device__ __forceinline__ void ldsm4(u32& r0, u32& r1, u32& r2, u32& r3, u32 addr)
{
    asm volatile("ldmatrix.sync.aligned.m8n8.x4.shared.b16 {%0,%1,%2,%3}, [%4];"
        : "=r"(r0), "=r"(r1), "=r"(r2), "=r"(r3) : "r"(addr));
}
__device__ __forceinline__ void mma16816(float (&c)[4], const u32 (&a)[4], u32 b0, u32 b1)
{
    asm volatile("mma.sync.aligned.m16n8k16.row.col.f32.f16.f16.f32 "
        "{%0,%1,%2,%3},{%4,%5,%6,%7},{%8,%9},{%0,%1,%2,%3};"
        : "+f"(c[0]), "+f"(c[1]), "+f"(c[2]), "+f"(c[3])
        : "r"(a[0]), "r"(a[1]), "r"(a[2]), "r"(a[3]), "r"(b0), "r"(b1));
}
__device__ __forceinline__ u32 pack_h(float a, float b)
{
    __half ha = __float2half_rn(a), hb = __float2half_rn(b);
    return (u32)__half_as_ushort(ha) | ((u32)__half_as_ushort(hb) << 16);
}
__device__ __forceinline__ float softplus_f(float x)
{
    return fmaxf(x, 0.f) + log1pf(expf(-fabsf(x)));
}
__device__ __forceinline__ const char* stage_img(int s)
{
    if (s < 7) return g_Bcat[s];
    int r = s - 7;
    return (r & 1) ? g_B2[r >> 1] : g_B1[r >> 1];
}
__device__ __forceinline__ void prefetch_img(const char* src, u32 dst, int tid)
{
    u64 g = __cvta_generic_to_global(src);
    #pragma unroll
    for (int i = 0; i < 5; i++) {
        int idx = i*NTHR + tid;
        if (idx < IMG_V16)
            asm volatile("cp.async.cg.shared.global [%0], [%1], 16;"
                :: "r"(dst + idx*16), "l"(g + (u64)idx*16));
    }
}
#define CP_COMMIT()  asm volatile("cp.async.commit_group;" ::: "memory")
#define CP_WAIT1()   asm volatile("cp.async.wait_group 1;" ::: "memory")

/* zero 9 float4 slices of this CTA's 64-row output region per stage */
__device__ __forceinline__ void zero_chunk(float* zbase, int s, int tid)
{
    int j0 = s*9, j1 = j0+9; if (j1 > 128) j1 = 128;
    #pragma unroll 1
    for (int j = j0; j < j1; j++) {
        float* p = zbase + (size_t)(j*NTHR + tid)*4;
        asm volatile("st.global.cs.v4.f32 [%0], {%1,%1,%1,%1};"
            :: "l"(p), "f"(0.f) : "memory");
    }
}

/* phase-1 A staging: split into LDG-issue and pack-store halves */
__device__ __forceinline__ void load_a(const float* src, int Krow, int Kc,
                                       int tid, float2 (&va)[8])
{
    int n  = (Kc == 128) ? 8 : 4;
    int pl = (Kc == 128) ? 6 : 5, pm = (Kc >> 1) - 1;
    #pragma unroll
    for (int i = 0; i < 8; i++) if (i < n) {
        int idx = i*NTHR + tid;
        int m = idx >> pl, kp = idx & pm;
        va[i] = *(const float2*)(src + (size_t)m*Krow + kp*2);
    }
}
__device__ __forceinline__ void pack_a(char* smem, u32 aoff, int Kc,
                                       int tid, const float2 (&va)[8])
{
    int n  = (Kc == 128) ? 8 : 4;
    int pl = (Kc == 128) ? 6 : 5, pm = (Kc >> 1) - 1;
    #pragma unroll
    for (int i = 0; i < 8; i++) if (i < n) {
        int idx = i*NTHR + tid;
        int m = idx >> pl, kp = idx & pm;
        *(u32*)(smem + aoff + m*AST + kp*4) =
            pack_h(fmaxf(va[i].x, 0.f), fmaxf(va[i].y, 0.f));
    }
}

/* -------- prep: fp16 weights into [n][k] images, destination-coalesced ----- */
__global__ void prep_kernel(
    const float* __restrict__ Win,  const float* __restrict__ bin,
    const float* __restrict__ Wini, const float* __restrict__ bini,
    const float* __restrict__ Wd,   const float* __restrict__ bd,
    const float* __restrict__ W1,   const float* __restrict__ W2,
    const float* __restrict__ Wout, const float* __restrict__ bout,
    const float* __restrict__ Wmu,  const float* __restrict__ bmu)
{
    int id = blockIdx.x * blockDim.x + threadIdx.x;
    int stride = gridDim.x * blockDim.x;

    /* g_Bcat: 7 images x 128 rows x 64 u32-pairs, dest- and src-coalesced */
    for (int x = id; x < 7*128*64; x += stride) {
        int c  = x / (128*64);
        int r  = x - c*128*64;
        int n  = r >> 6;          /* image row  */
        int kp = r & 63;          /* u32 column */
        int k  = c*128 + kp*2;    /* concat k   */
        float2 v;
        if (k < 384)       v = *(const float2*)(Win  + n*384 + k);
        else if (k < 768)  v = *(const float2*)(Wini + n*384 + (k-384));
        else               v = *(const float2*)(Wd   + n*64  + (k-768));
        *(u32*)(g_Bcat[c] + n*136*2 + kp*4) = pack_h(v.x, v.y);
    }
    /* g_B1/g_B2: NB images x 128 rows x 64 u32 */
    for (int x = id; x < NB*128*64; x += stride) {
        int blk = x / (128*64);
        int r   = x - blk*128*64;
        int n   = r >> 6, kp = r & 63;
        int off = n*136*2 + kp*4;
        float2 v1 = *(const float2*)(W1 + blk*CH*CH + n*CH + kp*2);
        float2 v2 = *(const float2*)(W2 + blk*CH*CH + n*CH + kp*2);
        *(u32*)(g_B1[blk] + off) = pack_h(v1.x, v1.y);
        *(u32*)(g_B2[blk] + off) = pack_h(v2.x, v2.y);
    }
    for (int x = id; x < CH*8; x += stride) {
        int k = x / 8, j = x % 8;
        float v = 0.f;
        if (j < 5)      v = Wout[j*CH + k];
        else if (j < 7) v = Wmu [(j-5)*CH + k];
        g_WTout[x] = v;
    }
    if (id < CH) g_bias0[id] = bin[id] + bini[id] + bd[id];
    if (id < 8)  g_bout[id] = (id < 5) ? bout[id] : ((id < 7) ? bmu[id-5] : 0.f);
}

/* ------- single-pass fp16 GEMM core: warp covers 16 rows x 32 cols -------
   Unroll-by-2 over k-steps: LDSMs of ks+1 overlap MMAs of ks. */
template<int NKS>
__device__ __forceinline__ void gemm1(u32 aimg, u32 bimg,
                                      u32 a_t, u32 b_t, float (&acc)[4][4])
{
    #pragma unroll 2
    for (int ks = 0; ks < NKS; ks++) {
        u32 ah[4];
        ldsm4(ah[0], ah[1], ah[2], ah[3], aimg + a_t + ks*32);
        u32 bc[4], bn[4];
        ldsm4(bc[0], bc[1], bc[2], bc[3], bimg + b_t + ks*32);
        ldsm4(bn[0], bn[1], bn[2], bn[3], bimg + b_t + 4352 + ks*32);
        mma16816(acc[0], ah, bc[0], bc[1]);
        mma16816(acc[1], ah, bc[2], bc[3]);
        mma16816(acc[2], ah, bn[0], bn[1]);
        mma16816(acc[3], ah, bn[2], bn[3]);
    }
}

/* -------- fused MLP kernel: 64 tokens/CTA, 512 thr, 2 CTAs/SM, 1 bar/stage -- */
__global__ __launch_bounds__(NTHR, 2) void fused_mlp_kernel(
    const float* __restrict__ s, const float* __restrict__ si, const float* __restrict__ ds,
    const float* __restrict__ b1g, const float* __restrict__ b2g,
    float* __restrict__ out)
{
    extern __shared__ char smem[];
    const int tid  = threadIdx.x;
    const int w    = tid >> 5;
    const int wr   = w >> 2;            /* row group 0..3  (16 rows)  */
    const int wcc  = w & 3;             /* col group 0..3  (32 cols)  */
    const int lane = tid & 31;
    const int seg  = lane >> 3;
    const int rr   = lane & 7;
    const int tok0 = blockIdx.x * TILE_M;
    float* zbase = out + (size_t)tok0 * NTOK;

    const u32 a_t = (u32)((wr*16 + (seg & 1)*8 + rr)*AST + (seg >> 1)*16);
    const u32 b_t = (u32)((wcc*32 + (seg >> 1)*8 + rr)*AST + (seg & 1)*16);
    const int r0   = wr*16 + (lane >> 2);
    const int r1   = r0 + 8;
    const int colb = wcc*32 + (lane & 3)*2;

    u32 sb = smem_u32(smem);
    u32 aoff[2] = { A0, A1 };
    u32 bb[2]   = { sb + BB0, sb + BB1 };

    float acc[4][4], hreg[4][4];
    float2 va[8];
    #pragma unroll
    for (int i = 0; i < 4; i++)
        #pragma unroll
        for (int j = 0; j < 4; j++) acc[i][j] = 0.f;

    /* phase-1 chunk descriptors */
    const float* csrc[7]; int ckrow[7], ckc[7];
    #pragma unroll
    for (int c = 0; c < 3; c++) { csrc[c] = s  + (size_t)tok0*C_IN + c*128;     ckrow[c] = C_IN; ckc[c] = 128; }
    #pragma unroll
    for (int c = 3; c < 6; c++) { csrc[c] = si + (size_t)tok0*C_IN + (c-3)*128; ckrow[c] = C_IN; ckc[c] = 128; }
    csrc[6] = ds + (size_t)tok0*C_DSSP; ckrow[6] = C_DSSP; ckc[6] = 64;

    /* prologue: B(0) prefetch; A(0) load+pack into A[0] */
    prefetch_img(stage_img(0), bb[0], tid);
    CP_COMMIT();
    load_a(csrc[0], ckrow[0], ckc[0], tid, va);
    pack_a(smem, aoff[0], ckc[0], tid, va);

    /* ---- phase 1: 7 chunk-GEMM stages, one barrier each ---- */
    #pragma unroll 1
    for (int c = 0; c < 7; c++) {
        __syncthreads();                 /* A(c), B(c) visible; all done with stage c-1 */
        prefetch_img(stage_img(c+1), bb[(c+1)&1], tid);
        CP_COMMIT();
        if (c+1 < 7) load_a(csrc[c+1], ckrow[c+1], ckc[c+1], tid, va);
        CP_WAIT1();
        if (ckc[c] == 128) gemm1<8>(sb + aoff[c&1], bb[c&1], a_t, b_t, acc);
        else               gemm1<4>(sb + aoff[c&1], bb[c&1], a_t, b_t, acc);
        zero_chunk(zbase, c, tid);
        if (c+1 < 7) pack_a(smem, aoff[(c+1)&1], ckc[c+1], tid, va);
    }

    /* phase-1 epilogue: hreg = D + bias0; A[1] = fp16(relu(hreg)) (gemm6 read A[0]) */
    #pragma unroll
    for (int nt = 0; nt < 4; nt++) {
        int col = colb + nt*8;
        float bc0 = g_bias0[col], bc1 = g_bias0[col+1];
        hreg[nt][0] = acc[nt][0] + bc0; hreg[nt][1] = acc[nt][1] + bc1;
        hreg[nt][2] = acc[nt][2] + bc0; hreg[nt][3] = acc[nt][3] + bc1;
        *(u32*)(smem + A1 + r0*AST + col*2) =
            pack_h(fmaxf(hreg[nt][0], 0.f), fmaxf(hreg[nt][1], 0.f));
        *(u32*)(smem + A1 + r1*AST + col*2) =
            pack_h(fmaxf(hreg[nt][2], 0.f), fmaxf(hreg[nt][3], 0.f));
    }

    /* ---- resnet: 8 stages, one barrier each; A ping-pongs via epilogues ---- */
    int ap = 1;                          /* first resnet gemm reads A[1] */
    #pragma unroll 1
    for (int st = 7; st < NSTAGES; st++) {
        __syncthreads();
        if (st+1 < NSTAGES) prefetch_img(stage_img(st+1), bb[(st+1)&1], tid);
        CP_COMMIT();
        CP_WAIT1();
        #pragma unroll
        for (int i = 0; i < 4; i++)
            #pragma unroll
            for (int j = 0; j < 4; j++) acc[i][j] = 0.f;
        gemm1<8>(sb + aoff[ap], bb[st&1], a_t, b_t, acc);
        zero_chunk(zbase, st, tid);

        int r = st - 7;
        int blk = r >> 1;
        if (!(r & 1)) {
            /* after GEMM1: A[ap^1] = fp16(relu(acc + b1)) */
            const float* bb1 = b1g + blk*CH;
            #pragma unroll
            for (int nt = 0; nt < 4; nt++) {
                int col = colb + nt*8;
                float bc0 = bb1[col], bc1 = bb1[col+1];
                *(u32*)(smem + aoff[ap^1] + r0*AST + col*2) =
                    pack_h(fmaxf(acc[nt][0] + bc0, 0.f), fmaxf(acc[nt][1] + bc1, 0.f));
                *(u32*)(smem + aoff[ap^1] + r1*AST + col*2) =
                    pack_h(fmaxf(acc[nt][2] + bc0, 0.f), fmaxf(acc[nt][3] + bc1, 0.f));
            }
        } else {
            /* after GEMM2: h += acc + b2; A[ap^1] or HF(last) */
            const float* bb2 = b2g + blk*CH;
            bool last = (st == NSTAGES-1);
            float* HF = (float*)(smem + BB1);   /* BB1 last read at stage 13 */
            #pragma unroll
            for (int nt = 0; nt < 4; nt++) {
                int col = colb + nt*8;
                float bc0 = bb2[col], bc1 = bb2[col+1];
                hreg[nt][0] += acc[nt][0] + bc0; hreg[nt][1] += acc[nt][1] + bc1;
                hreg[nt][2] += acc[nt][2] + bc0; hreg[nt][3] += acc[nt][3] + bc1;
                float w00 = fmaxf(hreg[nt][0], 0.f), w01 = fmaxf(hreg[nt][1], 0.f);
                float w10 = fmaxf(hreg[nt][2], 0.f), w11 = fmaxf(hreg[nt][3], 0.f);
                if (last) {
                    HF[r0*HFSTR + col] = w00; HF[r0*HFSTR + col+1] = w01;
                    HF[r1*HFSTR + col] = w10; HF[r1*HFSTR + col+1] = w11;
                } else {
                    *(u32*)(smem + aoff[ap^1] + r0*AST + col*2) = pack_h(w00, w01);
                    *(u32*)(smem + aoff[ap^1] + r1*AST + col*2) = pack_h(w10, w11);
                }
            }
        }
        ap ^= 1;
    }
    __syncthreads();

    /* ---- head: 7 outputs per token (HF at BB1 holds fp32 relu(h)) ---- */
    if (tid < TILE_M) {
        int m = tid;
        float o[7];
        #pragma unroll
        for (int j = 0; j < 7; j++) o[j] = g_bout[j];
        const float* rrow = (const float*)(smem + BB1) + m*HFSTR;
        #pragma unroll 4
        for (int k = 0; k < CH; k++) {
            float r = rrow[k];
            const float* wp = g_WTout + k*8;
            #pragma unroll
            for (int j = 0; j < 7; j++) o[j] = fmaf(r, wp[j], o[j]);
        }
        float d0 = softplus_f(o[0]) * softplus_f(o[5]) + softplus_f(o[6]);
        int g = tok0 + m;
        g_scratch[g*5 + 0] = d0;
        g_scratch[g*5 + 1] = o[1];
        g_scratch[g*5 + 2] = o[2];
        g_scratch[g*5 + 3] = o[3];
        g_scratch[g*5 + 4] = o[4];
    }
}

/* ------- diagonal writer (zeros already laid down by fused kernel) ------- */
__global__ void diag_kernel(float* __restrict__ out, const float* __restrict__ smp)
{
    const float sm = *smp;
    int row = blockIdx.x * blockDim.x + threadIdx.x;   /* 0..16383 */
    int i   = row & (NTOK - 1);
    size_t base = (size_t)row * NTOK;

    float d0 = sm * g_scratch[row*5 + 0];
    out[base + i] = d0;
    if (i >= 1) out[base + i - 1] = sm * (g_scratch[row*5 + 1] + g_scratch[(row-1)*5 + 3]);
    if (i >= 2) out[base + i - 2] = sm * (g_scratch[row*5 + 2] + g_scratch[(row-2)*5 + 4]);
}

/* ---------------- launch ---------------- */
extern "C" void kernel_launch(void* const* d_in, const int* in_sizes, int n_in,
                              void* d_out, int out_size)
{
    (void)in_sizes; (void)n_in; (void)out_size;
    const float* s    = (const float*)d_in[0];
    const float* si   = (const float*)d_in[1];
    const float* ds   = (const float*)d_in[2];
    const float* Win  = (const float*)d_in[3];
    const float* bin  = (const float*)d_in[4];
    const float* Wini = (const float*)d_in[5];
    const float* bini = (const float*)d_in[6];
    const float* Wd   = (const float*)d_in[7];
    const float* bd   = (const float*)d_in[8];
    const float* W1   = (const float*)d_in[9];
    const float* b1   = (const float*)d_in[10];
    const float* W2   = (const float*)d_in[11];
    const float* b2   = (const float*)d_in[12];
    const float* Wout = (const float*)d_in[13];
    const float* bout = (const float*)d_in[14];
    const float* Wmu  = (const float*)d_in[15];
    const float* bmu  = (const float*)d_in[16];
    const float* smod = (const float*)d_in[17];
    float* out = (float*)d_out;

    cudaFuncSetAttribute(fused_mlp_kernel,
                         cudaFuncAttributeMaxDynamicSharedMemorySize, SMEM_TOTAL);

    prep_kernel<<<148, 256>>>(Win, bin, Wini, bini, Wd, bd, W1, W2, Wout, bout, Wmu, bmu);
    fused_mlp_kernel<<<TOKENS/TILE_M, NTHR, SMEM_TOTAL>>>(s, si, ds, b1, b2, out);
    diag_kernel<<<TOKENS/128, 128>>>(out, smod);
}

// round 16
// speedup vs baseline: 4.1614x; 1.0056x over previous
#include <cuda_runtime.h>
#include <cuda_fp16.h>
#include <math.h>

typedef unsigned int u32;
typedef unsigned long long u64;

#define BSZ     4
#define NTOK    4096
#define C_IN    384
#define C_DSSP  64
#define CH      128
#define NB      4
#define TOKENS  (BSZ*NTOK)   /* 16384 */
#define TILE_M  64
#define NTHR    512
#define AST     272          /* A/B smem row stride in BYTES (136 fp16) */
#define NSTAGES 15           /* 7 phase-1 + 8 resnet GEMM stages */

/* smem layout (bytes): A ping-pong + B ping-pong */
#define A0    0
#define A1    17408
#define BB0   34816
#define BB1   69632
#define SMEM_TOTAL 104448
#define HFSTR 133            /* fp32 head-buffer row stride (floats); HF lives at BB1 */

#define IMG_BYTES 34816      /* one B image: 128 rows x 136 fp16 */
#define IMG_V16   (IMG_BYTES/16)   /* 2176 */

/* ---------------- device scratch (no allocations allowed) ---------------- */
__device__ __align__(16) char g_Bcat[7][IMG_BYTES];
__device__ __align__(16) char g_B1[NB][IMG_BYTES];
__device__ __align__(16) char g_B2[NB][IMG_BYTES];
__device__ __align__(16) float g_WTout[CH*8];
__device__ float g_bias0[CH];
__device__ float g_bout[8];
__device__ float g_scratch[TOKENS*5];

/* ---------------- helpers ---------------- */
__device__ __forceinline__ u32 smem_u32(const void* p) {
    u32 a;
    asm("{ .reg .u64 t; cvta.to.shared.u64 t, %1; cvt.u32.u64 %0, t; }" : "=r"(a) : "l"(p));
    return a;
}
__device__ __forceinline__ void ldsm4(u32& r0, u32& r1, u32& r2, u32& r3, u32 addr)
{
    asm volatile("ldmatrix.sync.aligned.m8n8.x4.shared.b16 {%0,%1,%2,%3}, [%4];"
        : "=r"(r0), "=r"(r1), "=r"(r2), "=r"(r3) : "r"(addr));
}
__device__ __forceinline__ void mma16816(float (&c)[4], const u32 (&a)[4], u32 b0, u32 b1)
{
    asm volatile("mma.sync.aligned.m16n8k16.row.col.f32.f16.f16.f32 "
        "{%0,%1,%2,%3},{%4,%5,%6,%7},{%8,%9},{%0,%1,%2,%3};"
        : "+f"(c[0]), "+f"(c[1]), "+f"(c[2]), "+f"(c[3])
        : "r"(a[0]), "r"(a[1]), "r"(a[2]), "r"(a[3]), "r"(b0), "r"(b1));
}
__device__ __forceinline__ u32 pack_h(float a, float b)
{
    __half ha = __float2half_rn(a), hb = __float2half_rn(b);
    return (u32)__half_as_ushort(ha) | ((u32)__half_as_ushort(hb) << 16);
}
__device__ __forceinline__ float softplus_f(float x)
{
    return fmaxf(x, 0.f) + log1pf(expf(-fabsf(x)));
}
__device__ __forceinline__ const char* stage_img(int s)
{
    if (s < 7) return g_Bcat[s];
    int r = s - 7;
    return (r & 1) ? g_B2[r >> 1] : g_B1[r >> 1];
}
__device__ __forceinline__ void prefetch_img(const char* src, u32 dst, int tid)
{
    u64 g = __cvta_generic_to_global(src);
    #pragma unroll
    for (int i = 0; i < 5; i++) {
        int idx = i*NTHR + tid;
        if (idx < IMG_V16)
            asm volatile("cp.async.cg.shared.global [%0], [%1], 16;"
                :: "r"(dst + idx*16), "l"(g + (u64)idx*16));
    }
}
#define CP_COMMIT()  asm volatile("cp.async.commit_group;" ::: "memory")
#define CP_WAIT1()   asm volatile("cp.async.wait_group 1;" ::: "memory")

/* zero 9 float4 slices of this CTA's 64-row output region per stage */
__device__ __forceinline__ void zero_chunk(float* zbase, int s, int tid)
{
    int j0 = s*9, j1 = j0+9; if (j1 > 128) j1 = 128;
    #pragma unroll 1
    for (int j = j0; j < j1; j++) {
        float* p = zbase + (size_t)(j*NTHR + tid)*4;
        asm volatile("st.global.cs.v4.f32 [%0], {%1,%1,%1,%1};"
            :: "l"(p), "f"(0.f) : "memory");
    }
}

/* phase-1 A staging: split into LDG-issue and pack-store halves */
__device__ __forceinline__ void load_a(const float* src, int Krow, int Kc,
                                       int tid, float2 (&va)[8])
{
    int n  = (Kc == 128) ? 8 : 4;
    int pl = (Kc == 128) ? 6 : 5, pm = (Kc >> 1) - 1;
    #pragma unroll
    for (int i = 0; i < 8; i++) if (i < n) {
        int idx = i*NTHR + tid;
        int m = idx >> pl, kp = idx & pm;
        va[i] = *(const float2*)(src + (size_t)m*Krow + kp*2);
    }
}
__device__ __forceinline__ void pack_a(char* smem, u32 aoff, int Kc,
                                       int tid, const float2 (&va)[8])
{
    int n  = (Kc == 128) ? 8 : 4;
    int pl = (Kc == 128) ? 6 : 5, pm = (Kc >> 1) - 1;
    #pragma unroll
    for (int i = 0; i < 8; i++) if (i < n) {
        int idx = i*NTHR + tid;
        int m = idx >> pl, kp = idx & pm;
        *(u32*)(smem + aoff + m*AST + kp*4) =
            pack_h(fmaxf(va[i].x, 0.f), fmaxf(va[i].y, 0.f));
    }
}

/* -------- prep: fp16 weights into [n][k] images, destination-coalesced ----- */
__global__ void prep_kernel(
    const float* __restrict__ Win,  const float* __restrict__ bin,
    const float* __restrict__ Wini, const float* __restrict__ bini,
    const float* __restrict__ Wd,   const float* __restrict__ bd,
    const float* __restrict__ W1,   const float* __restrict__ W2,
    const float* __restrict__ Wout, const float* __restrict__ bout,
    const float* __restrict__ Wmu,  const float* __restrict__ bmu)
{
    int id = blockIdx.x * blockDim.x + threadIdx.x;
    int stride = gridDim.x * blockDim.x;

    /* g_Bcat: 7 images x 128 rows x 64 u32-pairs, dest- and src-coalesced */
    for (int x = id; x < 7*128*64; x += stride) {
        int c  = x / (128*64);
        int r  = x - c*128*64;
        int n  = r >> 6;          /* image row  */
        int kp = r & 63;          /* u32 column */
        int k  = c*128 + kp*2;    /* concat k   */
        float2 v;
        if (k < 384)       v = *(const float2*)(Win  + n*384 + k);
        else if (k < 768)  v = *(const float2*)(Wini + n*384 + (k-384));
        else if (k < 832)  v = *(const float2*)(Wd   + n*64  + (k-768));
        else               v = make_float2(0.f, 0.f);
        *(u32*)(g_Bcat[c] + n*136*2 + kp*4) = pack_h(v.x, v.y);
    }
    /* g_B1/g_B2: NB images x 128 rows x 64 u32 */
    for (int x = id; x < NB*128*64; x += stride) {
        int blk = x / (128*64);
        int r   = x - blk*128*64;
        int n   = r >> 6, kp = r & 63;
        int off = n*136*2 + kp*4;
        float2 v1 = *(const float2*)(W1 + blk*CH*CH + n*CH + kp*2);
        float2 v2 = *(const float2*)(W2 + blk*CH*CH + n*CH + kp*2);
        *(u32*)(g_B1[blk] + off) = pack_h(v1.x, v1.y);
        *(u32*)(g_B2[blk] + off) = pack_h(v2.x, v2.y);
    }
    for (int x = id; x < CH*8; x += stride) {
        int k = x / 8, j = x % 8;
        float v = 0.f;
        if (j < 5)      v = Wout[j*CH + k];
        else if (j < 7) v = Wmu [(j-5)*CH + k];
        g_WTout[x] = v;
    }
    if (id < CH) g_bias0[id] = bin[id] + bini[id] + bd[id];
    if (id < 8)  g_bout[id] = (id < 5) ? bout[id] : ((id < 7) ? bmu[id-5] : 0.f);
}

/* ------- single-pass fp16 GEMM core: warp covers 16 rows x 32 cols ------- */
template<int NKS>
__device__ __forceinline__ void gemm1(u32 aimg, u32 bimg,
                                      u32 a_t, u32 b_t, float (&acc)[4][4])
{
    #pragma unroll 2
    for (int ks = 0; ks < NKS; ks++) {
        u32 ah[4];
        ldsm4(ah[0], ah[1], ah[2], ah[3], aimg + a_t + ks*32);
        u32 bc[4], bn[4];
        ldsm4(bc[0], bc[1], bc[2], bc[3], bimg + b_t + ks*32);
        ldsm4(bn[0], bn[1], bn[2], bn[3], bimg + b_t + 4352 + ks*32);
        mma16816(acc[0], ah, bc[0], bc[1]);
        mma16816(acc[1], ah, bc[2], bc[3]);
        mma16816(acc[2], ah, bn[0], bn[1]);
        mma16816(acc[3], ah, bn[2], bn[3]);
    }
}

/* -------- fused MLP kernel: 64 tokens/CTA, 512 thr, 2 CTAs/SM, 1 bar/stage -- */
__global__ __launch_bounds__(NTHR, 2) void fused_mlp_kernel(
    const float* __restrict__ s, const float* __restrict__ si, const float* __restrict__ ds,
    const float* __restrict__ b1g, const float* __restrict__ b2g,
    float* __restrict__ out)
{
    extern __shared__ char smem[];
    const int tid  = threadIdx.x;
    const int w    = tid >> 5;
    const int wr   = w >> 2;            /* row group 0..3  (16 rows)  */
    const int wcc  = w & 3;             /* col group 0..3  (32 cols)  */
    const int lane = tid & 31;
    const int seg  = lane >> 3;
    const int rr   = lane & 7;
    const int tok0 = blockIdx.x * TILE_M;
    float* zbase = out + (size_t)tok0 * NTOK;

    const u32 a_t = (u32)((wr*16 + (seg & 1)*8 + rr)*AST + (seg >> 1)*16);
    const u32 b_t = (u32)((wcc*32 + (seg >> 1)*8 + rr)*AST + (seg & 1)*16);
    const int r0   = wr*16 + (lane >> 2);
    const int r1   = r0 + 8;
    const int colb = wcc*32 + (lane & 3)*2;

    u32 sb = smem_u32(smem);
    u32 aoff[2] = { A0, A1 };
    u32 bb[2]   = { sb + BB0, sb + BB1 };

    float acc[4][4], hreg[4][4];
    float2 va[8];
    #pragma unroll
    for (int i = 0; i < 4; i++)
        #pragma unroll
        for (int j = 0; j < 4; j++) acc[i][j] = 0.f;

    /* phase-1 chunk descriptors */
    const float* csrc[7]; int ckrow[7], ckc[7];
    #pragma unroll
    for (int c = 0; c < 3; c++) { csrc[c] = s  + (size_t)tok0*C_IN + c*128;     ckrow[c] = C_IN; ckc[c] = 128; }
    #pragma unroll
    for (int c = 3; c < 6; c++) { csrc[c] = si + (size_t)tok0*C_IN + (c-3)*128; ckrow[c] = C_IN; ckc[c] = 128; }
    csrc[6] = ds + (size_t)tok0*C_DSSP; ckrow[6] = C_DSSP; ckc[6] = 64;

    /* prologue: B(0) prefetch; A(0) load+pack into A[0] */
    prefetch_img(stage_img(0), bb[0], tid);
    CP_COMMIT();
    load_a(csrc[0], ckrow[0], ckc[0], tid, va);
    pack_a(smem, aoff[0], ckc[0], tid, va);

    /* ---- phase 1: 7 chunk-GEMM stages, one barrier each ---- */
    #pragma unroll 1
    for (int c = 0; c < 7; c++) {
        __syncthreads();                 /* A(c), B(c) visible; all done with stage c-1 */
        prefetch_img(stage_img(c+1), bb[(c+1)&1], tid);
        CP_COMMIT();
        if (c+1 < 7) load_a(csrc[c+1], ckrow[c+1], ckc[c+1], tid, va);
        CP_WAIT1();
        if (ckc[c] == 128) gemm1<8>(sb + aoff[c&1], bb[c&1], a_t, b_t, acc);
        else               gemm1<4>(sb + aoff[c&1], bb[c&1], a_t, b_t, acc);
        zero_chunk(zbase, c, tid);
        if (c+1 < 7) pack_a(smem, aoff[(c+1)&1], ckc[c+1], tid, va);
    }

    /* phase-1 epilogue: hreg = D + bias0; A[1] = fp16(relu(hreg)) (gemm6 read A[0]) */
    #pragma unroll
    for (int nt = 0; nt < 4; nt++) {
        int col = colb + nt*8;
        float bc0 = g_bias0[col], bc1 = g_bias0[col+1];
        hreg[nt][0] = acc[nt][0] + bc0; hreg[nt][1] = acc[nt][1] + bc1;
        hreg[nt][2] = acc[nt][2] + bc0; hreg[nt][3] = acc[nt][3] + bc1;
        *(u32*)(smem + A1 + r0*AST + col*2) =
            pack_h(fmaxf(hreg[nt][0], 0.f), fmaxf(hreg[nt][1], 0.f));
        *(u32*)(smem + A1 + r1*AST + col*2) =
            pack_h(fmaxf(hreg[nt][2], 0.f), fmaxf(hreg[nt][3], 0.f));
    }

    /* ---- resnet: 8 stages, one barrier each; A ping-pongs via epilogues ---- */
    int ap = 1;                          /* first resnet gemm reads A[1] */
    #pragma unroll 1
    for (int st = 7; st < NSTAGES; st++) {
        __syncthreads();
        if (st+1 < NSTAGES) prefetch_img(stage_img(st+1), bb[(st+1)&1], tid);
        CP_COMMIT();
        CP_WAIT1();
        #pragma unroll
        for (int i = 0; i < 4; i++)
            #pragma unroll
            for (int j = 0; j < 4; j++) acc[i][j] = 0.f;
        gemm1<8>(sb + aoff[ap], bb[st&1], a_t, b_t, acc);
        zero_chunk(zbase, st, tid);

        int r = st - 7;
        int blk = r >> 1;
        if (!(r & 1)) {
            /* after GEMM1: A[ap^1] = fp16(relu(acc + b1)) */
            const float* bb1 = b1g + blk*CH;
            #pragma unroll
            for (int nt = 0; nt < 4; nt++) {
                int col = colb + nt*8;
                float bc0 = bb1[col], bc1 = bb1[col+1];
                *(u32*)(smem + aoff[ap^1] + r0*AST + col*2) =
                    pack_h(fmaxf(acc[nt][0] + bc0, 0.f), fmaxf(acc[nt][1] + bc1, 0.f));
                *(u32*)(smem + aoff[ap^1] + r1*AST + col*2) =
                    pack_h(fmaxf(acc[nt][2] + bc0, 0.f), fmaxf(acc[nt][3] + bc1, 0.f));
            }
        } else {
            /* after GEMM2: h += acc + b2; A[ap^1] or HF(last) */
            const float* bb2 = b2g + blk*CH;
            bool last = (st == NSTAGES-1);
            float* HF = (float*)(smem + BB1);   /* BB1 last read at stage 13 */
            #pragma unroll
            for (int nt = 0; nt < 4; nt++) {
                int col = colb + nt*8;
                float bc0 = bb2[col], bc1 = bb2[col+1];
                hreg[nt][0] += acc[nt][0] + bc0; hreg[nt][1] += acc[nt][1] + bc1;
                hreg[nt][2] += acc[nt][2] + bc0; hreg[nt][3] += acc[nt][3] + bc1;
                float w00 = fmaxf(hreg[nt][0], 0.f), w01 = fmaxf(hreg[nt][1], 0.f);
                float w10 = fmaxf(hreg[nt][2], 0.f), w11 = fmaxf(hreg[nt][3], 0.f);
                if (last) {
                    HF[r0*HFSTR + col] = w00; HF[r0*HFSTR + col+1] = w01;
                    HF[r1*HFSTR + col] = w10; HF[r1*HFSTR + col+1] = w11;
                } else {
                    *(u32*)(smem + aoff[ap^1] + r0*AST + col*2) = pack_h(w00, w01);
                    *(u32*)(smem + aoff[ap^1] + r1*AST + col*2) = pack_h(w10, w11);
                }
            }
        }
        ap ^= 1;
    }
    __syncthreads();

    /* ---- head: 7 outputs per token (HF at BB1 holds fp32 relu(h)) ---- */
    if (tid < TILE_M) {
        int m = tid;
        float o[7];
        #pragma unroll
        for (int j = 0; j < 7; j++) o[j] = g_bout[j];
        const float* rrow = (const float*)(smem + BB1) + m*HFSTR;
        #pragma unroll 4
        for (int k = 0; k < CH; k++) {
            float r = rrow[k];
            const float* wp = g_WTout + k*8;
            #pragma unroll
            for (int j = 0; j < 7; j++) o[j] = fmaf(r, wp[j], o[j]);
        }
        float d0 = softplus_f(o[0]) * softplus_f(o[5]) + softplus_f(o[6]);
        int g = tok0 + m;
        g_scratch[g*5 + 0] = d0;
        g_scratch[g*5 + 1] = o[1];
        g_scratch[g*5 + 2] = o[2];
        g_scratch[g*5 + 3] = o[3];
        g_scratch[g*5 + 4] = o[4];
    }
}

/* ------- diagonal writer (zeros already laid down by fused kernel) ------- */
__global__ void diag_kernel(float* __restrict__ out, const float* __restrict__ smp)
{
    const float sm = *smp;
    int row = blockIdx.x * blockDim.x + threadIdx.x;   /* 0..16383 */
    int i   = row & (NTOK - 1);
    size_t base = (size_t)row * NTOK;

    float d0 = sm * g_scratch[row*5 + 0];
    out[base + i] = d0;
    if (i >= 1) out[base + i - 1] = sm * (g_scratch[row*5 + 1] + g_scratch[(row-1)*5 + 3]);
    if (i >= 2) out[base + i - 2] = sm * (g_scratch[row*5 + 2] + g_scratch[(row-2)*5 + 4]);
}

/* ---------------- launch ---------------- */
extern "C" void kernel_launch(void* const* d_in, const int* in_sizes, int n_in,
                              void* d_out, int out_size)
{
    (void)in_sizes; (void)n_in; (void)out_size;
    const float* s    = (const float*)d_in[0];
    const float* si   = (const float*)d_in[1];
    const float* ds   = (const float*)d_in[2];
    const float* Win  = (const float*)d_in[3];
    const float* bin  = (const float*)d_in[4];
    const float* Wini = (const float*)d_in[5];
    const float* bini = (const float*)d_in[6];
    const float* Wd   = (const float*)d_in[7];
    const float* bd   = (const float*)d_in[8];
    const float* W1   = (const float*)d_in[9];
    const float* b1   = (const float*)d_in[10];
    const float* W2   = (const float*)d_in[11];
    const float* b2   = (const float*)d_in[12];
    const float* Wout = (const float*)d_in[13];
    const float* bout = (const float*)d_in[14];
    const float* Wmu  = (const float*)d_in[15];
    const float* bmu  = (const float*)d_in[16];
    const float* smod = (const float*)d_in[17];
    float* out = (float*)d_out;

    cudaFuncSetAttribute(fused_mlp_kernel,
                         cudaFuncAttributeMaxDynamicSharedMemorySize, SMEM_TOTAL);

    prep_kernel<<<592, 256>>>(Win, bin, Wini, bini, Wd, bd, W1, W2, Wout, bout, Wmu, bmu);
    fused_mlp_kernel<<<TOKENS/TILE_M, NTHR, SMEM_TOTAL>>>(s, si, ds, b1, b2, out);
    diag_kernel<<<TOKENS/128, 128>>>(out, smod);
}